// round 2
// baseline (speedup 1.0000x reference)
#include <cuda_runtime.h>

#define D 512
#define OUTD 128
#define MAXN 50000
#define MAXE 150000
#define BN_EPS 1e-5f

// ---------------- scratch (static device globals; no allocation) ----------------
__device__ float g_h[(size_t)MAXN * D];     // current node features
__device__ float g_hsum[(size_t)MAXN * D];  // hidden_sum accumulator
__device__ float g_z[(size_t)MAXN * D];     // aggregation buffer / gemm2 output
__device__ float g_y[(size_t)MAXN * D];     // gemm1 output / post-BN1
__device__ float g_s1[(size_t)MAXE * D];    // decoder hidden
__device__ float g_stats[2 * D];            // per-column sum, sumsq
__device__ float g_aff[2 * D];              // per-column scale, shift

// ---------------- embedding gather + hidden_sum init ----------------
__global__ void k_gather(const int* __restrict__ ids,
                         const float* __restrict__ emb, int Nn) {
    int idx = blockIdx.x * blockDim.x + threadIdx.x;
    int row = idx >> 7;
    if (row >= Nn) return;
    int c = (idx & 127) << 2;
    int e = ids[row];
    float4 val = *(const float4*)(emb + (size_t)e * D + c);
    *(float4*)(g_h + (size_t)row * D + c) = val;
    *(float4*)(g_hsum + (size_t)row * D + c) = val;
}

// z = 2*h   ((1+eps)*h with eps=0, plus the self-loop message h)
__global__ void k_scale2(int Nn) {
    int idx = blockIdx.x * blockDim.x + threadIdx.x;
    if (idx >= Nn * 128) return;
    float4 v = *(const float4*)(g_h + (size_t)idx * 4);
    v.x *= 2.f; v.y *= 2.f; v.z *= 2.f; v.w *= 2.f;
    *(float4*)(g_z + (size_t)idx * 4) = v;
}

// undirected edge scatter: z[v]+=h[u], z[u]+=h[v]
__global__ void k_scatter(const int* __restrict__ u, const int* __restrict__ v, int E) {
    int idx = blockIdx.x * blockDim.x + threadIdx.x;
    if (idx >= E * 128) return;
    int e = idx >> 7;
    int c = (idx & 127) << 2;
    int a = __ldg(u + e), b = __ldg(v + e);
    float4 ha = *(const float4*)(g_h + (size_t)a * D + c);
    float4 hb = *(const float4*)(g_h + (size_t)b * D + c);
    float* zb = g_z + (size_t)b * D + c;
    atomicAdd(zb + 0, ha.x); atomicAdd(zb + 1, ha.y);
    atomicAdd(zb + 2, ha.z); atomicAdd(zb + 3, ha.w);
    float* za = g_z + (size_t)a * D + c;
    atomicAdd(za + 0, hb.x); atomicAdd(za + 1, hb.y);
    atomicAdd(za + 2, hb.z); atomicAdd(za + 3, hb.w);
}

// ---------------- tiled SGEMM: C[M,N] = A[M,K] @ B[K,N] ----------------
// GATHER=1: logical A row r = concat(H[gu[r]], H[gv[r]]), K must be 1024, A=H.
// EPI: 0 = plain store, 1 = bias+relu, 2 = bias
template <int GATHER, int EPI>
__global__ __launch_bounds__(256, 2)
void k_sgemm(const float* __restrict__ A, const float* __restrict__ B,
             float* __restrict__ C, int M, int N, int K,
             const int* __restrict__ gu, const int* __restrict__ gv,
             const float* __restrict__ bias) {
    __shared__ __align__(16) float As[8][128];
    __shared__ __align__(16) float Bs[8][128];

    const int bm = blockIdx.x * 128, bn = blockIdx.y * 128;
    const int tid = threadIdx.x;
    const int tx = tid & 15, ty = tid >> 4;

    const int la_r = tid >> 1;          // 0..127
    const int la_c = (tid & 1) * 4;     // 0 or 4
    const int lb_r = tid >> 5;          // 0..7
    const int lb_c = (tid & 31) * 4;

    const int arow = bm + la_r;
    size_t arow_off = 0;
    int gia = 0, gib = 0;
    if (arow < M) {
        if (GATHER) { gia = gu[arow]; gib = gv[arow]; }
        else arow_off = (size_t)arow * K;
    }

    float acc[8][8];
#pragma unroll
    for (int i = 0; i < 8; i++)
#pragma unroll
        for (int j = 0; j < 8; j++) acc[i][j] = 0.f;

    for (int k0 = 0; k0 < K; k0 += 8) {
        float4 av = make_float4(0.f, 0.f, 0.f, 0.f);
        if (arow < M) {
            if (!GATHER) {
                av = *(const float4*)(A + arow_off + k0 + la_c);
            } else {
                int k = k0 + la_c;
                int node = (k < 512) ? gia : gib;
                av = *(const float4*)(A + (size_t)node * 512 + (k & 511));
            }
        }
        As[la_c + 0][la_r] = av.x;
        As[la_c + 1][la_r] = av.y;
        As[la_c + 2][la_r] = av.z;
        As[la_c + 3][la_r] = av.w;

        float4 bv = *(const float4*)(B + (size_t)(k0 + lb_r) * N + bn + lb_c);
        *(float4*)&Bs[lb_r][lb_c] = bv;

        __syncthreads();
#pragma unroll
        for (int kk = 0; kk < 8; kk++) {
            float a[8], b[8];
            *(float4*)(a)     = *(const float4*)&As[kk][ty * 8];
            *(float4*)(a + 4) = *(const float4*)&As[kk][ty * 8 + 4];
            *(float4*)(b)     = *(const float4*)&Bs[kk][tx * 8];
            *(float4*)(b + 4) = *(const float4*)&Bs[kk][tx * 8 + 4];
#pragma unroll
            for (int i = 0; i < 8; i++)
#pragma unroll
                for (int j = 0; j < 8; j++) acc[i][j] += a[i] * b[j];
        }
        __syncthreads();
    }

#pragma unroll
    for (int i = 0; i < 8; i++) {
        int r = bm + ty * 8 + i;
        if (r >= M) break;
#pragma unroll
        for (int j = 0; j < 8; j += 4) {
            int cidx = bn + tx * 8 + j;
            float4 val = make_float4(acc[i][j], acc[i][j + 1], acc[i][j + 2], acc[i][j + 3]);
            if (EPI >= 1) {
                float4 bb = *(const float4*)(bias + cidx);
                val.x += bb.x; val.y += bb.y; val.z += bb.z; val.w += bb.w;
                if (EPI == 1) {
                    val.x = fmaxf(val.x, 0.f); val.y = fmaxf(val.y, 0.f);
                    val.z = fmaxf(val.z, 0.f); val.w = fmaxf(val.w, 0.f);
                }
            }
            *(float4*)(C + (size_t)r * N + cidx) = val;
        }
    }
}

// ---------------- batch-norm helpers ----------------
__global__ void k_bnzero() {
    int t = threadIdx.x;
    if (t < 2 * D) g_stats[t] = 0.f;
}

#define BN_ROWS 256
__global__ void k_bnstats(const float* __restrict__ Y, int M) {
    int col = threadIdx.x;           // 512 threads
    int r0 = blockIdx.x * BN_ROWS;
    int r1 = min(r0 + BN_ROWS, M);
    float s = 0.f, s2 = 0.f;
    for (int r = r0; r < r1; r++) {
        float val = Y[(size_t)r * D + col];
        s += val; s2 += val * val;
    }
    atomicAdd(&g_stats[col], s);
    atomicAdd(&g_stats[D + col], s2);
}

__global__ void k_bnfin(const float* __restrict__ gamma,
                        const float* __restrict__ beta, int M) {
    int j = threadIdx.x;
    if (j >= D) return;
    float inv = 1.f / (float)M;
    float m = g_stats[j] * inv;
    float var = g_stats[D + j] * inv - m * m;
    float sc = gamma[j] * rsqrtf(var + BN_EPS);
    g_aff[j] = sc;
    g_aff[D + j] = beta[j] - m * sc;
}

// in-place: Y = relu(Y*scale + shift)
__global__ void k_bnrelu(float* __restrict__ Y, int Nn) {
    int idx = blockIdx.x * blockDim.x + threadIdx.x;
    if (idx >= Nn * 128) return;
    int c = (idx & 127) << 2;
    float4 v = *(const float4*)(Y + (size_t)idx * 4);
    v.x = fmaxf(v.x * g_aff[c + 0] + g_aff[D + c + 0], 0.f);
    v.y = fmaxf(v.y * g_aff[c + 1] + g_aff[D + c + 1], 0.f);
    v.z = fmaxf(v.z * g_aff[c + 2] + g_aff[D + c + 2], 0.f);
    v.w = fmaxf(v.w * g_aff[c + 3] + g_aff[D + c + 3], 0.f);
    *(float4*)(Y + (size_t)idx * 4) = v;
}

// h = relu(Y2*scale+shift); hsum += h
__global__ void k_bnrelu_acc(const float* __restrict__ Y2, int Nn) {
    int idx = blockIdx.x * blockDim.x + threadIdx.x;
    if (idx >= Nn * 128) return;
    int c = (idx & 127) << 2;
    float4 v = *(const float4*)(Y2 + (size_t)idx * 4);
    v.x = fmaxf(v.x * g_aff[c + 0] + g_aff[D + c + 0], 0.f);
    v.y = fmaxf(v.y * g_aff[c + 1] + g_aff[D + c + 1], 0.f);
    v.z = fmaxf(v.z * g_aff[c + 2] + g_aff[D + c + 2], 0.f);
    v.w = fmaxf(v.w * g_aff[c + 3] + g_aff[D + c + 3], 0.f);
    *(float4*)(g_h + (size_t)idx * 4) = v;
    float4 hs = *(const float4*)(g_hsum + (size_t)idx * 4);
    hs.x += v.x; hs.y += v.y; hs.z += v.z; hs.w += v.w;
    *(float4*)(g_hsum + (size_t)idx * 4) = hs;
}

// ---------------- launch ----------------
extern "C" void kernel_launch(void* const* d_in, const int* in_sizes, int n_in,
                              void* d_out, int out_size) {
    const int* h_ids = (const int*)d_in[0];
    const int* u     = (const int*)d_in[1];
    const int* v     = (const int*)d_in[2];
    const float* emb   = (const float*)d_in[3];
    const float* lin1  = (const float*)d_in[4];
    const float* lin2  = (const float*)d_in[5];
    const float* bn1_g = (const float*)d_in[6];
    const float* bn1_b = (const float*)d_in[7];
    const float* bn2_g = (const float*)d_in[8];
    const float* bn2_b = (const float*)d_in[9];
    const float* W1_w  = (const float*)d_in[10];
    const float* W1_b  = (const float*)d_in[11];
    const float* W2_w  = (const float*)d_in[12];
    const float* W2_b  = (const float*)d_in[13];
    float* out = (float*)d_out;

    const int N = in_sizes[0];
    const int E = in_sizes[1];
    const int L = in_sizes[4] / (D * D);

    float *dg_h, *dg_hsum, *dg_z, *dg_y, *dg_s1;
    cudaGetSymbolAddress((void**)&dg_h, g_h);
    cudaGetSymbolAddress((void**)&dg_hsum, g_hsum);
    cudaGetSymbolAddress((void**)&dg_z, g_z);
    cudaGetSymbolAddress((void**)&dg_y, g_y);
    cudaGetSymbolAddress((void**)&dg_s1, g_s1);

    const int ew = N * 128;                 // float4 work items over [N, D]
    const int ewB = (ew + 255) / 256;
    const int sc = E * 128;
    const int scB = (sc + 255) / 256;
    const int mtiles = (N + 127) / 128;
    const int etiles = (E + 127) / 128;
    const int bnB = (N + BN_ROWS - 1) / BN_ROWS;

    // h = emb[h_ids]; hidden_sum = h
    k_gather<<<ewB, 256>>>(h_ids, emb, N);

    for (int i = 0; i < L; i++) {
        // z = 2h + neighbor sums
        k_scale2<<<ewB, 256>>>(N);
        k_scatter<<<scB, 256>>>(u, v, E);
        // y = z @ lin1[i]
        k_sgemm<0, 0><<<dim3(mtiles, D / 128), 256>>>(
            dg_z, lin1 + (size_t)i * D * D, dg_y, N, D, D, nullptr, nullptr, nullptr);
        // BN1 + relu
        k_bnzero<<<1, 1024>>>();
        k_bnstats<<<bnB, D>>>(dg_y, N);
        k_bnfin<<<1, D>>>(bn1_g + (size_t)i * D, bn1_b + (size_t)i * D, N);
        k_bnrelu<<<ewB, 256>>>(dg_y, N);
        // z(out) = y @ lin2[i]
        k_sgemm<0, 0><<<dim3(mtiles, D / 128), 256>>>(
            dg_y, lin2 + (size_t)i * D * D, dg_z, N, D, D, nullptr, nullptr, nullptr);
        // BN2 + relu, h update, hidden_sum accumulate
        k_bnzero<<<1, 1024>>>();
        k_bnstats<<<bnB, D>>>(dg_z, N);
        k_bnfin<<<1, D>>>(bn2_g + (size_t)i * D, bn2_b + (size_t)i * D, N);
        k_bnrelu_acc<<<ewB, 256>>>(dg_z, N);
    }

    // decoder: s1 = relu(concat(H[u],H[v]) @ W1 + b1)   [E, 512]
    k_sgemm<1, 1><<<dim3(etiles, D / 128), 256>>>(
        dg_hsum, W1_w, dg_s1, E, D, 2 * D, u, v, W1_b);
    // out = s1 @ W2 + b2                                 [E, 128]
    k_sgemm<0, 2><<<dim3(etiles, 1), 256>>>(
        dg_s1, W2_w, out, E, OUTD, D, nullptr, nullptr, W2_b);
}

// round 4
// speedup vs baseline: 1.8633x; 1.8633x over previous
#include <cuda_runtime.h>
#include <cuda_bf16.h>

#define D 512
#define OUTD 128
#define MAXN 50000
#define MAXE 150000
#define BN_EPS 1e-5f

// ---------------- scratch (static device globals; no allocation) ----------------
__device__ float g_h[(size_t)MAXN * D];     // current node features
__device__ float g_hsum[(size_t)MAXN * D];  // hidden_sum accumulator
__device__ float g_z[(size_t)MAXN * D];     // aggregation buffer / gemm2 output
__device__ float g_y[(size_t)MAXN * D];     // gemm1 output
__device__ float g_stats[2 * D];
__device__ float g_aff[2 * D];

// bf16 split pairs
__device__ __nv_bfloat16 g_zh[(size_t)MAXN * D], g_zl[(size_t)MAXN * D];
__device__ __nv_bfloat16 g_yh[(size_t)MAXN * D], g_yl[(size_t)MAXN * D];
__device__ __nv_bfloat16 g_hsh[(size_t)MAXN * D], g_hsl[(size_t)MAXN * D];
__device__ __nv_bfloat16 g_s1h[(size_t)MAXE * D], g_s1l[(size_t)MAXE * D];
// transposed + split weights: Bt[n][k]
__device__ __nv_bfloat16 g_l1th[(size_t)4 * D * D], g_l1tl[(size_t)4 * D * D];
__device__ __nv_bfloat16 g_l2th[(size_t)4 * D * D], g_l2tl[(size_t)4 * D * D];
__device__ __nv_bfloat16 g_w1th[(size_t)D * 2 * D], g_w1tl[(size_t)D * 2 * D];
__device__ __nv_bfloat16 g_w2th[(size_t)OUTD * D], g_w2tl[(size_t)OUTD * D];

// ---------------- PTX helpers (all plain compute_100-legal) ----------------
__device__ __forceinline__ unsigned smem_u32(const void* p) {
    unsigned a;
    asm("{ .reg .u64 t; cvta.to.shared.u64 t, %1; cvt.u32.u64 %0, t; }" : "=r"(a) : "l"(p));
    return a;
}
__device__ __forceinline__ void cpasync16(unsigned dst, const void* src) {
    asm volatile("cp.async.cg.shared.global [%0], [%1], 16;" ::"r"(dst), "l"(src));
}
__device__ __forceinline__ void ldm4(unsigned* r, unsigned addr) {
    asm volatile("ldmatrix.sync.aligned.m8n8.x4.shared.b16 {%0,%1,%2,%3}, [%4];"
                 : "=r"(r[0]), "=r"(r[1]), "=r"(r[2]), "=r"(r[3]) : "r"(addr));
}
__device__ __forceinline__ void mma16816(float* c, const unsigned* a, const unsigned* b) {
    asm volatile(
        "mma.sync.aligned.m16n8k16.row.col.f32.bf16.bf16.f32 "
        "{%0,%1,%2,%3}, {%4,%5,%6,%7}, {%8,%9}, {%0,%1,%2,%3};"
        : "+f"(c[0]), "+f"(c[1]), "+f"(c[2]), "+f"(c[3])
        : "r"(a[0]), "r"(a[1]), "r"(a[2]), "r"(a[3]), "r"(b[0]), "r"(b[1]));
}
__device__ __forceinline__ void f2pair(float v, __nv_bfloat16& h, __nv_bfloat16& l) {
    h = __float2bfloat16(v);
    l = __float2bfloat16(v - __bfloat162float(h));
}

// ---------------- mma.sync split-bf16 GEMM ----------------
// C[M,Nout] = A[M,KTOT] @ Bt[Nout,KTOT]^T, A/Bt given as (hi,lo) bf16 pairs.
// GATHER=1: logical A row r = concat(hs[u[r]], hs[v[r]])  (KTOT=1024, A base = hs).
// EPI: 0 = fp32 store; 1 = relu(x+bias)->bf16 pair; 2 = x+bias -> fp32.
//
// smem per stage: Ah | Al | Bh | Bl, each 128 rows x 32 bf16, row stride 80B
// (padded: conflict-free ldmatrix with 80B stride), 10240B per tile,
// 40960B per stage, 2 stages = 81920B dynamic smem.
#define TILE_B   10240
#define STAGE_B  40960
#define SMEMSZ   81920

template <int KTOT, int GATHER, int EPI>
__global__ __launch_bounds__(256)
void k_mma(const __nv_bfloat16* __restrict__ Ah, const __nv_bfloat16* __restrict__ Al,
           const __nv_bfloat16* __restrict__ Bh, const __nv_bfloat16* __restrict__ Bl,
           float* __restrict__ Cf, __nv_bfloat16* __restrict__ Ch, __nv_bfloat16* __restrict__ Cl,
           int M, int Nout,
           const int* __restrict__ gu, const int* __restrict__ gv,
           const float* __restrict__ bias) {
    extern __shared__ __align__(16) char smem[];
    __shared__ int s_u[128], s_v[128];
    const int tid = threadIdx.x;
    const int wid = tid >> 5, lane = tid & 31;
    const int wm = wid & 3, wn = wid >> 2;      // 4 x 2 warp grid, warp tile 32x64
    const int bm = blockIdx.x * 128, bn = blockIdx.y * 128;
    const unsigned sb = smem_u32(smem);

    if (GATHER) {
        if (tid < 128) {
            int e = min(bm + tid, M - 1);
            s_u[tid] = gu[e]; s_v[tid] = gv[e];
        }
        __syncthreads();
    }

    const int lrow = tid >> 1;                       // 0..127 (loader row)
    const int grA = GATHER ? 0 : min(bm + lrow, M - 1);
    const int grB = bn + lrow;

    float acc[2][8][4];
#pragma unroll
    for (int i = 0; i < 2; i++)
#pragma unroll
        for (int j = 0; j < 8; j++)
#pragma unroll
            for (int q = 0; q < 4; q++) acc[i][j][q] = 0.f;

#define LOAD_CHUNK(STG, K0)                                                    \
    {                                                                          \
        unsigned st = sb + (STG) * STAGE_B;                                    \
        _Pragma("unroll") for (int j = 0; j < 2; j++) {                        \
            int cc = (tid & 1) * 2 + j;                                        \
            unsigned dsto = lrow * 80 + cc * 16;                               \
            const __nv_bfloat16 *pa_h, *pa_l;                                  \
            if (GATHER) {                                                      \
                int node = ((K0) < 512) ? s_u[lrow] : s_v[lrow];               \
                int ge = ((K0) & 511) + cc * 8;                                \
                pa_h = Ah + (size_t)node * 512 + ge;                           \
                pa_l = Al + (size_t)node * 512 + ge;                           \
            } else {                                                           \
                size_t o = (size_t)grA * KTOT + (K0) + cc * 8;                 \
                pa_h = Ah + o; pa_l = Al + o;                                  \
            }                                                                  \
            cpasync16(st + 0 * TILE_B + dsto, pa_h);                           \
            cpasync16(st + 1 * TILE_B + dsto, pa_l);                           \
            size_t ob = (size_t)grB * KTOT + (K0) + cc * 8;                    \
            cpasync16(st + 2 * TILE_B + dsto, Bh + ob);                        \
            cpasync16(st + 3 * TILE_B + dsto, Bl + ob);                        \
        }                                                                      \
    }

    const int NC = KTOT / 32;
    LOAD_CHUNK(0, 0);
    asm volatile("cp.async.commit_group;");

    for (int c = 0; c < NC; c++) {
        if (c + 1 < NC) {
            LOAD_CHUNK((c + 1) & 1, (c + 1) * 32);
            asm volatile("cp.async.commit_group;");
            asm volatile("cp.async.wait_group 1;");
        } else {
            asm volatile("cp.async.wait_group 0;");
        }
        __syncthreads();

        const unsigned st = sb + (c & 1) * STAGE_B;
#pragma unroll
        for (int ks = 0; ks < 2; ks++) {
            const unsigned koff = ks * 32;  // 16 bf16 per k-step
            unsigned ah[2][4], al[2][4];
#pragma unroll
            for (int mf = 0; mf < 2; mf++) {
                unsigned addr = st + (wm * 32 + mf * 16 + (lane & 15)) * 80 +
                                ((lane >> 4) * 16) + koff;
                ldm4(ah[mf], addr);
                ldm4(al[mf], addr + TILE_B);
            }
#pragma unroll
            for (int nb = 0; nb < 4; nb++) {
                unsigned addr = st + 2 * TILE_B +
                                (wn * 64 + nb * 16 + (lane & 15)) * 80 +
                                ((lane >> 4) * 16) + koff;
                unsigned bh[4], bl[4];
                ldm4(bh, addr);
                ldm4(bl, addr + TILE_B);
                unsigned b0h[2] = {bh[0], bh[2]}, b1h[2] = {bh[1], bh[3]};
                unsigned b0l[2] = {bl[0], bl[2]}, b1l[2] = {bl[1], bl[3]};
#pragma unroll
                for (int mf = 0; mf < 2; mf++) {
                    mma16816(acc[mf][nb * 2], ah[mf], b0h);
                    mma16816(acc[mf][nb * 2], ah[mf], b0l);
                    mma16816(acc[mf][nb * 2], al[mf], b0h);
                    mma16816(acc[mf][nb * 2 + 1], ah[mf], b1h);
                    mma16816(acc[mf][nb * 2 + 1], ah[mf], b1l);
                    mma16816(acc[mf][nb * 2 + 1], al[mf], b1h);
                }
            }
        }
        __syncthreads();
    }
#undef LOAD_CHUNK

    // epilogue: c-frag layout m16n8 -> rows t/4 & t/4+8, cols 2*(t%4)+{0,1}
#pragma unroll
    for (int mf = 0; mf < 2; mf++) {
        const int r0 = bm + wm * 32 + mf * 16 + (lane >> 2);
#pragma unroll
        for (int nf = 0; nf < 8; nf++) {
            const int col = bn + wn * 64 + nf * 8 + (lane & 3) * 2;
            const float* a = acc[mf][nf];
#pragma unroll
            for (int hh = 0; hh < 2; hh++) {
                const int row = r0 + hh * 8;
                if (row >= M) continue;
                float v0 = a[hh * 2], v1 = a[hh * 2 + 1];
                if (EPI == 0) {
                    float2 s = make_float2(v0, v1);
                    *(float2*)(Cf + (size_t)row * Nout + col) = s;
                } else if (EPI == 1) {
                    v0 = fmaxf(v0 + bias[col], 0.f);
                    v1 = fmaxf(v1 + bias[col + 1], 0.f);
                    __nv_bfloat16 h0, l0, h1, l1;
                    f2pair(v0, h0, l0);
                    f2pair(v1, h1, l1);
                    __nv_bfloat162 hp; hp.x = h0; hp.y = h1;
                    __nv_bfloat162 lp; lp.x = l0; lp.y = l1;
                    *(__nv_bfloat162*)(Ch + (size_t)row * Nout + col) = hp;
                    *(__nv_bfloat162*)(Cl + (size_t)row * Nout + col) = lp;
                } else {
                    float2 s = make_float2(v0 + bias[col], v1 + bias[col + 1]);
                    *(float2*)(Cf + (size_t)row * Nout + col) = s;
                }
            }
        }
    }
}

// ---------------- elementwise / graph kernels ----------------
__global__ void k_gather(const int* __restrict__ ids, const float* __restrict__ emb, int Nn) {
    int idx = blockIdx.x * blockDim.x + threadIdx.x;
    int row = idx >> 7;
    if (row >= Nn) return;
    int c = (idx & 127) << 2;
    float4 val = *(const float4*)(emb + (size_t)ids[row] * D + c);
    *(float4*)(g_h + (size_t)row * D + c) = val;
    *(float4*)(g_hsum + (size_t)row * D + c) = val;
}

__global__ void k_scale2(int Nn) {
    int idx = blockIdx.x * blockDim.x + threadIdx.x;
    if (idx >= Nn * 128) return;
    float4 v = *(const float4*)(g_h + (size_t)idx * 4);
    v.x *= 2.f; v.y *= 2.f; v.z *= 2.f; v.w *= 2.f;
    *(float4*)(g_z + (size_t)idx * 4) = v;
}

__global__ void k_scatter(const int* __restrict__ u, const int* __restrict__ v, int E) {
    int idx = blockIdx.x * blockDim.x + threadIdx.x;
    if (idx >= E * 128) return;
    int e = idx >> 7;
    int c = (idx & 127) << 2;
    int a = __ldg(u + e), b = __ldg(v + e);
    float4 ha = *(const float4*)(g_h + (size_t)a * D + c);
    float4 hb = *(const float4*)(g_h + (size_t)b * D + c);
    float* zb = g_z + (size_t)b * D + c;
    atomicAdd(zb + 0, ha.x); atomicAdd(zb + 1, ha.y);
    atomicAdd(zb + 2, ha.z); atomicAdd(zb + 3, ha.w);
    float* za = g_z + (size_t)a * D + c;
    atomicAdd(za + 0, hb.x); atomicAdd(za + 1, hb.y);
    atomicAdd(za + 2, hb.z); atomicAdd(za + 3, hb.w);
}

// fp32 -> bf16 pair
__global__ void k_cvt(const float* __restrict__ X, __nv_bfloat16* __restrict__ H,
                      __nv_bfloat16* __restrict__ Lo, int n4) {
    int i = blockIdx.x * blockDim.x + threadIdx.x;
    if (i >= n4) return;
    float4 v = *(const float4*)(X + (size_t)i * 4);
    __nv_bfloat16 h0, l0, h1, l1, h2, l2, h3, l3;
    f2pair(v.x, h0, l0); f2pair(v.y, h1, l1);
    f2pair(v.z, h2, l2); f2pair(v.w, h3, l3);
    __nv_bfloat162* Hp = (__nv_bfloat162*)(H + (size_t)i * 4);
    __nv_bfloat162* Lp = (__nv_bfloat162*)(Lo + (size_t)i * 4);
    __nv_bfloat162 a; a.x = h0; a.y = h1; Hp[0] = a;
    a.x = h2; a.y = h3; Hp[1] = a;
    a.x = l0; a.y = l1; Lp[0] = a;
    a.x = l2; a.y = l3; Lp[1] = a;
}

// weight transpose+convert: src [K,Nn] row-major -> dst [Nn,K] pairs
__global__ void k_tcvt(const float* __restrict__ B, __nv_bfloat16* __restrict__ H,
                       __nv_bfloat16* __restrict__ Lo, int K, int Nn) {
    int idx = blockIdx.x * blockDim.x + threadIdx.x;
    if (idx >= K * Nn) return;
    int n = idx / K, k = idx - n * K;
    float x = B[(size_t)k * Nn + n];
    __nv_bfloat16 h, l;
    f2pair(x, h, l);
    H[idx] = h; Lo[idx] = l;
}

__global__ void k_bnzero() {
    int t = threadIdx.x;
    if (t < 2 * D) g_stats[t] = 0.f;
}

#define BN_ROWS 256
__global__ void k_bnstats(const float* __restrict__ Y, int M) {
    int col = threadIdx.x;
    int r0 = blockIdx.x * BN_ROWS;
    int r1 = min(r0 + BN_ROWS, M);
    float s = 0.f, s2 = 0.f;
    for (int rr = r0; rr < r1; rr++) {
        float val = Y[(size_t)rr * D + col];
        s += val; s2 += val * val;
    }
    atomicAdd(&g_stats[col], s);
    atomicAdd(&g_stats[D + col], s2);
}

__global__ void k_bnfin(const float* __restrict__ gamma, const float* __restrict__ beta, int M) {
    int j = threadIdx.x;
    if (j >= D) return;
    float inv = 1.f / (float)M;
    float m = g_stats[j] * inv;
    float var = g_stats[D + j] * inv - m * m;
    float sc = gamma[j] * rsqrtf(var + BN_EPS);
    g_aff[j] = sc;
    g_aff[D + j] = beta[j] - m * sc;
}

// relu(affine(Y)) -> bf16 pairs
__global__ void k_bnrelu_cvt(const float* __restrict__ Y, __nv_bfloat16* __restrict__ H,
                             __nv_bfloat16* __restrict__ Lo, int Nn) {
    int idx = blockIdx.x * blockDim.x + threadIdx.x;
    if (idx >= Nn * 128) return;
    int c = (idx & 127) << 2;
    float4 v = *(const float4*)(Y + (size_t)idx * 4);
    v.x = fmaxf(v.x * g_aff[c + 0] + g_aff[D + c + 0], 0.f);
    v.y = fmaxf(v.y * g_aff[c + 1] + g_aff[D + c + 1], 0.f);
    v.z = fmaxf(v.z * g_aff[c + 2] + g_aff[D + c + 2], 0.f);
    v.w = fmaxf(v.w * g_aff[c + 3] + g_aff[D + c + 3], 0.f);
    __nv_bfloat16 h0, l0, h1, l1, h2, l2, h3, l3;
    f2pair(v.x, h0, l0); f2pair(v.y, h1, l1);
    f2pair(v.z, h2, l2); f2pair(v.w, h3, l3);
    __nv_bfloat162* Hp = (__nv_bfloat162*)(H + (size_t)idx * 4);
    __nv_bfloat162* Lp = (__nv_bfloat162*)(Lo + (size_t)idx * 4);
    __nv_bfloat162 a; a.x = h0; a.y = h1; Hp[0] = a;
    a.x = h2; a.y = h3; Hp[1] = a;
    a.x = l0; a.y = l1; Lp[0] = a;
    a.x = l2; a.y = l3; Lp[1] = a;
}

// h = relu(affine(Y2)); hsum += h   (fp32)
__global__ void k_bnrelu_acc(const float* __restrict__ Y2, int Nn) {
    int idx = blockIdx.x * blockDim.x + threadIdx.x;
    if (idx >= Nn * 128) return;
    int c = (idx & 127) << 2;
    float4 v = *(const float4*)(Y2 + (size_t)idx * 4);
    v.x = fmaxf(v.x * g_aff[c + 0] + g_aff[D + c + 0], 0.f);
    v.y = fmaxf(v.y * g_aff[c + 1] + g_aff[D + c + 1], 0.f);
    v.z = fmaxf(v.z * g_aff[c + 2] + g_aff[D + c + 2], 0.f);
    v.w = fmaxf(v.w * g_aff[c + 3] + g_aff[D + c + 3], 0.f);
    *(float4*)(g_h + (size_t)idx * 4) = v;
    float4 hs = *(const float4*)(g_hsum + (size_t)idx * 4);
    hs.x += v.x; hs.y += v.y; hs.z += v.z; hs.w += v.w;
    *(float4*)(g_hsum + (size_t)idx * 4) = hs;
}

// ---------------- launch ----------------
extern "C" void kernel_launch(void* const* d_in, const int* in_sizes, int n_in,
                              void* d_out, int out_size) {
    const int* h_ids = (const int*)d_in[0];
    const int* u     = (const int*)d_in[1];
    const int* v     = (const int*)d_in[2];
    const float* emb   = (const float*)d_in[3];
    const float* lin1  = (const float*)d_in[4];
    const float* lin2  = (const float*)d_in[5];
    const float* bn1_g = (const float*)d_in[6];
    const float* bn1_b = (const float*)d_in[7];
    const float* bn2_g = (const float*)d_in[8];
    const float* bn2_b = (const float*)d_in[9];
    const float* W1_w  = (const float*)d_in[10];
    const float* W1_b  = (const float*)d_in[11];
    const float* W2_w  = (const float*)d_in[12];
    const float* W2_b  = (const float*)d_in[13];
    float* out = (float*)d_out;

    const int N = in_sizes[0];
    const int E = in_sizes[1];
    const int L = in_sizes[4] / (D * D);

    static int s_attr = 0;
    if (!s_attr) {
        cudaFuncSetAttribute(k_mma<512, 0, 0>,  cudaFuncAttributeMaxDynamicSharedMemorySize, SMEMSZ);
        cudaFuncSetAttribute(k_mma<1024, 1, 1>, cudaFuncAttributeMaxDynamicSharedMemorySize, SMEMSZ);
        cudaFuncSetAttribute(k_mma<512, 0, 2>,  cudaFuncAttributeMaxDynamicSharedMemorySize, SMEMSZ);
        s_attr = 1;
    }

    float *dg_z, *dg_y, *dg_hsum;
    cudaGetSymbolAddress((void**)&dg_z, g_z);
    cudaGetSymbolAddress((void**)&dg_y, g_y);
    cudaGetSymbolAddress((void**)&dg_hsum, g_hsum);
    __nv_bfloat16 *zh, *zl, *yh, *yl, *hsh, *hsl, *s1h, *s1l;
    __nv_bfloat16 *l1th, *l1tl, *l2th, *l2tl, *w1th, *w1tl, *w2th, *w2tl;
    cudaGetSymbolAddress((void**)&zh, g_zh);  cudaGetSymbolAddress((void**)&zl, g_zl);
    cudaGetSymbolAddress((void**)&yh, g_yh);  cudaGetSymbolAddress((void**)&yl, g_yl);
    cudaGetSymbolAddress((void**)&hsh, g_hsh); cudaGetSymbolAddress((void**)&hsl, g_hsl);
    cudaGetSymbolAddress((void**)&s1h, g_s1h); cudaGetSymbolAddress((void**)&s1l, g_s1l);
    cudaGetSymbolAddress((void**)&l1th, g_l1th); cudaGetSymbolAddress((void**)&l1tl, g_l1tl);
    cudaGetSymbolAddress((void**)&l2th, g_l2th); cudaGetSymbolAddress((void**)&l2tl, g_l2tl);
    cudaGetSymbolAddress((void**)&w1th, g_w1th); cudaGetSymbolAddress((void**)&w1tl, g_w1tl);
    cudaGetSymbolAddress((void**)&w2th, g_w2th); cudaGetSymbolAddress((void**)&w2tl, g_w2tl);

    const int ew = N * 128, ewB = (ew + 255) / 256;
    const int sc = E * 128, scB = (sc + 255) / 256;
    const int mtiles = (N + 127) / 128;
    const int etiles = (E + 127) / 128;
    const int bnB = (N + BN_ROWS - 1) / BN_ROWS;
    const int cvtB = (N * 128 + 255) / 256;

    // weight conversion (transpose + split)
    const int wB = (D * D + 255) / 256;
    for (int i = 0; i < L; i++) {
        k_tcvt<<<wB, 256>>>(lin1 + (size_t)i * D * D, l1th + (size_t)i * D * D, l1tl + (size_t)i * D * D, D, D);
        k_tcvt<<<wB, 256>>>(lin2 + (size_t)i * D * D, l2th + (size_t)i * D * D, l2tl + (size_t)i * D * D, D, D);
    }
    k_tcvt<<<(2 * D * D + 255) / 256, 256>>>(W1_w, w1th, w1tl, 2 * D, D);
    k_tcvt<<<(D * OUTD + 255) / 256, 256>>>(W2_w, w2th, w2tl, D, OUTD);

    // h = emb[h_ids]; hidden_sum = h
    k_gather<<<ewB, 256>>>(h_ids, emb, N);

    for (int i = 0; i < L; i++) {
        k_scale2<<<ewB, 256>>>(N);
        k_scatter<<<scB, 256>>>(u, v, E);
        k_cvt<<<cvtB, 256>>>(dg_z, zh, zl, N * 128);
        k_mma<512, 0, 0><<<dim3(mtiles, 4), 256, SMEMSZ>>>(
            zh, zl, l1th + (size_t)i * D * D, l1tl + (size_t)i * D * D,
            dg_y, nullptr, nullptr, N, D, nullptr, nullptr, nullptr);
        k_bnzero<<<1, 1024>>>();
        k_bnstats<<<bnB, D>>>(dg_y, N);
        k_bnfin<<<1, D>>>(bn1_g + (size_t)i * D, bn1_b + (size_t)i * D, N);
        k_bnrelu_cvt<<<ewB, 256>>>(dg_y, yh, yl, N);
        k_mma<512, 0, 0><<<dim3(mtiles, 4), 256, SMEMSZ>>>(
            yh, yl, l2th + (size_t)i * D * D, l2tl + (size_t)i * D * D,
            dg_z, nullptr, nullptr, N, D, nullptr, nullptr, nullptr);
        k_bnzero<<<1, 1024>>>();
        k_bnstats<<<bnB, D>>>(dg_z, N);
        k_bnfin<<<1, D>>>(bn2_g + (size_t)i * D, bn2_b + (size_t)i * D, N);
        k_bnrelu_acc<<<ewB, 256>>>(dg_z, N);
    }

    // decoder
    k_cvt<<<cvtB, 256>>>(dg_hsum, hsh, hsl, N * 128);
    k_mma<1024, 1, 1><<<dim3(etiles, 4), 256, SMEMSZ>>>(
        hsh, hsl, w1th, w1tl, nullptr, s1h, s1l, E, D, u, v, W1_b);
    k_mma<512, 0, 2><<<dim3(etiles, 1), 256, SMEMSZ>>>(
        s1h, s1l, w2th, w2tl, out, nullptr, nullptr, E, OUTD, nullptr, nullptr, W2_b);
}

// round 5
// speedup vs baseline: 2.4036x; 1.2900x over previous
#include <cuda_runtime.h>
#include <cuda_bf16.h>

#define D 512
#define OUTD 128
#define MAXN 50000
#define MAXE 150000
#define BN_EPS 1e-5f

// ---------------- scratch (static device globals; no allocation) ----------------
__device__ float g_h[(size_t)MAXN * D];     // current node features
__device__ float g_hsum[(size_t)MAXN * D];  // hidden_sum accumulator
__device__ float g_y[(size_t)MAXN * D];     // gemm1 output
__device__ float g_z[(size_t)MAXN * D];     // gemm2 output
__device__ float g_stats[2 * D];
__device__ float g_aff[2 * D];

// CSR graph
__device__ int g_deg[MAXN];
__device__ int g_off[MAXN + 1];
__device__ int g_cur[MAXN];
__device__ int g_adj[2 * MAXE];

// bf16 split pairs
__device__ __nv_bfloat16 g_zh[(size_t)MAXN * D], g_zl[(size_t)MAXN * D];
__device__ __nv_bfloat16 g_yh[(size_t)MAXN * D], g_yl[(size_t)MAXN * D];
__device__ __nv_bfloat16 g_hsh[(size_t)MAXN * D], g_hsl[(size_t)MAXN * D];
__device__ __nv_bfloat16 g_s1h[(size_t)MAXE * D], g_s1l[(size_t)MAXE * D];
// transposed + split weights: Bt[n][k]
__device__ __nv_bfloat16 g_l1th[(size_t)4 * D * D], g_l1tl[(size_t)4 * D * D];
__device__ __nv_bfloat16 g_l2th[(size_t)4 * D * D], g_l2tl[(size_t)4 * D * D];
__device__ __nv_bfloat16 g_w1th[(size_t)D * 2 * D], g_w1tl[(size_t)D * 2 * D];
__device__ __nv_bfloat16 g_w2th[(size_t)OUTD * D], g_w2tl[(size_t)OUTD * D];

// ---------------- PTX helpers (plain compute_100-legal) ----------------
__device__ __forceinline__ unsigned smem_u32(const void* p) {
    unsigned a;
    asm("{ .reg .u64 t; cvta.to.shared.u64 t, %1; cvt.u32.u64 %0, t; }" : "=r"(a) : "l"(p));
    return a;
}
__device__ __forceinline__ void cpasync16(unsigned dst, const void* src) {
    asm volatile("cp.async.cg.shared.global [%0], [%1], 16;" ::"r"(dst), "l"(src));
}
__device__ __forceinline__ void ldm4(unsigned* r, unsigned addr) {
    asm volatile("ldmatrix.sync.aligned.m8n8.x4.shared.b16 {%0,%1,%2,%3}, [%4];"
                 : "=r"(r[0]), "=r"(r[1]), "=r"(r[2]), "=r"(r[3]) : "r"(addr));
}
__device__ __forceinline__ void mma16816(float* c, const unsigned* a, const unsigned* b) {
    asm volatile(
        "mma.sync.aligned.m16n8k16.row.col.f32.bf16.bf16.f32 "
        "{%0,%1,%2,%3}, {%4,%5,%6,%7}, {%8,%9}, {%0,%1,%2,%3};"
        : "+f"(c[0]), "+f"(c[1]), "+f"(c[2]), "+f"(c[3])
        : "r"(a[0]), "r"(a[1]), "r"(a[2]), "r"(a[3]), "r"(b[0]), "r"(b[1]));
}
__device__ __forceinline__ void f2pair(float v, __nv_bfloat16& h, __nv_bfloat16& l) {
    h = __float2bfloat16(v);
    l = __float2bfloat16(v - __bfloat162float(h));
}

// ---------------- mma.sync split-bf16 GEMM ----------------
// C[M,Nout] = A[M,KTOT] @ Bt[Nout,KTOT]^T, A/Bt given as (hi,lo) bf16 pairs.
// GATHER=1: logical A row r = concat(hs[u[r]], hs[v[r]])  (KTOT=1024, A base = hs).
// EPI: 0 = fp32 store; 1 = relu(x+bias)->bf16 pair; 2 = x+bias -> fp32.
// STATS=1: accumulate per-column sum/sumsq into g_stats (valid rows only).
#define TILE_B   10240
#define STAGE_B  40960
#define SMEMSZ   81920

template <int KTOT, int GATHER, int EPI, int STATS>
__global__ __launch_bounds__(256)
void k_mma(const __nv_bfloat16* __restrict__ Ah, const __nv_bfloat16* __restrict__ Al,
           const __nv_bfloat16* __restrict__ Bh, const __nv_bfloat16* __restrict__ Bl,
           float* __restrict__ Cf, __nv_bfloat16* __restrict__ Ch, __nv_bfloat16* __restrict__ Cl,
           int M, int Nout,
           const int* __restrict__ gu, const int* __restrict__ gv,
           const float* __restrict__ bias) {
    extern __shared__ __align__(16) char smem[];
    __shared__ int s_u[128], s_v[128];
    const int tid = threadIdx.x;
    const int wid = tid >> 5, lane = tid & 31;
    const int wm = wid & 3, wn = wid >> 2;      // 4 x 2 warp grid, warp tile 32x64
    const int bm = blockIdx.x * 128, bn = blockIdx.y * 128;
    const unsigned sb = smem_u32(smem);

    if (GATHER) {
        if (tid < 128) {
            int e = min(bm + tid, M - 1);
            s_u[tid] = gu[e]; s_v[tid] = gv[e];
        }
        __syncthreads();
    }

    const int lrow = tid >> 1;                       // 0..127 (loader row)
    const int grA = GATHER ? 0 : min(bm + lrow, M - 1);
    const int grB = bn + lrow;

    float acc[2][8][4];
#pragma unroll
    for (int i = 0; i < 2; i++)
#pragma unroll
        for (int j = 0; j < 8; j++)
#pragma unroll
            for (int q = 0; q < 4; q++) acc[i][j][q] = 0.f;

#define LOAD_CHUNK(STG, K0)                                                    \
    {                                                                          \
        unsigned st = sb + (STG) * STAGE_B;                                    \
        _Pragma("unroll") for (int j = 0; j < 2; j++) {                        \
            int cc = (tid & 1) * 2 + j;                                        \
            unsigned dsto = lrow * 80 + cc * 16;                               \
            const __nv_bfloat16 *pa_h, *pa_l;                                  \
            if (GATHER) {                                                      \
                int node = ((K0) < 512) ? s_u[lrow] : s_v[lrow];               \
                int ge = ((K0) & 511) + cc * 8;                                \
                pa_h = Ah + (size_t)node * 512 + ge;                           \
                pa_l = Al + (size_t)node * 512 + ge;                           \
            } else {                                                           \
                size_t o = (size_t)grA * KTOT + (K0) + cc * 8;                 \
                pa_h = Ah + o; pa_l = Al + o;                                  \
            }                                                                  \
            cpasync16(st + 0 * TILE_B + dsto, pa_h);                           \
            cpasync16(st + 1 * TILE_B + dsto, pa_l);                           \
            size_t ob = (size_t)grB * KTOT + (K0) + cc * 8;                    \
            cpasync16(st + 2 * TILE_B + dsto, Bh + ob);                        \
            cpasync16(st + 3 * TILE_B + dsto, Bl + ob);                        \
        }                                                                      \
    }

    const int NC = KTOT / 32;
    LOAD_CHUNK(0, 0);
    asm volatile("cp.async.commit_group;");

    for (int c = 0; c < NC; c++) {
        if (c + 1 < NC) {
            LOAD_CHUNK((c + 1) & 1, (c + 1) * 32);
            asm volatile("cp.async.commit_group;");
            asm volatile("cp.async.wait_group 1;");
        } else {
            asm volatile("cp.async.wait_group 0;");
        }
        __syncthreads();

        const unsigned st = sb + (c & 1) * STAGE_B;
#pragma unroll
        for (int ks = 0; ks < 2; ks++) {
            const unsigned koff = ks * 32;  // 16 bf16 per k-step
            unsigned ah[2][4], al[2][4];
#pragma unroll
            for (int mf = 0; mf < 2; mf++) {
                unsigned addr = st + (wm * 32 + mf * 16 + (lane & 15)) * 80 +
                                ((lane >> 4) * 16) + koff;
                ldm4(ah[mf], addr);
                ldm4(al[mf], addr + TILE_B);
            }
#pragma unroll
            for (int nb = 0; nb < 4; nb++) {
                unsigned addr = st + 2 * TILE_B +
                                (wn * 64 + nb * 16 + (lane & 15)) * 80 +
                                ((lane >> 4) * 16) + koff;
                unsigned bh[4], bl[4];
                ldm4(bh, addr);
                ldm4(bl, addr + TILE_B);
                unsigned b0h[2] = {bh[0], bh[2]}, b1h[2] = {bh[1], bh[3]};
                unsigned b0l[2] = {bl[0], bl[2]}, b1l[2] = {bl[1], bl[3]};
#pragma unroll
                for (int mf = 0; mf < 2; mf++) {
                    mma16816(acc[mf][nb * 2], ah[mf], b0h);
                    mma16816(acc[mf][nb * 2], ah[mf], b0l);
                    mma16816(acc[mf][nb * 2], al[mf], b0h);
                    mma16816(acc[mf][nb * 2 + 1], ah[mf], b1h);
                    mma16816(acc[mf][nb * 2 + 1], ah[mf], b1l);
                    mma16816(acc[mf][nb * 2 + 1], al[mf], b1h);
                }
            }
        }
        __syncthreads();
    }
#undef LOAD_CHUNK

    // epilogue: c-frag layout m16n8 -> rows t/4 & t/4+8, cols 2*(t%4)+{0,1}
#pragma unroll
    for (int mf = 0; mf < 2; mf++) {
        const int r0 = bm + wm * 32 + mf * 16 + (lane >> 2);
#pragma unroll
        for (int nf = 0; nf < 8; nf++) {
            const int col = bn + wn * 64 + nf * 8 + (lane & 3) * 2;
            const float* a = acc[mf][nf];
#pragma unroll
            for (int hh = 0; hh < 2; hh++) {
                const int row = r0 + hh * 8;
                if (row >= M) continue;
                float v0 = a[hh * 2], v1 = a[hh * 2 + 1];
                if (EPI == 0) {
                    float2 s = make_float2(v0, v1);
                    *(float2*)(Cf + (size_t)row * Nout + col) = s;
                } else if (EPI == 1) {
                    v0 = fmaxf(v0 + bias[col], 0.f);
                    v1 = fmaxf(v1 + bias[col + 1], 0.f);
                    __nv_bfloat16 h0, l0, h1, l1;
                    f2pair(v0, h0, l0);
                    f2pair(v1, h1, l1);
                    __nv_bfloat162 hp; hp.x = h0; hp.y = h1;
                    __nv_bfloat162 lp; lp.x = l0; lp.y = l1;
                    *(__nv_bfloat162*)(Ch + (size_t)row * Nout + col) = hp;
                    *(__nv_bfloat162*)(Cl + (size_t)row * Nout + col) = lp;
                } else {
                    float2 s = make_float2(v0 + bias[col], v1 + bias[col + 1]);
                    *(float2*)(Cf + (size_t)row * Nout + col) = s;
                }
            }
        }
    }

    if (STATS) {
        // per-column sum / sumsq over valid rows of this CTA's tile
#pragma unroll
        for (int nf = 0; nf < 8; nf++) {
            float s0 = 0.f, s1 = 0.f, q0 = 0.f, q1 = 0.f;
#pragma unroll
            for (int mf = 0; mf < 2; mf++) {
                const int rb = bm + wm * 32 + mf * 16 + (lane >> 2);
#pragma unroll
                for (int hh = 0; hh < 2; hh++) {
                    if (rb + hh * 8 < M) {
                        float v0 = acc[mf][nf][hh * 2], v1 = acc[mf][nf][hh * 2 + 1];
                        s0 += v0; q0 += v0 * v0;
                        s1 += v1; q1 += v1 * v1;
                    }
                }
            }
#pragma unroll
            for (int o = 4; o < 32; o <<= 1) {
                s0 += __shfl_xor_sync(0xffffffffu, s0, o);
                s1 += __shfl_xor_sync(0xffffffffu, s1, o);
                q0 += __shfl_xor_sync(0xffffffffu, q0, o);
                q1 += __shfl_xor_sync(0xffffffffu, q1, o);
            }
            if ((lane >> 2) == 0) {
                int col = bn + wn * 64 + nf * 8 + (lane & 3) * 2;
                atomicAdd(&g_stats[col], s0);
                atomicAdd(&g_stats[col + 1], s1);
                atomicAdd(&g_stats[D + col], q0);
                atomicAdd(&g_stats[D + col + 1], q1);
            }
        }
    }
}

// ---------------- CSR build ----------------
__global__ void k_zerodeg(int Nn) {
    int i = blockIdx.x * blockDim.x + threadIdx.x;
    if (i < Nn) g_deg[i] = 0;
}
__global__ void k_deg(const int* __restrict__ u, const int* __restrict__ v, int E) {
    int e = blockIdx.x * blockDim.x + threadIdx.x;
    if (e >= E) return;
    atomicAdd(&g_deg[u[e]], 1);
    atomicAdd(&g_deg[v[e]], 1);
}
__global__ void k_scan(int Nn) {   // single block, 1024 threads
    __shared__ int warpsum[32];
    __shared__ int s_carry;
    const int tid = threadIdx.x, lane = tid & 31, w = tid >> 5;
    if (tid == 0) s_carry = 0;
    __syncthreads();
    for (int base = 0; base < Nn; base += 1024) {
        int i = base + tid;
        int v = (i < Nn) ? g_deg[i] : 0;
        int x = v;
#pragma unroll
        for (int o = 1; o < 32; o <<= 1) {
            int t = __shfl_up_sync(0xffffffffu, x, o);
            if (lane >= o) x += t;
        }
        if (lane == 31) warpsum[w] = x;
        __syncthreads();
        if (w == 0) {
            int s = warpsum[lane];
#pragma unroll
            for (int o = 1; o < 32; o <<= 1) {
                int t = __shfl_up_sync(0xffffffffu, s, o);
                if (lane >= o) s += t;
            }
            warpsum[lane] = s;
        }
        __syncthreads();
        int incl = x + (w > 0 ? warpsum[w - 1] : 0) + s_carry;
        if (i < Nn) {
            int excl = incl - v;
            g_off[i] = excl;
            g_cur[i] = excl;
        }
        __syncthreads();
        if (tid == 1023) s_carry = incl;
        __syncthreads();
    }
    if (tid == 0) g_off[Nn] = s_carry;
}
__global__ void k_fill(const int* __restrict__ u, const int* __restrict__ v, int E) {
    int e = blockIdx.x * blockDim.x + threadIdx.x;
    if (e >= E) return;
    int a = u[e], b = v[e];
    int p = atomicAdd(&g_cur[b], 1);
    g_adj[p] = a;
    int q = atomicAdd(&g_cur[a], 1);
    g_adj[q] = b;
}

// ---------------- aggregation: z = 2h + sum_{nb} h[nb]  -> bf16 pairs ----------------
__global__ void k_agg(int Nn) {
    int node = blockIdx.x * 8 + (threadIdx.x >> 5);
    if (node >= Nn) return;
    const int lane = threadIdx.x & 31;
    float4 acc[4];
    const float4* hp = (const float4*)(g_h + (size_t)node * D);
#pragma unroll
    for (int j = 0; j < 4; j++) {
        float4 t = hp[j * 32 + lane];
        acc[j] = make_float4(2.f * t.x, 2.f * t.y, 2.f * t.z, 2.f * t.w);
    }
    const int e1 = g_off[node + 1];
    for (int e = g_off[node]; e < e1; e++) {
        const float4* np = (const float4*)(g_h + (size_t)g_adj[e] * D);
#pragma unroll
        for (int j = 0; j < 4; j++) {
            float4 t = np[j * 32 + lane];
            acc[j].x += t.x; acc[j].y += t.y; acc[j].z += t.z; acc[j].w += t.w;
        }
    }
#pragma unroll
    for (int j = 0; j < 4; j++) {
        __nv_bfloat16 h0, l0, h1, l1, h2, l2, h3, l3;
        f2pair(acc[j].x, h0, l0); f2pair(acc[j].y, h1, l1);
        f2pair(acc[j].z, h2, l2); f2pair(acc[j].w, h3, l3);
        size_t o = (size_t)node * D + (j * 32 + lane) * 4;
        __nv_bfloat162 a;
        a.x = h0; a.y = h1; ((__nv_bfloat162*)(g_zh + o))[0] = a;
        a.x = h2; a.y = h3; ((__nv_bfloat162*)(g_zh + o))[1] = a;
        a.x = l0; a.y = l1; ((__nv_bfloat162*)(g_zl + o))[0] = a;
        a.x = l2; a.y = l3; ((__nv_bfloat162*)(g_zl + o))[1] = a;
    }
}

// ---------------- elementwise kernels ----------------
__global__ void k_gather(const int* __restrict__ ids, const float* __restrict__ emb, int Nn) {
    int idx = blockIdx.x * blockDim.x + threadIdx.x;
    int row = idx >> 7;
    if (row >= Nn) return;
    int c = (idx & 127) << 2;
    float4 val = *(const float4*)(emb + (size_t)ids[row] * D + c);
    *(float4*)(g_h + (size_t)row * D + c) = val;
    *(float4*)(g_hsum + (size_t)row * D + c) = val;
}

// fp32 -> bf16 pair
__global__ void k_cvt(const float* __restrict__ X, __nv_bfloat16* __restrict__ H,
                      __nv_bfloat16* __restrict__ Lo, int n4) {
    int i = blockIdx.x * blockDim.x + threadIdx.x;
    if (i >= n4) return;
    float4 v = *(const float4*)(X + (size_t)i * 4);
    __nv_bfloat16 h0, l0, h1, l1, h2, l2, h3, l3;
    f2pair(v.x, h0, l0); f2pair(v.y, h1, l1);
    f2pair(v.z, h2, l2); f2pair(v.w, h3, l3);
    __nv_bfloat162* Hp = (__nv_bfloat162*)(H + (size_t)i * 4);
    __nv_bfloat162* Lp = (__nv_bfloat162*)(Lo + (size_t)i * 4);
    __nv_bfloat162 a; a.x = h0; a.y = h1; Hp[0] = a;
    a.x = h2; a.y = h3; Hp[1] = a;
    a.x = l0; a.y = l1; Lp[0] = a;
    a.x = l2; a.y = l3; Lp[1] = a;
}

// weight transpose+convert: src [K,Nn] row-major -> dst [Nn,K] pairs
__global__ void k_tcvt(const float* __restrict__ B, __nv_bfloat16* __restrict__ H,
                       __nv_bfloat16* __restrict__ Lo, int K, int Nn) {
    int idx = blockIdx.x * blockDim.x + threadIdx.x;
    if (idx >= K * Nn) return;
    int n = idx / K, k = idx - n * K;
    float x = B[(size_t)k * Nn + n];
    __nv_bfloat16 h, l;
    f2pair(x, h, l);
    H[idx] = h; Lo[idx] = l;
}

__global__ void k_bnzero() {
    int t = threadIdx.x;
    if (t < 2 * D) g_stats[t] = 0.f;
}

__global__ void k_bnfin(const float* __restrict__ gamma, const float* __restrict__ beta, int M) {
    int j = threadIdx.x;
    if (j >= D) return;
    float inv = 1.f / (float)M;
    float m = g_stats[j] * inv;
    float var = g_stats[D + j] * inv - m * m;
    float sc = gamma[j] * rsqrtf(var + BN_EPS);
    g_aff[j] = sc;
    g_aff[D + j] = beta[j] - m * sc;
}

// relu(affine(Y)) -> bf16 pairs
__global__ void k_bnrelu_cvt(const float* __restrict__ Y, __nv_bfloat16* __restrict__ H,
                             __nv_bfloat16* __restrict__ Lo, int Nn) {
    int idx = blockIdx.x * blockDim.x + threadIdx.x;
    if (idx >= Nn * 128) return;
    int c = (idx & 127) << 2;
    float4 v = *(const float4*)(Y + (size_t)idx * 4);
    v.x = fmaxf(v.x * g_aff[c + 0] + g_aff[D + c + 0], 0.f);
    v.y = fmaxf(v.y * g_aff[c + 1] + g_aff[D + c + 1], 0.f);
    v.z = fmaxf(v.z * g_aff[c + 2] + g_aff[D + c + 2], 0.f);
    v.w = fmaxf(v.w * g_aff[c + 3] + g_aff[D + c + 3], 0.f);
    __nv_bfloat16 h0, l0, h1, l1, h2, l2, h3, l3;
    f2pair(v.x, h0, l0); f2pair(v.y, h1, l1);
    f2pair(v.z, h2, l2); f2pair(v.w, h3, l3);
    __nv_bfloat162* Hp = (__nv_bfloat162*)(H + (size_t)idx * 4);
    __nv_bfloat162* Lp = (__nv_bfloat162*)(Lo + (size_t)idx * 4);
    __nv_bfloat162 a; a.x = h0; a.y = h1; Hp[0] = a;
    a.x = h2; a.y = h3; Hp[1] = a;
    a.x = l0; a.y = l1; Lp[0] = a;
    a.x = l2; a.y = l3; Lp[1] = a;
}

// h = relu(affine(Y2)); hsum += h   (fp32)
__global__ void k_bnrelu_acc(const float* __restrict__ Y2, int Nn) {
    int idx = blockIdx.x * blockDim.x + threadIdx.x;
    if (idx >= Nn * 128) return;
    int c = (idx & 127) << 2;
    float4 v = *(const float4*)(Y2 + (size_t)idx * 4);
    v.x = fmaxf(v.x * g_aff[c + 0] + g_aff[D + c + 0], 0.f);
    v.y = fmaxf(v.y * g_aff[c + 1] + g_aff[D + c + 1], 0.f);
    v.z = fmaxf(v.z * g_aff[c + 2] + g_aff[D + c + 2], 0.f);
    v.w = fmaxf(v.w * g_aff[c + 3] + g_aff[D + c + 3], 0.f);
    *(float4*)(g_h + (size_t)idx * 4) = v;
    float4 hs = *(const float4*)(g_hsum + (size_t)idx * 4);
    hs.x += v.x; hs.y += v.y; hs.z += v.z; hs.w += v.w;
    *(float4*)(g_hsum + (size_t)idx * 4) = hs;
}

// ---------------- launch ----------------
extern "C" void kernel_launch(void* const* d_in, const int* in_sizes, int n_in,
                              void* d_out, int out_size) {
    const int* h_ids = (const int*)d_in[0];
    const int* u     = (const int*)d_in[1];
    const int* v     = (const int*)d_in[2];
    const float* emb   = (const float*)d_in[3];
    const float* lin1  = (const float*)d_in[4];
    const float* lin2  = (const float*)d_in[5];
    const float* bn1_g = (const float*)d_in[6];
    const float* bn1_b = (const float*)d_in[7];
    const float* bn2_g = (const float*)d_in[8];
    const float* bn2_b = (const float*)d_in[9];
    const float* W1_w  = (const float*)d_in[10];
    const float* W1_b  = (const float*)d_in[11];
    const float* W2_w  = (const float*)d_in[12];
    const float* W2_b  = (const float*)d_in[13];
    float* out = (float*)d_out;

    const int N = in_sizes[0];
    const int E = in_sizes[1];
    const int L = in_sizes[4] / (D * D);

    static int s_attr = 0;
    if (!s_attr) {
        cudaFuncSetAttribute(k_mma<512, 0, 0, 1>,  cudaFuncAttributeMaxDynamicSharedMemorySize, SMEMSZ);
        cudaFuncSetAttribute(k_mma<1024, 1, 1, 0>, cudaFuncAttributeMaxDynamicSharedMemorySize, SMEMSZ);
        cudaFuncSetAttribute(k_mma<512, 0, 2, 0>,  cudaFuncAttributeMaxDynamicSharedMemorySize, SMEMSZ);
        s_attr = 1;
    }

    float *dg_z, *dg_y, *dg_hsum;
    cudaGetSymbolAddress((void**)&dg_z, g_z);
    cudaGetSymbolAddress((void**)&dg_y, g_y);
    cudaGetSymbolAddress((void**)&dg_hsum, g_hsum);
    __nv_bfloat16 *zh, *zl, *yh, *yl, *hsh, *hsl, *s1h, *s1l;
    __nv_bfloat16 *l1th, *l1tl, *l2th, *l2tl, *w1th, *w1tl, *w2th, *w2tl;
    cudaGetSymbolAddress((void**)&zh, g_zh);  cudaGetSymbolAddress((void**)&zl, g_zl);
    cudaGetSymbolAddress((void**)&yh, g_yh);  cudaGetSymbolAddress((void**)&yl, g_yl);
    cudaGetSymbolAddress((void**)&hsh, g_hsh); cudaGetSymbolAddress((void**)&hsl, g_hsl);
    cudaGetSymbolAddress((void**)&s1h, g_s1h); cudaGetSymbolAddress((void**)&s1l, g_s1l);
    cudaGetSymbolAddress((void**)&l1th, g_l1th); cudaGetSymbolAddress((void**)&l1tl, g_l1tl);
    cudaGetSymbolAddress((void**)&l2th, g_l2th); cudaGetSymbolAddress((void**)&l2tl, g_l2tl);
    cudaGetSymbolAddress((void**)&w1th, g_w1th); cudaGetSymbolAddress((void**)&w1tl, g_w1tl);
    cudaGetSymbolAddress((void**)&w2th, g_w2th); cudaGetSymbolAddress((void**)&w2tl, g_w2tl);

    const int ew = N * 128, ewB = (ew + 255) / 256;
    const int mtiles = (N + 127) / 128;
    const int etiles = (E + 127) / 128;
    const int cvtB = (N * 128 + 255) / 256;
    const int edB = (E + 255) / 256;
    const int ndB = (N + 255) / 256;
    const int aggB = (N + 7) / 8;

    // weight conversion (transpose + split)
    const int wB = (D * D + 255) / 256;
    for (int i = 0; i < L; i++) {
        k_tcvt<<<wB, 256>>>(lin1 + (size_t)i * D * D, l1th + (size_t)i * D * D, l1tl + (size_t)i * D * D, D, D);
        k_tcvt<<<wB, 256>>>(lin2 + (size_t)i * D * D, l2th + (size_t)i * D * D, l2tl + (size_t)i * D * D, D, D);
    }
    k_tcvt<<<(2 * D * D + 255) / 256, 256>>>(W1_w, w1th, w1tl, 2 * D, D);
    k_tcvt<<<(D * OUTD + 255) / 256, 256>>>(W2_w, w2th, w2tl, D, OUTD);

    // h = emb[h_ids]; hidden_sum = h
    k_gather<<<ewB, 256>>>(h_ids, emb, N);

    // CSR build (once)
    k_zerodeg<<<ndB, 256>>>(N);
    k_deg<<<edB, 256>>>(u, v, E);
    k_scan<<<1, 1024>>>(N);
    k_fill<<<edB, 256>>>(u, v, E);

    for (int i = 0; i < L; i++) {
        // z = 2h + neighbor sums -> bf16 pairs
        k_agg<<<aggB, 256>>>(N);
        // y = z @ lin1[i]  (+ fused BN stats)
        k_bnzero<<<1, 1024>>>();
        k_mma<512, 0, 0, 1><<<dim3(mtiles, 4), 256, SMEMSZ>>>(
            zh, zl, l1th + (size_t)i * D * D, l1tl + (size_t)i * D * D,
            dg_y, nullptr, nullptr, N, D, nullptr, nullptr, nullptr);
        k_bnfin<<<1, D>>>(bn1_g + (size_t)i * D, bn1_b + (size_t)i * D, N);
        k_bnrelu_cvt<<<ewB, 256>>>(dg_y, yh, yl, N);
        // z(out) = y @ lin2[i]  (+ fused BN stats)
        k_bnzero<<<1, 1024>>>();
        k_mma<512, 0, 0, 1><<<dim3(mtiles, 4), 256, SMEMSZ>>>(
            yh, yl, l2th + (size_t)i * D * D, l2tl + (size_t)i * D * D,
            dg_z, nullptr, nullptr, N, D, nullptr, nullptr, nullptr);
        k_bnfin<<<1, D>>>(bn2_g + (size_t)i * D, bn2_b + (size_t)i * D, N);
        k_bnrelu_acc<<<ewB, 256>>>(dg_z, N);
    }

    // decoder
    k_cvt<<<cvtB, 256>>>(dg_hsum, hsh, hsl, N * 128);
    k_mma<1024, 1, 1, 0><<<dim3(etiles, 4), 256, SMEMSZ>>>(
        hsh, hsl, w1th, w1tl, nullptr, s1h, s1l, E, D, u, v, W1_b);
    k_mma<512, 0, 2, 0><<<dim3(etiles, 1), 256, SMEMSZ>>>(
        s1h, s1l, w2th, w2tl, out, nullptr, nullptr, E, OUTD, nullptr, nullptr, W2_b);
}

// round 6
// speedup vs baseline: 2.6863x; 1.1176x over previous
#include <cuda_runtime.h>
#include <cuda_bf16.h>

#define D 512
#define OUTD 128
#define MAXN 50000
#define MAXE 150000
#define BN_EPS 1e-5f

// ---------------- scratch (static device globals; no allocation) ----------------
__device__ float g_h[(size_t)MAXN * D];     // current node features
__device__ float g_hsum[(size_t)MAXN * D];  // hidden_sum accumulator
__device__ float g_y[(size_t)MAXN * D];     // gemm1 output / P
__device__ float g_z[(size_t)MAXN * D];     // gemm2 output / Q
__device__ float g_stats[2 * D];
__device__ float g_aff[2 * D];

// CSR graph
__device__ int g_deg[MAXN];
__device__ int g_off[MAXN + 1];
__device__ int g_cur[MAXN];
__device__ int g_adj[2 * MAXE];

// bf16 split pairs
__device__ __nv_bfloat16 g_zh[(size_t)MAXN * D], g_zl[(size_t)MAXN * D];
__device__ __nv_bfloat16 g_yh[(size_t)MAXN * D], g_yl[(size_t)MAXN * D];
__device__ __nv_bfloat16 g_hsh[(size_t)MAXN * D], g_hsl[(size_t)MAXN * D];
__device__ __nv_bfloat16 g_s1h[(size_t)MAXE * D], g_s1l[(size_t)MAXE * D];
// transposed + split weights: Bt[n][k]
__device__ __nv_bfloat16 g_l1th[(size_t)4 * D * D], g_l1tl[(size_t)4 * D * D];
__device__ __nv_bfloat16 g_l2th[(size_t)4 * D * D], g_l2tl[(size_t)4 * D * D];
__device__ __nv_bfloat16 g_w1th[(size_t)D * 2 * D], g_w1tl[(size_t)D * 2 * D];  // [a half | b half]
__device__ __nv_bfloat16 g_w2th[(size_t)OUTD * D], g_w2tl[(size_t)OUTD * D];

// ---------------- PTX helpers (plain compute_100-legal) ----------------
__device__ __forceinline__ unsigned smem_u32(const void* p) {
    unsigned a;
    asm("{ .reg .u64 t; cvta.to.shared.u64 t, %1; cvt.u32.u64 %0, t; }" : "=r"(a) : "l"(p));
    return a;
}
__device__ __forceinline__ void cpasync16(unsigned dst, const void* src) {
    asm volatile("cp.async.cg.shared.global [%0], [%1], 16;" ::"r"(dst), "l"(src));
}
__device__ __forceinline__ void ldm4(unsigned* r, unsigned addr) {
    asm volatile("ldmatrix.sync.aligned.m8n8.x4.shared.b16 {%0,%1,%2,%3}, [%4];"
                 : "=r"(r[0]), "=r"(r[1]), "=r"(r[2]), "=r"(r[3]) : "r"(addr));
}
__device__ __forceinline__ void mma16816(float* c, const unsigned* a, const unsigned* b) {
    asm volatile(
        "mma.sync.aligned.m16n8k16.row.col.f32.bf16.bf16.f32 "
        "{%0,%1,%2,%3}, {%4,%5,%6,%7}, {%8,%9}, {%0,%1,%2,%3};"
        : "+f"(c[0]), "+f"(c[1]), "+f"(c[2]), "+f"(c[3])
        : "r"(a[0]), "r"(a[1]), "r"(a[2]), "r"(a[3]), "r"(b[0]), "r"(b[1]));
}
__device__ __forceinline__ void f2pair(float v, __nv_bfloat16& h, __nv_bfloat16& l) {
    h = __float2bfloat16(v);
    l = __float2bfloat16(v - __bfloat162float(h));
}

// ---------------- mma.sync split-bf16 GEMM, 4-stage cp.async pipeline ----------------
// C[M,Nout] = A[M,KTOT] @ Bt[Nout,KTOT]^T, A/Bt given as (hi,lo) bf16 pairs.
// EPI: 0 = fp32 store; 2 = x+bias -> fp32.
// STATS=1: accumulate per-column sum/sumsq into g_stats (valid rows only).
#define TILE_B   10240
#define STAGE_B  40960
#define NSTAGE   4
#define SMEMSZ   (NSTAGE * STAGE_B)

template <int KTOT, int EPI, int STATS>
__global__ __launch_bounds__(256)
void k_mma(const __nv_bfloat16* __restrict__ Ah, const __nv_bfloat16* __restrict__ Al,
           const __nv_bfloat16* __restrict__ Bh, const __nv_bfloat16* __restrict__ Bl,
           float* __restrict__ Cf, int M, int Nout,
           const float* __restrict__ bias) {
    extern __shared__ __align__(16) char smem[];
    const int tid = threadIdx.x;
    const int wid = tid >> 5, lane = tid & 31;
    const int wm = wid & 3, wn = wid >> 2;      // 4 x 2 warp grid, warp tile 32x64
    const int bm = blockIdx.x * 128, bn = blockIdx.y * 128;
    const unsigned sb = smem_u32(smem);

    const int lrow = tid >> 1;                       // 0..127 (loader row)
    const int grA = min(bm + lrow, M - 1);
    const int grB = bn + lrow;

    float acc[2][8][4];
#pragma unroll
    for (int i = 0; i < 2; i++)
#pragma unroll
        for (int j = 0; j < 8; j++)
#pragma unroll
            for (int q = 0; q < 4; q++) acc[i][j][q] = 0.f;

#define LOAD_CHUNK(STG, K0)                                                    \
    {                                                                          \
        unsigned st = sb + (STG) * STAGE_B;                                    \
        _Pragma("unroll") for (int j = 0; j < 2; j++) {                        \
            int cc = (tid & 1) * 2 + j;                                        \
            unsigned dsto = lrow * 80 + cc * 16;                               \
            size_t o = (size_t)grA * KTOT + (K0) + cc * 8;                     \
            cpasync16(st + 0 * TILE_B + dsto, Ah + o);                         \
            cpasync16(st + 1 * TILE_B + dsto, Al + o);                         \
            size_t ob = (size_t)grB * KTOT + (K0) + cc * 8;                    \
            cpasync16(st + 2 * TILE_B + dsto, Bh + ob);                        \
            cpasync16(st + 3 * TILE_B + dsto, Bl + ob);                        \
        }                                                                      \
    }

    const int NC = KTOT / 32;
    // prologue: fill 3 stages (commit a group per stage, even if empty)
#pragma unroll
    for (int p = 0; p < NSTAGE - 1; p++) {
        if (p < NC) LOAD_CHUNK(p, p * 32);
        asm volatile("cp.async.commit_group;");
    }

    for (int c = 0; c < NC; c++) {
        // wait for chunk c's group; then CTA-wide visibility + all warps done
        // computing chunk c-1 (so stage (c+3)&3 == (c-1)&3 is free to overwrite)
        asm volatile("cp.async.wait_group %0;" ::"n"(NSTAGE - 2));
        __syncthreads();
        if (c + NSTAGE - 1 < NC) LOAD_CHUNK((c + NSTAGE - 1) & (NSTAGE - 1), (c + NSTAGE - 1) * 32);
        asm volatile("cp.async.commit_group;");

        const unsigned st = sb + (c & (NSTAGE - 1)) * STAGE_B;
#pragma unroll
        for (int ks = 0; ks < 2; ks++) {
            const unsigned koff = ks * 32;  // 16 bf16 per k-step
            unsigned ah[2][4], al[2][4];
#pragma unroll
            for (int mf = 0; mf < 2; mf++) {
                unsigned addr = st + (wm * 32 + mf * 16 + (lane & 15)) * 80 +
                                ((lane >> 4) * 16) + koff;
                ldm4(ah[mf], addr);
                ldm4(al[mf], addr + TILE_B);
            }
#pragma unroll
            for (int nb = 0; nb < 4; nb++) {
                unsigned addr = st + 2 * TILE_B +
                                (wn * 64 + nb * 16 + (lane & 15)) * 80 +
                                ((lane >> 4) * 16) + koff;
                unsigned bh[4], bl[4];
                ldm4(bh, addr);
                ldm4(bl, addr + TILE_B);
                unsigned b0h[2] = {bh[0], bh[2]}, b1h[2] = {bh[1], bh[3]};
                unsigned b0l[2] = {bl[0], bl[2]}, b1l[2] = {bl[1], bl[3]};
#pragma unroll
                for (int mf = 0; mf < 2; mf++) {
                    mma16816(acc[mf][nb * 2], ah[mf], b0h);
                    mma16816(acc[mf][nb * 2], ah[mf], b0l);
                    mma16816(acc[mf][nb * 2], al[mf], b0h);
                    mma16816(acc[mf][nb * 2 + 1], ah[mf], b1h);
                    mma16816(acc[mf][nb * 2 + 1], ah[mf], b1l);
                    mma16816(acc[mf][nb * 2 + 1], al[mf], b1h);
                }
            }
        }
    }
#undef LOAD_CHUNK

    // epilogue: c-frag layout m16n8 -> rows t/4 & t/4+8, cols 2*(t%4)+{0,1}
#pragma unroll
    for (int mf = 0; mf < 2; mf++) {
        const int r0 = bm + wm * 32 + mf * 16 + (lane >> 2);
#pragma unroll
        for (int nf = 0; nf < 8; nf++) {
            const int col = bn + wn * 64 + nf * 8 + (lane & 3) * 2;
            const float* a = acc[mf][nf];
#pragma unroll
            for (int hh = 0; hh < 2; hh++) {
                const int row = r0 + hh * 8;
                if (row >= M) continue;
                float v0 = a[hh * 2], v1 = a[hh * 2 + 1];
                if (EPI == 0) {
                    float2 s = make_float2(v0, v1);
                    *(float2*)(Cf + (size_t)row * Nout + col) = s;
                } else {
                    float2 s = make_float2(v0 + bias[col], v1 + bias[col + 1]);
                    *(float2*)(Cf + (size_t)row * Nout + col) = s;
                }
            }
        }
    }

    if (STATS) {
#pragma unroll
        for (int nf = 0; nf < 8; nf++) {
            float s0 = 0.f, s1 = 0.f, q0 = 0.f, q1 = 0.f;
#pragma unroll
            for (int mf = 0; mf < 2; mf++) {
                const int rb = bm + wm * 32 + mf * 16 + (lane >> 2);
#pragma unroll
                for (int hh = 0; hh < 2; hh++) {
                    if (rb + hh * 8 < M) {
                        float v0 = acc[mf][nf][hh * 2], v1 = acc[mf][nf][hh * 2 + 1];
                        s0 += v0; q0 += v0 * v0;
                        s1 += v1; q1 += v1 * v1;
                    }
                }
            }
#pragma unroll
            for (int o = 4; o < 32; o <<= 1) {
                s0 += __shfl_xor_sync(0xffffffffu, s0, o);
                s1 += __shfl_xor_sync(0xffffffffu, s1, o);
                q0 += __shfl_xor_sync(0xffffffffu, q0, o);
                q1 += __shfl_xor_sync(0xffffffffu, q1, o);
            }
            if ((lane >> 2) == 0) {
                int col = bn + wn * 64 + nf * 8 + (lane & 3) * 2;
                atomicAdd(&g_stats[col], s0);
                atomicAdd(&g_stats[col + 1], s1);
                atomicAdd(&g_stats[D + col], q0);
                atomicAdd(&g_stats[D + col + 1], q1);
            }
        }
    }
}

// ---------------- CSR build ----------------
__global__ void k_zerodeg(int Nn) {
    int i = blockIdx.x * blockDim.x + threadIdx.x;
    if (i < Nn) g_deg[i] = 0;
}
__global__ void k_deg(const int* __restrict__ u, const int* __restrict__ v, int E) {
    int e = blockIdx.x * blockDim.x + threadIdx.x;
    if (e >= E) return;
    atomicAdd(&g_deg[u[e]], 1);
    atomicAdd(&g_deg[v[e]], 1);
}
__global__ void k_scan(int Nn) {   // single block, 1024 threads
    __shared__ int warpsum[32];
    __shared__ int s_carry;
    const int tid = threadIdx.x, lane = tid & 31, w = tid >> 5;
    if (tid == 0) s_carry = 0;
    __syncthreads();
    for (int base = 0; base < Nn; base += 1024) {
        int i = base + tid;
        int v = (i < Nn) ? g_deg[i] : 0;
        int x = v;
#pragma unroll
        for (int o = 1; o < 32; o <<= 1) {
            int t = __shfl_up_sync(0xffffffffu, x, o);
            if (lane >= o) x += t;
        }
        if (lane == 31) warpsum[w] = x;
        __syncthreads();
        if (w == 0) {
            int s = warpsum[lane];
#pragma unroll
            for (int o = 1; o < 32; o <<= 1) {
                int t = __shfl_up_sync(0xffffffffu, s, o);
                if (lane >= o) s += t;
            }
            warpsum[lane] = s;
        }
        __syncthreads();
        int incl = x + (w > 0 ? warpsum[w - 1] : 0) + s_carry;
        if (i < Nn) {
            int excl = incl - v;
            g_off[i] = excl;
            g_cur[i] = excl;
        }
        __syncthreads();
        if (tid == 1023) s_carry = incl;
        __syncthreads();
    }
    if (tid == 0) g_off[Nn] = s_carry;
}
__global__ void k_fill(const int* __restrict__ u, const int* __restrict__ v, int E) {
    int e = blockIdx.x * blockDim.x + threadIdx.x;
    if (e >= E) return;
    int a = u[e], b = v[e];
    int p = atomicAdd(&g_cur[b], 1);
    g_adj[p] = a;
    int q = atomicAdd(&g_cur[a], 1);
    g_adj[q] = b;
}

// ---------------- aggregation: z = 2h + sum_{nb} h[nb]  -> bf16 pairs ----------------
__global__ void k_agg(int Nn) {
    int node = blockIdx.x * 8 + (threadIdx.x >> 5);
    if (node >= Nn) return;
    const int lane = threadIdx.x & 31;
    float4 acc[4];
    const float4* hp = (const float4*)(g_h + (size_t)node * D);
#pragma unroll
    for (int j = 0; j < 4; j++) {
        float4 t = hp[j * 32 + lane];
        acc[j] = make_float4(2.f * t.x, 2.f * t.y, 2.f * t.z, 2.f * t.w);
    }
    const int e1 = g_off[node + 1];
    for (int e = g_off[node]; e < e1; e++) {
        const float4* np = (const float4*)(g_h + (size_t)g_adj[e] * D);
#pragma unroll
        for (int j = 0; j < 4; j++) {
            float4 t = np[j * 32 + lane];
            acc[j].x += t.x; acc[j].y += t.y; acc[j].z += t.z; acc[j].w += t.w;
        }
    }
#pragma unroll
    for (int j = 0; j < 4; j++) {
        __nv_bfloat16 h0, l0, h1, l1, h2, l2, h3, l3;
        f2pair(acc[j].x, h0, l0); f2pair(acc[j].y, h1, l1);
        f2pair(acc[j].z, h2, l2); f2pair(acc[j].w, h3, l3);
        size_t o = (size_t)node * D + (j * 32 + lane) * 4;
        __nv_bfloat162 a;
        a.x = h0; a.y = h1; ((__nv_bfloat162*)(g_zh + o))[0] = a;
        a.x = h2; a.y = h3; ((__nv_bfloat162*)(g_zh + o))[1] = a;
        a.x = l0; a.y = l1; ((__nv_bfloat162*)(g_zl + o))[0] = a;
        a.x = l2; a.y = l3; ((__nv_bfloat162*)(g_zl + o))[1] = a;
    }
}

// ---------------- elementwise kernels ----------------
__global__ void k_gather(const int* __restrict__ ids, const float* __restrict__ emb, int Nn) {
    int idx = blockIdx.x * blockDim.x + threadIdx.x;
    int row = idx >> 7;
    if (row >= Nn) return;
    int c = (idx & 127) << 2;
    float4 val = *(const float4*)(emb + (size_t)ids[row] * D + c);
    *(float4*)(g_h + (size_t)row * D + c) = val;
    *(float4*)(g_hsum + (size_t)row * D + c) = val;
}

// fp32 -> bf16 pair
__global__ void k_cvt(const float* __restrict__ X, __nv_bfloat16* __restrict__ H,
                      __nv_bfloat16* __restrict__ Lo, int n4) {
    int i = blockIdx.x * blockDim.x + threadIdx.x;
    if (i >= n4) return;
    float4 v = *(const float4*)(X + (size_t)i * 4);
    __nv_bfloat16 h0, l0, h1, l1, h2, l2, h3, l3;
    f2pair(v.x, h0, l0); f2pair(v.y, h1, l1);
    f2pair(v.z, h2, l2); f2pair(v.w, h3, l3);
    __nv_bfloat162* Hp = (__nv_bfloat162*)(H + (size_t)i * 4);
    __nv_bfloat162* Lp = (__nv_bfloat162*)(Lo + (size_t)i * 4);
    __nv_bfloat162 a; a.x = h0; a.y = h1; Hp[0] = a;
    a.x = h2; a.y = h3; Hp[1] = a;
    a.x = l0; a.y = l1; Lp[0] = a;
    a.x = l2; a.y = l3; Lp[1] = a;
}

// weight transpose+convert: src [K,Nn] row-major -> dst [Nn,K] pairs
__global__ void k_tcvt(const float* __restrict__ B, __nv_bfloat16* __restrict__ H,
                       __nv_bfloat16* __restrict__ Lo, int K, int Nn) {
    int idx = blockIdx.x * blockDim.x + threadIdx.x;
    if (idx >= K * Nn) return;
    int n = idx / K, k = idx - n * K;
    float x = B[(size_t)k * Nn + n];
    __nv_bfloat16 h, l;
    f2pair(x, h, l);
    H[idx] = h; Lo[idx] = l;
}

__global__ void k_bnzero() {
    int t = threadIdx.x;
    if (t < 2 * D) g_stats[t] = 0.f;
}

__global__ void k_bnfin(const float* __restrict__ gamma, const float* __restrict__ beta, int M) {
    int j = threadIdx.x;
    if (j >= D) return;
    float inv = 1.f / (float)M;
    float m = g_stats[j] * inv;
    float var = g_stats[D + j] * inv - m * m;
    float sc = gamma[j] * rsqrtf(var + BN_EPS);
    g_aff[j] = sc;
    g_aff[D + j] = beta[j] - m * sc;
}

// relu(affine(Y)) -> bf16 pairs
__global__ void k_bnrelu_cvt(const float* __restrict__ Y, __nv_bfloat16* __restrict__ H,
                             __nv_bfloat16* __restrict__ Lo, int Nn) {
    int idx = blockIdx.x * blockDim.x + threadIdx.x;
    if (idx >= Nn * 128) return;
    int c = (idx & 127) << 2;
    float4 v = *(const float4*)(Y + (size_t)idx * 4);
    v.x = fmaxf(v.x * g_aff[c + 0] + g_aff[D + c + 0], 0.f);
    v.y = fmaxf(v.y * g_aff[c + 1] + g_aff[D + c + 1], 0.f);
    v.z = fmaxf(v.z * g_aff[c + 2] + g_aff[D + c + 2], 0.f);
    v.w = fmaxf(v.w * g_aff[c + 3] + g_aff[D + c + 3], 0.f);
    __nv_bfloat16 h0, l0, h1, l1, h2, l2, h3, l3;
    f2pair(v.x, h0, l0); f2pair(v.y, h1, l1);
    f2pair(v.z, h2, l2); f2pair(v.w, h3, l3);
    __nv_bfloat162* Hp = (__nv_bfloat162*)(H + (size_t)idx * 4);
    __nv_bfloat162* Lp = (__nv_bfloat162*)(Lo + (size_t)idx * 4);
    __nv_bfloat162 a; a.x = h0; a.y = h1; Hp[0] = a;
    a.x = h2; a.y = h3; Hp[1] = a;
    a.x = l0; a.y = l1; Lp[0] = a;
    a.x = l2; a.y = l3; Lp[1] = a;
}

// h = relu(affine(Y2)); hsum += h   (fp32)
__global__ void k_bnrelu_acc(const float* __restrict__ Y2, int Nn) {
    int idx = blockIdx.x * blockDim.x + threadIdx.x;
    if (idx >= Nn * 128) return;
    int c = (idx & 127) << 2;
    float4 v = *(const float4*)(Y2 + (size_t)idx * 4);
    v.x = fmaxf(v.x * g_aff[c + 0] + g_aff[D + c + 0], 0.f);
    v.y = fmaxf(v.y * g_aff[c + 1] + g_aff[D + c + 1], 0.f);
    v.z = fmaxf(v.z * g_aff[c + 2] + g_aff[D + c + 2], 0.f);
    v.w = fmaxf(v.w * g_aff[c + 3] + g_aff[D + c + 3], 0.f);
    *(float4*)(g_h + (size_t)idx * 4) = v;
    float4 hs = *(const float4*)(g_hsum + (size_t)idx * 4);
    hs.x += v.x; hs.y += v.y; hs.z += v.z; hs.w += v.w;
    *(float4*)(g_hsum + (size_t)idx * 4) = hs;
}

// s1[e] = relu(P[u[e]] + Q[v[e]] + bias) -> bf16 pairs
__global__ void k_edge(const int* __restrict__ u, const int* __restrict__ v,
                       const float* __restrict__ bias, int E) {
    int idx = blockIdx.x * blockDim.x + threadIdx.x;
    if (idx >= E * 128) return;
    int e = idx >> 7;
    int c = (idx & 127) << 2;
    int a = __ldg(u + e), b = __ldg(v + e);
    float4 p = *(const float4*)(g_y + (size_t)a * D + c);
    float4 q = *(const float4*)(g_z + (size_t)b * D + c);
    float4 bb = *(const float4*)(bias + c);
    float x0 = fmaxf(p.x + q.x + bb.x, 0.f);
    float x1 = fmaxf(p.y + q.y + bb.y, 0.f);
    float x2 = fmaxf(p.z + q.z + bb.z, 0.f);
    float x3 = fmaxf(p.w + q.w + bb.w, 0.f);
    __nv_bfloat16 h0, l0, h1, l1, h2, l2, h3, l3;
    f2pair(x0, h0, l0); f2pair(x1, h1, l1);
    f2pair(x2, h2, l2); f2pair(x3, h3, l3);
    size_t o = (size_t)e * D + c;
    __nv_bfloat162 t;
    t.x = h0; t.y = h1; ((__nv_bfloat162*)(g_s1h + o))[0] = t;
    t.x = h2; t.y = h3; ((__nv_bfloat162*)(g_s1h + o))[1] = t;
    t.x = l0; t.y = l1; ((__nv_bfloat162*)(g_s1l + o))[0] = t;
    t.x = l2; t.y = l3; ((__nv_bfloat162*)(g_s1l + o))[1] = t;
}

// ---------------- launch ----------------
extern "C" void kernel_launch(void* const* d_in, const int* in_sizes, int n_in,
                              void* d_out, int out_size) {
    const int* h_ids = (const int*)d_in[0];
    const int* u     = (const int*)d_in[1];
    const int* v     = (const int*)d_in[2];
    const float* emb   = (const float*)d_in[3];
    const float* lin1  = (const float*)d_in[4];
    const float* lin2  = (const float*)d_in[5];
    const float* bn1_g = (const float*)d_in[6];
    const float* bn1_b = (const float*)d_in[7];
    const float* bn2_g = (const float*)d_in[8];
    const float* bn2_b = (const float*)d_in[9];
    const float* W1_w  = (const float*)d_in[10];
    const float* W1_b  = (const float*)d_in[11];
    const float* W2_w  = (const float*)d_in[12];
    const float* W2_b  = (const float*)d_in[13];
    float* out = (float*)d_out;

    const int N = in_sizes[0];
    const int E = in_sizes[1];
    const int L = in_sizes[4] / (D * D);

    static int s_attr = 0;
    if (!s_attr) {
        cudaFuncSetAttribute(k_mma<512, 0, 1>, cudaFuncAttributeMaxDynamicSharedMemorySize, SMEMSZ);
        cudaFuncSetAttribute(k_mma<512, 0, 0>, cudaFuncAttributeMaxDynamicSharedMemorySize, SMEMSZ);
        cudaFuncSetAttribute(k_mma<512, 2, 0>, cudaFuncAttributeMaxDynamicSharedMemorySize, SMEMSZ);
        s_attr = 1;
    }

    float *dg_z, *dg_y, *dg_hsum;
    cudaGetSymbolAddress((void**)&dg_z, g_z);
    cudaGetSymbolAddress((void**)&dg_y, g_y);
    cudaGetSymbolAddress((void**)&dg_hsum, g_hsum);
    __nv_bfloat16 *zh, *zl, *yh, *yl, *hsh, *hsl, *s1h, *s1l;
    __nv_bfloat16 *l1th, *l1tl, *l2th, *l2tl, *w1th, *w1tl, *w2th, *w2tl;
    cudaGetSymbolAddress((void**)&zh, g_zh);  cudaGetSymbolAddress((void**)&zl, g_zl);
    cudaGetSymbolAddress((void**)&yh, g_yh);  cudaGetSymbolAddress((void**)&yl, g_yl);
    cudaGetSymbolAddress((void**)&hsh, g_hsh); cudaGetSymbolAddress((void**)&hsl, g_hsl);
    cudaGetSymbolAddress((void**)&s1h, g_s1h); cudaGetSymbolAddress((void**)&s1l, g_s1l);
    cudaGetSymbolAddress((void**)&l1th, g_l1th); cudaGetSymbolAddress((void**)&l1tl, g_l1tl);
    cudaGetSymbolAddress((void**)&l2th, g_l2th); cudaGetSymbolAddress((void**)&l2tl, g_l2tl);
    cudaGetSymbolAddress((void**)&w1th, g_w1th); cudaGetSymbolAddress((void**)&w1tl, g_w1tl);
    cudaGetSymbolAddress((void**)&w2th, g_w2th); cudaGetSymbolAddress((void**)&w2tl, g_w2tl);

    const int ew = N * 128, ewB = (ew + 255) / 256;
    const int mtiles = (N + 127) / 128;
    const int etiles = (E + 127) / 128;
    const int cvtB = (N * 128 + 255) / 256;
    const int edB = (E + 255) / 256;
    const int ndB = (N + 255) / 256;
    const int aggB = (N + 7) / 8;
    const int egB = (E * 128 + 255) / 256;

    // weight conversion (transpose + split)
    const int wB = (D * D + 255) / 256;
    for (int i = 0; i < L; i++) {
        k_tcvt<<<wB, 256>>>(lin1 + (size_t)i * D * D, l1th + (size_t)i * D * D, l1tl + (size_t)i * D * D, D, D);
        k_tcvt<<<wB, 256>>>(lin2 + (size_t)i * D * D, l2th + (size_t)i * D * D, l2tl + (size_t)i * D * D, D, D);
    }
    // W1 split into two [512,512] halves, each transposed
    k_tcvt<<<wB, 256>>>(W1_w, w1th, w1tl, D, D);                                   // W1a
    k_tcvt<<<wB, 256>>>(W1_w + (size_t)D * D, w1th + (size_t)D * D, w1tl + (size_t)D * D, D, D);  // W1b
    k_tcvt<<<(D * OUTD + 255) / 256, 256>>>(W2_w, w2th, w2tl, D, OUTD);

    // h = emb[h_ids]; hidden_sum = h
    k_gather<<<ewB, 256>>>(h_ids, emb, N);

    // CSR build (once)
    k_zerodeg<<<ndB, 256>>>(N);
    k_deg<<<edB, 256>>>(u, v, E);
    k_scan<<<1, 1024>>>(N);
    k_fill<<<edB, 256>>>(u, v, E);

    for (int i = 0; i < L; i++) {
        // z = 2h + neighbor sums -> bf16 pairs
        k_agg<<<aggB, 256>>>(N);
        // y = z @ lin1[i]  (+ fused BN stats)
        k_bnzero<<<1, 1024>>>();
        k_mma<512, 0, 1><<<dim3(mtiles, 4), 256, SMEMSZ>>>(
            zh, zl, l1th + (size_t)i * D * D, l1tl + (size_t)i * D * D,
            dg_y, N, D, nullptr);
        k_bnfin<<<1, D>>>(bn1_g + (size_t)i * D, bn1_b + (size_t)i * D, N);
        k_bnrelu_cvt<<<ewB, 256>>>(dg_y, yh, yl, N);
        // z(out) = y @ lin2[i]  (+ fused BN stats)
        k_bnzero<<<1, 1024>>>();
        k_mma<512, 0, 1><<<dim3(mtiles, 4), 256, SMEMSZ>>>(
            yh, yl, l2th + (size_t)i * D * D, l2tl + (size_t)i * D * D,
            dg_z, N, D, nullptr);
        k_bnfin<<<1, D>>>(bn2_g + (size_t)i * D, bn2_b + (size_t)i * D, N);
        k_bnrelu_acc<<<ewB, 256>>>(dg_z, N);
    }

    // decoder: P = hsum @ W1a^T -> g_y, Q = hsum @ W1b^T -> g_z
    k_cvt<<<cvtB, 256>>>(dg_hsum, hsh, hsl, N * 128);
    k_mma<512, 0, 0><<<dim3(mtiles, 4), 256, SMEMSZ>>>(
        hsh, hsl, w1th, w1tl, dg_y, N, D, nullptr);
    k_mma<512, 0, 0><<<dim3(mtiles, 4), 256, SMEMSZ>>>(
        hsh, hsl, w1th + (size_t)D * D, w1tl + (size_t)D * D, dg_z, N, D, nullptr);
    // s1 = relu(P[u] + Q[v] + b1) -> bf16 pairs
    k_edge<<<egB, 256>>>(u, v, W1_b, E);
    // out = s1 @ W2 + b2
    k_mma<512, 2, 0><<<dim3(etiles, 1), 256, SMEMSZ>>>(
        s1h, s1l, w2th, w2tl, out, E, OUTD, W2_b);
}

// round 8
// speedup vs baseline: 2.8456x; 1.0593x over previous
#include <cuda_runtime.h>
#include <cuda_bf16.h>

#define D 512
#define OUTD 128
#define MAXN 50000
#define MAXE 150000
#define BN_EPS 1e-5f

// ---------------- scratch (static device globals; no allocation) ----------------
__device__ float g_h[(size_t)MAXN * D];     // current node features
__device__ float g_hsum[(size_t)MAXN * D];  // hidden_sum accumulator
__device__ float g_y[(size_t)MAXN * D];     // gemm1 output
__device__ float g_z[(size_t)MAXN * D];     // gemm2 output
__device__ float g_pq[(size_t)MAXN * 2 * D];// decoder P|Q concat
__device__ float g_stats[2 * D];
__device__ float g_aff[2 * D];

// CSR graph
__device__ int g_deg[MAXN];
__device__ int g_off[MAXN + 1];
__device__ int g_cur[MAXN];
__device__ int g_adj[2 * MAXE];

// bf16 split pairs
__device__ __nv_bfloat16 g_zh[(size_t)MAXN * D], g_zl[(size_t)MAXN * D];
__device__ __nv_bfloat16 g_yh[(size_t)MAXN * D], g_yl[(size_t)MAXN * D];
__device__ __nv_bfloat16 g_hsh[(size_t)MAXN * D], g_hsl[(size_t)MAXN * D];
__device__ __nv_bfloat16 g_s1h[(size_t)MAXE * D], g_s1l[(size_t)MAXE * D];
// transposed + split weights: Bt[n][k]
__device__ __nv_bfloat16 g_l1th[(size_t)4 * D * D], g_l1tl[(size_t)4 * D * D];
__device__ __nv_bfloat16 g_l2th[(size_t)4 * D * D], g_l2tl[(size_t)4 * D * D];
__device__ __nv_bfloat16 g_w1th[(size_t)D * 2 * D], g_w1tl[(size_t)D * 2 * D];  // [a half | b half] rows 0..1023
__device__ __nv_bfloat16 g_w2th[(size_t)OUTD * D], g_w2tl[(size_t)OUTD * D];

// ---------------- PTX helpers (plain compute_100-legal) ----------------
__device__ __forceinline__ unsigned smem_u32(const void* p) {
    unsigned a;
    asm("{ .reg .u64 t; cvta.to.shared.u64 t, %1; cvt.u32.u64 %0, t; }" : "=r"(a) : "l"(p));
    return a;
}
__device__ __forceinline__ void cpasync16(unsigned dst, const void* src) {
    asm volatile("cp.async.cg.shared.global [%0], [%1], 16;" ::"r"(dst), "l"(src));
}
__device__ __forceinline__ void ldm4(unsigned* r, unsigned addr) {
    asm volatile("ldmatrix.sync.aligned.m8n8.x4.shared.b16 {%0,%1,%2,%3}, [%4];"
                 : "=r"(r[0]), "=r"(r[1]), "=r"(r[2]), "=r"(r[3]) : "r"(addr));
}
__device__ __forceinline__ void mma16816(float* c, const unsigned* a, const unsigned* b) {
    asm volatile(
        "mma.sync.aligned.m16n8k16.row.col.f32.bf16.bf16.f32 "
        "{%0,%1,%2,%3}, {%4,%5,%6,%7}, {%8,%9}, {%0,%1,%2,%3};"
        : "+f"(c[0]), "+f"(c[1]), "+f"(c[2]), "+f"(c[3])
        : "r"(a[0]), "r"(a[1]), "r"(a[2]), "r"(a[3]), "r"(b[0]), "r"(b[1]));
}
__device__ __forceinline__ void f2pair(float v, __nv_bfloat16& h, __nv_bfloat16& l) {
    h = __float2bfloat16(v);
    l = __float2bfloat16(v - __bfloat162float(h));
}

// ---------------- mma.sync split-bf16 GEMM ----------------
// 512 threads, 128 x BN CTA tile, 16 warps in 4x4 grid (warp tile 32 x BN/4),
// 3-stage cp.async pipeline, BK=32.
// C[M,Nout] = A[M,KTOT] @ Bt[Nout,KTOT]^T, A/Bt given as (hi,lo) bf16 pairs.
// EPI: 0 = fp32 store; 2 = x+bias -> fp32.
// STATS=1: accumulate per-column sum/sumsq into g_stats (valid rows only).
#define NSTAGE 3

template <int KTOT, int BN, int EPI, int STATS>
__global__ __launch_bounds__(512)
void k_mma(const __nv_bfloat16* __restrict__ Ah, const __nv_bfloat16* __restrict__ Al,
           const __nv_bfloat16* __restrict__ Bh, const __nv_bfloat16* __restrict__ Bl,
           float* __restrict__ Cf, int M, int Nout,
           const float* __restrict__ bias) {
    constexpr int NB = BN / 64;                  // 16-col blocks per warp
    constexpr int O_AL = 10240;
    constexpr int O_BH = 20480;
    constexpr int O_BL = 20480 + BN * 80;
    constexpr int STAGE_BYTES = 20480 + BN * 160;

    extern __shared__ __align__(16) char smem[];
    const int tid = threadIdx.x;
    const int wid = tid >> 5, lane = tid & 31;
    const int wm = wid & 3, wn = wid >> 2;       // 4 x 4 warp grid
    const int bm = blockIdx.x * 128, bn = blockIdx.y * BN;
    const unsigned sb = smem_u32(smem);

    const int arow = tid >> 2, quad = tid & 3;   // loader coords
    const int grA = min(bm + arow, M - 1);

    float acc[2][2 * NB][4];
#pragma unroll
    for (int i = 0; i < 2; i++)
#pragma unroll
        for (int j = 0; j < 2 * NB; j++)
#pragma unroll
            for (int q = 0; q < 4; q++) acc[i][j][q] = 0.f;

#define LOAD_CHUNK(STG, K0)                                                    \
    {                                                                          \
        unsigned st = sb + (STG) * STAGE_BYTES;                                \
        unsigned dsto = arow * 80 + quad * 16;                                 \
        size_t o = (size_t)grA * KTOT + (K0) + quad * 8;                       \
        cpasync16(st + dsto, Ah + o);                                          \
        cpasync16(st + O_AL + dsto, Al + o);                                   \
        _Pragma("unroll") for (int i = 0; i < BN / 128; i++) {                 \
            int brow = arow + i * 128;                                         \
            unsigned bd = brow * 80 + quad * 16;                               \
            size_t ob = (size_t)(bn + brow) * KTOT + (K0) + quad * 8;          \
            cpasync16(st + O_BH + bd, Bh + ob);                                \
            cpasync16(st + O_BL + bd, Bl + ob);                                \
        }                                                                      \
    }

    const int NC = KTOT / 32;
    // prologue: stages 0,1 <- chunks 0,1
#pragma unroll
    for (int p = 0; p < NSTAGE - 1; p++) {
        if (p < NC) LOAD_CHUNK(p, p * 32);
        asm volatile("cp.async.commit_group;");
    }

    int cstg = 0, lstg = NSTAGE - 1;
    for (int c = 0; c < NC; c++) {
        asm volatile("cp.async.wait_group %0;" ::"n"(NSTAGE - 2));
        __syncthreads();
        if (c + NSTAGE - 1 < NC) LOAD_CHUNK(lstg, (c + NSTAGE - 1) * 32);
        asm volatile("cp.async.commit_group;");
        lstg = (lstg + 1 == NSTAGE) ? 0 : lstg + 1;

        const unsigned st = sb + cstg * STAGE_BYTES;
        cstg = (cstg + 1 == NSTAGE) ? 0 : cstg + 1;
#pragma unroll
        for (int ks = 0; ks < 2; ks++) {
            const unsigned koff = ks * 32;  // 16 bf16 per k-step
            unsigned ah[2][4], al[2][4];
#pragma unroll
            for (int mf = 0; mf < 2; mf++) {
                unsigned addr = st + (wm * 32 + mf * 16 + (lane & 15)) * 80 +
                                ((lane >> 4) * 16) + koff;
                ldm4(ah[mf], addr);
                ldm4(al[mf], addr + O_AL);
            }
#pragma unroll
            for (int nb = 0; nb < NB; nb++) {
                unsigned addr = st + O_BH +
                                (wn * (BN / 4) + nb * 16 + (lane & 15)) * 80 +
                                ((lane >> 4) * 16) + koff;
                unsigned bh[4], bl[4];
                ldm4(bh, addr);
                ldm4(bl, addr + BN * 80);
                unsigned b0h[2] = {bh[0], bh[2]}, b1h[2] = {bh[1], bh[3]};
                unsigned b0l[2] = {bl[0], bl[2]}, b1l[2] = {bl[1], bl[3]};
#pragma unroll
                for (int mf = 0; mf < 2; mf++) {
                    mma16816(acc[mf][nb * 2], ah[mf], b0h);
                    mma16816(acc[mf][nb * 2], ah[mf], b0l);
                    mma16816(acc[mf][nb * 2], al[mf], b0h);
                    mma16816(acc[mf][nb * 2 + 1], ah[mf], b1h);
                    mma16816(acc[mf][nb * 2 + 1], ah[mf], b1l);
                    mma16816(acc[mf][nb * 2 + 1], al[mf], b1h);
                }
            }
        }
    }
#undef LOAD_CHUNK

    // epilogue: c-frag m16n8 -> rows t/4 & t/4+8, cols 2*(t%4)+{0,1}
#pragma unroll
    for (int mf = 0; mf < 2; mf++) {
        const int r0 = bm + wm * 32 + mf * 16 + (lane >> 2);
#pragma unroll
        for (int nf = 0; nf < 2 * NB; nf++) {
            const int col = bn + wn * (BN / 4) + nf * 8 + (lane & 3) * 2;
            const float* a = acc[mf][nf];
#pragma unroll
            for (int hh = 0; hh < 2; hh++) {
                const int row = r0 + hh * 8;
                if (row >= M) continue;
                float v0 = a[hh * 2], v1 = a[hh * 2 + 1];
                if (EPI == 0) {
                    float2 s = make_float2(v0, v1);
                    *(float2*)(Cf + (size_t)row * Nout + col) = s;
                } else {
                    float2 s = make_float2(v0 + bias[col], v1 + bias[col + 1]);
                    *(float2*)(Cf + (size_t)row * Nout + col) = s;
                }
            }
        }
    }

    if (STATS) {
#pragma unroll
        for (int nf = 0; nf < 2 * NB; nf++) {
            float s0 = 0.f, s1 = 0.f, q0 = 0.f, q1 = 0.f;
#pragma unroll
            for (int mf = 0; mf < 2; mf++) {
                const int rb = bm + wm * 32 + mf * 16 + (lane >> 2);
#pragma unroll
                for (int hh = 0; hh < 2; hh++) {
                    if (rb + hh * 8 < M) {
                        float v0 = acc[mf][nf][hh * 2], v1 = acc[mf][nf][hh * 2 + 1];
                        s0 += v0; q0 += v0 * v0;
                        s1 += v1; q1 += v1 * v1;
                    }
                }
            }
#pragma unroll
            for (int o = 4; o < 32; o <<= 1) {
                s0 += __shfl_xor_sync(0xffffffffu, s0, o);
                s1 += __shfl_xor_sync(0xffffffffu, s1, o);
                q0 += __shfl_xor_sync(0xffffffffu, q0, o);
                q1 += __shfl_xor_sync(0xffffffffu, q1, o);
            }
            if ((lane >> 2) == 0) {
                int col = bn + wn * (BN / 4) + nf * 8 + (lane & 3) * 2;
                atomicAdd(&g_stats[col], s0);
                atomicAdd(&g_stats[col + 1], s1);
                atomicAdd(&g_stats[D + col], q0);
                atomicAdd(&g_stats[D + col + 1], q1);
            }
        }
    }
}

// ---------------- CSR build ----------------
__global__ void k_zerodeg(int Nn) {
    int i = blockIdx.x * blockDim.x + threadIdx.x;
    if (i < Nn) g_deg[i] = 0;
}
__global__ void k_deg(const int* __restrict__ u, const int* __restrict__ v, int E) {
    int e = blockIdx.x * blockDim.x + threadIdx.x;
    if (e >= E) return;
    atomicAdd(&g_deg[u[e]], 1);
    atomicAdd(&g_deg[v[e]], 1);
}
__global__ void k_scan(int Nn) {   // single block, 1024 threads
    __shared__ int warpsum[32];
    __shared__ int s_carry;
    const int tid = threadIdx.x, lane = tid & 31, w = tid >> 5;
    if (tid == 0) s_carry = 0;
    __syncthreads();
    for (int base = 0; base < Nn; base += 1024) {
        int i = base + tid;
        int v = (i < Nn) ? g_deg[i] : 0;
        int x = v;
#pragma unroll
        for (int o = 1; o < 32; o <<= 1) {
            int t = __shfl_up_sync(0xffffffffu, x, o);
            if (lane >= o) x += t;
        }
        if (lane == 31) warpsum[w] = x;
        __syncthreads();
        if (w == 0) {
            int s = warpsum[lane];
#pragma unroll
            for (int o = 1; o < 32; o <<= 1) {
                int t = __shfl_up_sync(0xffffffffu, s, o);
                if (lane >= o) s += t;
            }
            warpsum[lane] = s;
        }
        __syncthreads();
        int incl = x + (w > 0 ? warpsum[w - 1] : 0) + s_carry;
        if (i < Nn) {
            int excl = incl - v;
            g_off[i] = excl;
            g_cur[i] = excl;
        }
        __syncthreads();
        if (tid == 1023) s_carry = incl;
        __syncthreads();
    }
    if (tid == 0) g_off[Nn] = s_carry;
}
__global__ void k_fill(const int* __restrict__ u, const int* __restrict__ v, int E) {
    int e = blockIdx.x * blockDim.x + threadIdx.x;
    if (e >= E) return;
    int a = u[e], b = v[e];
    int p = atomicAdd(&g_cur[b], 1);
    g_adj[p] = a;
    int q = atomicAdd(&g_cur[a], 1);
    g_adj[q] = b;
}

// ---------------- aggregation: z = 2h + sum_{nb} h[nb]  -> bf16 pairs ----------------
__global__ void k_agg(int Nn) {
    int node = blockIdx.x * 8 + (threadIdx.x >> 5);
    if (node >= Nn) return;
    const int lane = threadIdx.x & 31;
    float4 acc[4];
    const float4* hp = (const float4*)(g_h + (size_t)node * D);
#pragma unroll
    for (int j = 0; j < 4; j++) {
        float4 t = hp[j * 32 + lane];
        acc[j] = make_float4(2.f * t.x, 2.f * t.y, 2.f * t.z, 2.f * t.w);
    }
    const int e1 = g_off[node + 1];
    for (int e = g_off[node]; e < e1; e++) {
        const float4* np = (const float4*)(g_h + (size_t)g_adj[e] * D);
#pragma unroll
        for (int j = 0; j < 4; j++) {
            float4 t = np[j * 32 + lane];
            acc[j].x += t.x; acc[j].y += t.y; acc[j].z += t.z; acc[j].w += t.w;
        }
    }
#pragma unroll
    for (int j = 0; j < 4; j++) {
        __nv_bfloat16 h0, l0, h1, l1, h2, l2, h3, l3;
        f2pair(acc[j].x, h0, l0); f2pair(acc[j].y, h1, l1);
        f2pair(acc[j].z, h2, l2); f2pair(acc[j].w, h3, l3);
        size_t o = (size_t)node * D + (j * 32 + lane) * 4;
        __nv_bfloat162 a;
        a.x = h0; a.y = h1; ((__nv_bfloat162*)(g_zh + o))[0] = a;
        a.x = h2; a.y = h3; ((__nv_bfloat162*)(g_zh + o))[1] = a;
        a.x = l0; a.y = l1; ((__nv_bfloat162*)(g_zl + o))[0] = a;
        a.x = l2; a.y = l3; ((__nv_bfloat162*)(g_zl + o))[1] = a;
    }
}

// ---------------- elementwise kernels ----------------
__global__ void k_gather(const int* __restrict__ ids, const float* __restrict__ emb, int Nn) {
    int idx = blockIdx.x * blockDim.x + threadIdx.x;
    int row = idx >> 7;
    if (row >= Nn) return;
    int c = (idx & 127) << 2;
    float4 val = *(const float4*)(emb + (size_t)ids[row] * D + c);
    *(float4*)(g_h + (size_t)row * D + c) = val;
    *(float4*)(g_hsum + (size_t)row * D + c) = val;
}

// fp32 -> bf16 pair
__global__ void k_cvt(const float* __restrict__ X, __nv_bfloat16* __restrict__ H,
                      __nv_bfloat16* __restrict__ Lo, int n4) {
    int i = blockIdx.x * blockDim.x + threadIdx.x;
    if (i >= n4) return;
    float4 v = *(const float4*)(X + (size_t)i * 4);
    __nv_bfloat16 h0, l0, h1, l1, h2, l2, h3, l3;
    f2pair(v.x, h0, l0); f2pair(v.y, h1, l1);
    f2pair(v.z, h2, l2); f2pair(v.w, h3, l3);
    __nv_bfloat162* Hp = (__nv_bfloat162*)(H + (size_t)i * 4);
    __nv_bfloat162* Lp = (__nv_bfloat162*)(Lo + (size_t)i * 4);
    __nv_bfloat162 a; a.x = h0; a.y = h1; Hp[0] = a;
    a.x = h2; a.y = h3; Hp[1] = a;
    a.x = l0; a.y = l1; Lp[0] = a;
    a.x = l2; a.y = l3; Lp[1] = a;
}

// weight transpose+convert: src [K,Nn] row-major -> dst [Nn,K] pairs
__global__ void k_tcvt(const float* __restrict__ B, __nv_bfloat16* __restrict__ H,
                       __nv_bfloat16* __restrict__ Lo, int K, int Nn) {
    int idx = blockIdx.x * blockDim.x + threadIdx.x;
    if (idx >= K * Nn) return;
    int n = idx / K, k = idx - n * K;
    float x = B[(size_t)k * Nn + n];
    __nv_bfloat16 h, l;
    f2pair(x, h, l);
    H[idx] = h; Lo[idx] = l;
}

__global__ void k_bnzero() {
    int t = threadIdx.x;
    if (t < 2 * D) g_stats[t] = 0.f;
}

__global__ void k_bnfin(const float* __restrict__ gamma, const float* __restrict__ beta, int M) {
    int j = threadIdx.x;
    if (j >= D) return;
    float inv = 1.f / (float)M;
    float m = g_stats[j] * inv;
    float var = g_stats[D + j] * inv - m * m;
    float sc = gamma[j] * rsqrtf(var + BN_EPS);
    g_aff[j] = sc;
    g_aff[D + j] = beta[j] - m * sc;
}

// relu(affine(Y)) -> bf16 pairs
__global__ void k_bnrelu_cvt(const float* __restrict__ Y, __nv_bfloat16* __restrict__ H,
                             __nv_bfloat16* __restrict__ Lo, int Nn) {
    int idx = blockIdx.x * blockDim.x + threadIdx.x;
    if (idx >= Nn * 128) return;
    int c = (idx & 127) << 2;
    float4 v = *(const float4*)(Y + (size_t)idx * 4);
    v.x = fmaxf(v.x * g_aff[c + 0] + g_aff[D + c + 0], 0.f);
    v.y = fmaxf(v.y * g_aff[c + 1] + g_aff[D + c + 1], 0.f);
    v.z = fmaxf(v.z * g_aff[c + 2] + g_aff[D + c + 2], 0.f);
    v.w = fmaxf(v.w * g_aff[c + 3] + g_aff[D + c + 3], 0.f);
    __nv_bfloat16 h0, l0, h1, l1, h2, l2, h3, l3;
    f2pair(v.x, h0, l0); f2pair(v.y, h1, l1);
    f2pair(v.z, h2, l2); f2pair(v.w, h3, l3);
    __nv_bfloat162* Hp = (__nv_bfloat162*)(H + (size_t)idx * 4);
    __nv_bfloat162* Lp = (__nv_bfloat162*)(Lo + (size_t)idx * 4);
    __nv_bfloat162 a; a.x = h0; a.y = h1; Hp[0] = a;
    a.x = h2; a.y = h3; Hp[1] = a;
    a.x = l0; a.y = l1; Lp[0] = a;
    a.x = l2; a.y = l3; Lp[1] = a;
}

// h = relu(affine(Y2)); hsum += h   (fp32)
__global__ void k_bnrelu_acc(const float* __restrict__ Y2, int Nn) {
    int idx = blockIdx.x * blockDim.x + threadIdx.x;
    if (idx >= Nn * 128) return;
    int c = (idx & 127) << 2;
    float4 v = *(const float4*)(Y2 + (size_t)idx * 4);
    v.x = fmaxf(v.x * g_aff[c + 0] + g_aff[D + c + 0], 0.f);
    v.y = fmaxf(v.y * g_aff[c + 1] + g_aff[D + c + 1], 0.f);
    v.z = fmaxf(v.z * g_aff[c + 2] + g_aff[D + c + 2], 0.f);
    v.w = fmaxf(v.w * g_aff[c + 3] + g_aff[D + c + 3], 0.f);
    *(float4*)(g_h + (size_t)idx * 4) = v;
    float4 hs = *(const float4*)(g_hsum + (size_t)idx * 4);
    hs.x += v.x; hs.y += v.y; hs.z += v.z; hs.w += v.w;
    *(float4*)(g_hsum + (size_t)idx * 4) = hs;
}

// s1[e] = relu(P[u[e]] + Q[v[e]] + bias) -> bf16 pairs ; P|Q in g_pq[N,1024]
__global__ void k_edge(const int* __restrict__ u, const int* __restrict__ v,
                       const float* __restrict__ bias, int E) {
    int idx = blockIdx.x * blockDim.x + threadIdx.x;
    if (idx >= E * 128) return;
    int e = idx >> 7;
    int c = (idx & 127) << 2;
    int a = __ldg(u + e), b = __ldg(v + e);
    float4 p = *(const float4*)(g_pq + (size_t)a * 1024 + c);
    float4 q = *(const float4*)(g_pq + (size_t)b * 1024 + 512 + c);
    float4 bb = *(const float4*)(bias + c);
    float x0 = fmaxf(p.x + q.x + bb.x, 0.f);
    float x1 = fmaxf(p.y + q.y + bb.y, 0.f);
    float x2 = fmaxf(p.z + q.z + bb.z, 0.f);
    float x3 = fmaxf(p.w + q.w + bb.w, 0.f);
    __nv_bfloat16 h0, l0, h1, l1, h2, l2, h3, l3;
    f2pair(x0, h0, l0); f2pair(x1, h1, l1);
    f2pair(x2, h2, l2); f2pair(x3, h3, l3);
    size_t o = (size_t)e * D + c;
    __nv_bfloat162 t;
    t.x = h0; t.y = h1; ((__nv_bfloat162*)(g_s1h + o))[0] = t;
    t.x = h2; t.y = h3; ((__nv_bfloat162*)(g_s1h + o))[1] = t;
    t.x = l0; t.y = l1; ((__nv_bfloat162*)(g_s1l + o))[0] = t;
    t.x = l2; t.y = l3; ((__nv_bfloat162*)(g_s1l + o))[1] = t;
}

// ---------------- launch ----------------
extern "C" void kernel_launch(void* const* d_in, const int* in_sizes, int n_in,
                              void* d_out, int out_size) {
    const int* h_ids = (const int*)d_in[0];
    const int* u     = (const int*)d_in[1];
    const int* v     = (const int*)d_in[2];
    const float* emb   = (const float*)d_in[3];
    const float* lin1  = (const float*)d_in[4];
    const float* lin2  = (const float*)d_in[5];
    const float* bn1_g = (const float*)d_in[6];
    const float* bn1_b = (const float*)d_in[7];
    const float* bn2_g = (const float*)d_in[8];
    const float* bn2_b = (const float*)d_in[9];
    const float* W1_w  = (const float*)d_in[10];
    const float* W1_b  = (const float*)d_in[11];
    const float* W2_w  = (const float*)d_in[12];
    const float* W2_b  = (const float*)d_in[13];
    float* out = (float*)d_out;

    const int N = in_sizes[0];
    const int E = in_sizes[1];
    const int L = in_sizes[4] / (D * D);

    const int SMEM_256 = (20480 + 256 * 160) * NSTAGE;  // 184320
    const int SMEM_128 = (20480 + 128 * 160) * NSTAGE;  // 122880

    static int s_attr = 0;
    if (!s_attr) {
        cudaFuncSetAttribute(k_mma<512, 256, 0, 1>, cudaFuncAttributeMaxDynamicSharedMemorySize, SMEM_256);
        cudaFuncSetAttribute(k_mma<512, 256, 0, 0>, cudaFuncAttributeMaxDynamicSharedMemorySize, SMEM_256);
        cudaFuncSetAttribute(k_mma<512, 128, 2, 0>, cudaFuncAttributeMaxDynamicSharedMemorySize, SMEM_128);
        s_attr = 1;
    }

    float *dg_z, *dg_y, *dg_hsum, *dg_pq;
    cudaGetSymbolAddress((void**)&dg_z, g_z);
    cudaGetSymbolAddress((void**)&dg_y, g_y);
    cudaGetSymbolAddress((void**)&dg_hsum, g_hsum);
    cudaGetSymbolAddress((void**)&dg_pq, g_pq);
    __nv_bfloat16 *zh, *zl, *yh, *yl, *hsh, *hsl, *s1h, *s1l;
    __nv_bfloat16 *l1th, *l1tl, *l2th, *l2tl, *w1th, *w1tl, *w2th, *w2tl;
    cudaGetSymbolAddress((void**)&zh, g_zh);  cudaGetSymbolAddress((void**)&zl, g_zl);
    cudaGetSymbolAddress((void**)&yh, g_yh);  cudaGetSymbolAddress((void**)&yl, g_yl);
    cudaGetSymbolAddress((void**)&hsh, g_hsh); cudaGetSymbolAddress((void**)&hsl, g_hsl);
    cudaGetSymbolAddress((void**)&s1h, g_s1h); cudaGetSymbolAddress((void**)&s1l, g_s1l);
    cudaGetSymbolAddress((void**)&l1th, g_l1th); cudaGetSymbolAddress((void**)&l1tl, g_l1tl);
    cudaGetSymbolAddress((void**)&l2th, g_l2th); cudaGetSymbolAddress((void**)&l2tl, g_l2tl);
    cudaGetSymbolAddress((void**)&w1th, g_w1th); cudaGetSymbolAddress((void**)&w1tl, g_w1tl);
    cudaGetSymbolAddress((void**)&w2th, g_w2th); cudaGetSymbolAddress((void**)&w2tl, g_w2tl);

    const int ew = N * 128, ewB = (ew + 255) / 256;
    const int mtiles = (N + 127) / 128;
    const int etiles = (E + 127) / 128;
    const int cvtB = (N * 128 + 255) / 256;
    const int edB = (E + 255) / 256;
    const int ndB = (N + 255) / 256;
    const int aggB = (N + 7) / 8;
    const int egB = (E * 128 + 255) / 256;

    // weight conversion (transpose + split)
    const int wB = (D * D + 255) / 256;
    for (int i = 0; i < L; i++) {
        k_tcvt<<<wB, 256>>>(lin1 + (size_t)i * D * D, l1th + (size_t)i * D * D, l1tl + (size_t)i * D * D, D, D);
        k_tcvt<<<wB, 256>>>(lin2 + (size_t)i * D * D, l2th + (size_t)i * D * D, l2tl + (size_t)i * D * D, D, D);
    }
    // W1 halves, transposed: rows 0..511 = W1a, rows 512..1023 = W1b
    k_tcvt<<<wB, 256>>>(W1_w, w1th, w1tl, D, D);
    k_tcvt<<<wB, 256>>>(W1_w + (size_t)D * D, w1th + (size_t)D * D, w1tl + (size_t)D * D, D, D);
    k_tcvt<<<(D * OUTD + 255) / 256, 256>>>(W2_w, w2th, w2tl, D, OUTD);

    // h = emb[h_ids]; hidden_sum = h
    k_gather<<<ewB, 256>>>(h_ids, emb, N);

    // CSR build (once)
    k_zerodeg<<<ndB, 256>>>(N);
    k_deg<<<edB, 256>>>(u, v, E);
    k_scan<<<1, 1024>>>(N);
    k_fill<<<edB, 256>>>(u, v, E);

    for (int i = 0; i < L; i++) {
        // z = 2h + neighbor sums -> bf16 pairs
        k_agg<<<aggB, 256>>>(N);
        // y = z @ lin1[i]  (+ fused BN stats)
        k_bnzero<<<1, 1024>>>();
        k_mma<512, 256, 0, 1><<<dim3(mtiles, 2), 512, SMEM_256>>>(
            zh, zl, l1th + (size_t)i * D * D, l1tl + (size_t)i * D * D,
            dg_y, N, D, nullptr);
        k_bnfin<<<1, D>>>(bn1_g + (size_t)i * D, bn1_b + (size_t)i * D, N);
        k_bnrelu_cvt<<<ewB, 256>>>(dg_y, yh, yl, N);
        // z(out) = y @ lin2[i]  (+ fused BN stats)
        k_bnzero<<<1, 1024>>>();
        k_mma<512, 256, 0, 1><<<dim3(mtiles, 2), 512, SMEM_256>>>(
            yh, yl, l2th + (size_t)i * D * D, l2tl + (size_t)i * D * D,
            dg_z, N, D, nullptr);
        k_bnfin<<<1, D>>>(bn2_g + (size_t)i * D, bn2_b + (size_t)i * D, N);
        k_bnrelu_acc<<<ewB, 256>>>(dg_z, N);
    }

    // decoder: [P|Q] = hsum @ [W1a;W1b]^T  (one GEMM, Nout=1024)
    k_cvt<<<cvtB, 256>>>(dg_hsum, hsh, hsl, N * 128);
    k_mma<512, 256, 0, 0><<<dim3(mtiles, 4), 512, SMEM_256>>>(
        hsh, hsl, w1th, w1tl, dg_pq, N, 2 * D, nullptr);
    // s1 = relu(P[u] + Q[v] + b1) -> bf16 pairs
    k_edge<<<egB, 256>>>(u, v, W1_b, E);
    // out = s1 @ W2 + b2
    k_mma<512, 128, 2, 0><<<dim3(etiles, 1), 512, SMEM_128>>>(
        s1h, s1l, w2th, w2tl, out, E, OUTD, W2_b);
}

// round 9
// speedup vs baseline: 2.9831x; 1.0483x over previous
#include <cuda_runtime.h>
#include <cuda_bf16.h>

#define D 512
#define OUTD 128
#define MAXN 50000
#define MAXE 150000
#define BN_EPS 1e-5f

// ---------------- scratch (static device globals; no allocation) ----------------
__device__ float g_h[(size_t)MAXN * D];     // current node features
__device__ float g_hsum[(size_t)MAXN * D];  // hidden_sum accumulator
__device__ float g_y[(size_t)MAXN * D];     // gemm1 output
__device__ float g_z[(size_t)MAXN * D];     // gemm2 output
__device__ float g_pq[(size_t)MAXN * 2 * D];// decoder P|Q concat
__device__ float g_stats[2 * D];
__device__ float g_aff[2 * D];

// CSR graph
__device__ int g_deg[MAXN];
__device__ int g_off[MAXN + 1];
__device__ int g_cur[MAXN];
__device__ int g_adj[2 * MAXE];

// bf16 split pairs
__device__ __nv_bfloat16 g_zh[(size_t)MAXN * D], g_zl[(size_t)MAXN * D];
__device__ __nv_bfloat16 g_yh[(size_t)MAXN * D], g_yl[(size_t)MAXN * D];
__device__ __nv_bfloat16 g_hsh[(size_t)MAXN * D], g_hsl[(size_t)MAXN * D];
// transposed + split weights: Bt[n][k]
__device__ __nv_bfloat16 g_l1th[(size_t)4 * D * D], g_l1tl[(size_t)4 * D * D];
__device__ __nv_bfloat16 g_l2th[(size_t)4 * D * D], g_l2tl[(size_t)4 * D * D];
__device__ __nv_bfloat16 g_w1th[(size_t)D * 2 * D], g_w1tl[(size_t)D * 2 * D];  // [a half | b half]
__device__ __nv_bfloat16 g_w2th[(size_t)OUTD * D], g_w2tl[(size_t)OUTD * D];

// ---------------- PTX helpers (plain compute_100-legal) ----------------
__device__ __forceinline__ unsigned smem_u32(const void* p) {
    unsigned a;
    asm("{ .reg .u64 t; cvta.to.shared.u64 t, %1; cvt.u32.u64 %0, t; }" : "=r"(a) : "l"(p));
    return a;
}
__device__ __forceinline__ void cpasync16(unsigned dst, const void* src) {
    asm volatile("cp.async.cg.shared.global [%0], [%1], 16;" ::"r"(dst), "l"(src));
}
__device__ __forceinline__ void ldm4(unsigned* r, unsigned addr) {
    asm volatile("ldmatrix.sync.aligned.m8n8.x4.shared.b16 {%0,%1,%2,%3}, [%4];"
                 : "=r"(r[0]), "=r"(r[1]), "=r"(r[2]), "=r"(r[3]) : "r"(addr));
}
__device__ __forceinline__ void mma16816(float* c, const unsigned* a, const unsigned* b) {
    asm volatile(
        "mma.sync.aligned.m16n8k16.row.col.f32.bf16.bf16.f32 "
        "{%0,%1,%2,%3}, {%4,%5,%6,%7}, {%8,%9}, {%0,%1,%2,%3};"
        : "+f"(c[0]), "+f"(c[1]), "+f"(c[2]), "+f"(c[3])
        : "r"(a[0]), "r"(a[1]), "r"(a[2]), "r"(a[3]), "r"(b[0]), "r"(b[1]));
}
__device__ __forceinline__ void f2pair(float v, __nv_bfloat16& h, __nv_bfloat16& l) {
    h = __float2bfloat16(v);
    l = __float2bfloat16(v - __bfloat162float(h));
}
__device__ __forceinline__ void split2(float a, float b, unsigned& hi, unsigned& lo) {
    __nv_bfloat16 h0, l0, h1, l1;
    f2pair(a, h0, l0);
    f2pair(b, h1, l1);
    __nv_bfloat162 hp; hp.x = h0; hp.y = h1;
    __nv_bfloat162 lp; lp.x = l0; lp.y = l1;
    hi = *(unsigned*)&hp;
    lo = *(unsigned*)&lp;
}

// 12 mma for one nb-block, interleaved so each accumulator is reused at distance >=3
#define MMA_GROUP(A0, A1, C0, C1, AH, AL, B0H, B1H, B0L, B1L)                  \
    mma16816(A0, AH[0], B0H); mma16816(A1, AH[1], B0H);                        \
    mma16816(C0, AH[0], B1H); mma16816(C1, AH[1], B1H);                        \
    mma16816(A0, AH[0], B0L); mma16816(A1, AH[1], B0L);                        \
    mma16816(C0, AH[0], B1L); mma16816(C1, AH[1], B1L);                        \
    mma16816(A0, AL[0], B0H); mma16816(A1, AL[1], B0H);                        \
    mma16816(C0, AL[0], B1H); mma16816(C1, AL[1], B1H);

// ---------------- mma.sync split-bf16 GEMM ----------------
// 512 threads, 128 x BN CTA tile, 16 warps in 4x4 grid, 3-stage cp.async, BK=32.
// C[M,Nout] = A[M,KTOT] @ Bt[Nout,KTOT]^T, A/Bt given as (hi,lo) bf16 pairs.
// EPI: 0 = fp32 store; 2 = x+bias -> fp32.
// STATS=1: accumulate per-column sum/sumsq into g_stats (valid rows only).
#define NSTAGE 3

template <int KTOT, int BN, int EPI, int STATS>
__global__ __launch_bounds__(512)
void k_mma(const __nv_bfloat16* __restrict__ Ah, const __nv_bfloat16* __restrict__ Al,
           const __nv_bfloat16* __restrict__ Bh, const __nv_bfloat16* __restrict__ Bl,
           float* __restrict__ Cf, int M, int Nout,
           const float* __restrict__ bias) {
    constexpr int NB = BN / 64;
    constexpr int O_AL = 10240;
    constexpr int O_BH = 20480;
    constexpr int O_BL = 20480 + BN * 80;
    constexpr int STAGE_BYTES = 20480 + BN * 160;

    extern __shared__ __align__(16) char smem[];
    const int tid = threadIdx.x;
    const int wid = tid >> 5, lane = tid & 31;
    const int wm = wid & 3, wn = wid >> 2;
    const int bm = blockIdx.x * 128, bn = blockIdx.y * BN;
    const unsigned sb = smem_u32(smem);

    const int arow = tid >> 2, quad = tid & 3;
    const int grA = min(bm + arow, M - 1);

    float acc[2][2 * NB][4];
#pragma unroll
    for (int i = 0; i < 2; i++)
#pragma unroll
        for (int j = 0; j < 2 * NB; j++)
#pragma unroll
            for (int q = 0; q < 4; q++) acc[i][j][q] = 0.f;

#define LOAD_CHUNK(STG, K0)                                                    \
    {                                                                          \
        unsigned st = sb + (STG) * STAGE_BYTES;                                \
        unsigned dsto = arow * 80 + quad * 16;                                 \
        size_t o = (size_t)grA * KTOT + (K0) + quad * 8;                       \
        cpasync16(st + dsto, Ah + o);                                          \
        cpasync16(st + O_AL + dsto, Al + o);                                   \
        _Pragma("unroll") for (int i = 0; i < BN / 128; i++) {                 \
            int brow = arow + i * 128;                                         \
            unsigned bd = brow * 80 + quad * 16;                               \
            size_t ob = (size_t)(bn + brow) * KTOT + (K0) + quad * 8;          \
            cpasync16(st + O_BH + bd, Bh + ob);                                \
            cpasync16(st + O_BL + bd, Bl + ob);                                \
        }                                                                      \
    }

    const int NC = KTOT / 32;
#pragma unroll
    for (int p = 0; p < NSTAGE - 1; p++) {
        if (p < NC) LOAD_CHUNK(p, p * 32);
        asm volatile("cp.async.commit_group;");
    }

    int cstg = 0, lstg = NSTAGE - 1;
    for (int c = 0; c < NC; c++) {
        asm volatile("cp.async.wait_group %0;" ::"n"(NSTAGE - 2));
        __syncthreads();
        if (c + NSTAGE - 1 < NC) LOAD_CHUNK(lstg, (c + NSTAGE - 1) * 32);
        asm volatile("cp.async.commit_group;");
        lstg = (lstg + 1 == NSTAGE) ? 0 : lstg + 1;

        const unsigned st = sb + cstg * STAGE_BYTES;
        cstg = (cstg + 1 == NSTAGE) ? 0 : cstg + 1;
#pragma unroll
        for (int ks = 0; ks < 2; ks++) {
            const unsigned koff = ks * 32;
            unsigned ah[2][4], al[2][4];
#pragma unroll
            for (int mf = 0; mf < 2; mf++) {
                unsigned addr = st + (wm * 32 + mf * 16 + (lane & 15)) * 80 +
                                ((lane >> 4) * 16) + koff;
                ldm4(ah[mf], addr);
                ldm4(al[mf], addr + O_AL);
            }
#pragma unroll
            for (int nb = 0; nb < NB; nb++) {
                unsigned addr = st + O_BH +
                                (wn * (BN / 4) + nb * 16 + (lane & 15)) * 80 +
                                ((lane >> 4) * 16) + koff;
                unsigned bh[4], bl[4];
                ldm4(bh, addr);
                ldm4(bl, addr + BN * 80);
                unsigned b0h[2] = {bh[0], bh[2]}, b1h[2] = {bh[1], bh[3]};
                unsigned b0l[2] = {bl[0], bl[2]}, b1l[2] = {bl[1], bl[3]};
                float* a0 = acc[0][nb * 2];
                float* a1 = acc[1][nb * 2];
                float* c0 = acc[0][nb * 2 + 1];
                float* c1 = acc[1][nb * 2 + 1];
                MMA_GROUP(a0, a1, c0, c1, ah, al, b0h, b1h, b0l, b1l)
            }
        }
    }
#undef LOAD_CHUNK

#pragma unroll
    for (int mf = 0; mf < 2; mf++) {
        const int r0 = bm + wm * 32 + mf * 16 + (lane >> 2);
#pragma unroll
        for (int nf = 0; nf < 2 * NB; nf++) {
            const int col = bn + wn * (BN / 4) + nf * 8 + (lane & 3) * 2;
            const float* a = acc[mf][nf];
#pragma unroll
            for (int hh = 0; hh < 2; hh++) {
                const int row = r0 + hh * 8;
                if (row >= M) continue;
                float v0 = a[hh * 2], v1 = a[hh * 2 + 1];
                if (EPI == 0) {
                    float2 s = make_float2(v0, v1);
                    *(float2*)(Cf + (size_t)row * Nout + col) = s;
                } else {
                    float2 s = make_float2(v0 + bias[col], v1 + bias[col + 1]);
                    *(float2*)(Cf + (size_t)row * Nout + col) = s;
                }
            }
        }
    }

    if (STATS) {
#pragma unroll
        for (int nf = 0; nf < 2 * NB; nf++) {
            float s0 = 0.f, s1 = 0.f, q0 = 0.f, q1 = 0.f;
#pragma unroll
            for (int mf = 0; mf < 2; mf++) {
                const int rb = bm + wm * 32 + mf * 16 + (lane >> 2);
#pragma unroll
                for (int hh = 0; hh < 2; hh++) {
                    if (rb + hh * 8 < M) {
                        float v0 = acc[mf][nf][hh * 2], v1 = acc[mf][nf][hh * 2 + 1];
                        s0 += v0; q0 += v0 * v0;
                        s1 += v1; q1 += v1 * v1;
                    }
                }
            }
#pragma unroll
            for (int o = 4; o < 32; o <<= 1) {
                s0 += __shfl_xor_sync(0xffffffffu, s0, o);
                s1 += __shfl_xor_sync(0xffffffffu, s1, o);
                q0 += __shfl_xor_sync(0xffffffffu, q0, o);
                q1 += __shfl_xor_sync(0xffffffffu, q1, o);
            }
            if ((lane >> 2) == 0) {
                int col = bn + wn * (BN / 4) + nf * 8 + (lane & 3) * 2;
                atomicAdd(&g_stats[col], s0);
                atomicAdd(&g_stats[col + 1], s1);
                atomicAdd(&g_stats[D + col], q0);
                atomicAdd(&g_stats[D + col + 1], q1);
            }
        }
    }
}

// ---------------- decoder final GEMM with fused edge-combine loader ----------------
// out[e, 0:128] = relu(P[u[e]] + Q[v[e]] + b1) @ W2t^T + b2
// A row built in-register from fp32 P/Q (stride 1024), split to bf16 pairs, STS.
// A: 2 stages x 20480 B (hi at +0, lo at +10240). B: 3 stages x 20480 B at +40960.
#define DEC_SMEM (2 * 20480 + 3 * 20480)

__global__ __launch_bounds__(512)
void k_dec(const float* __restrict__ PQ,
           const __nv_bfloat16* __restrict__ Bh, const __nv_bfloat16* __restrict__ Bl,
           float* __restrict__ Cf, int M,
           const int* __restrict__ gu, const int* __restrict__ gv,
           const float* __restrict__ bias1, const float* __restrict__ bias2) {
    constexpr int KTOT = 512, BN = 128, NB = 2, NC = 16;
    extern __shared__ __align__(16) char smem[];
    __shared__ int s_u[128], s_v[128];
    const int tid = threadIdx.x;
    const int wid = tid >> 5, lane = tid & 31;
    const int wm = wid & 3, wn = wid >> 2;
    const int bm = blockIdx.x * 128;
    const unsigned sb = smem_u32(smem);

    if (tid < 128) {
        int e = min(bm + tid, M - 1);
        s_u[tid] = gu[e];
        s_v[tid] = gv[e];
    }
    __syncthreads();

    const int arow = tid >> 2, quad = tid & 3;
    const size_t prow = (size_t)s_u[arow] * 1024;
    const size_t qrow = (size_t)s_v[arow] * 1024 + 512;

    float acc[2][2 * NB][4];
#pragma unroll
    for (int i = 0; i < 2; i++)
#pragma unroll
        for (int j = 0; j < 2 * NB; j++)
#pragma unroll
            for (int q = 0; q < 4; q++) acc[i][j][q] = 0.f;

#define DEC_LOADB(STG, K0)                                                     \
    {                                                                          \
        unsigned st = sb + 40960 + (STG) * 20480;                              \
        unsigned bd = arow * 80 + quad * 16;                                   \
        size_t ob = (size_t)arow * KTOT + (K0) + quad * 8;                     \
        cpasync16(st + bd, Bh + ob);                                           \
        cpasync16(st + 10240 + bd, Bl + ob);                                   \
    }
#define DEC_LDGA(K0)                                                           \
    {                                                                          \
        const float4* pp = (const float4*)(PQ + prow + (K0) + quad * 8);       \
        const float4* qq = (const float4*)(PQ + qrow + (K0) + quad * 8);       \
        pa[0] = __ldg(pp); pa[1] = __ldg(pp + 1);                              \
        qa[0] = __ldg(qq); qa[1] = __ldg(qq + 1);                              \
    }

    float4 pa[2], qa[2];
    DEC_LDGA(0);
    DEC_LOADB(0, 0);
    asm volatile("cp.async.commit_group;");
    DEC_LOADB(1, 32);
    asm volatile("cp.async.commit_group;");

    for (int c = 0; c < NC; c++) {
        // STS A(c) from regs (into stage c&1; safe: compute(c-2) finished pre-sync(c-1))
        {
            unsigned hi[4], lo[4];
            const float* b1 = bias1 + c * 32 + quad * 8;
#pragma unroll
            for (int j = 0; j < 2; j++) {
                float4 p = pa[j], q = qa[j];
                float4 bb = *(const float4*)(b1 + j * 4);
                float x0 = fmaxf(p.x + q.x + bb.x, 0.f);
                float x1 = fmaxf(p.y + q.y + bb.y, 0.f);
                float x2 = fmaxf(p.z + q.z + bb.z, 0.f);
                float x3 = fmaxf(p.w + q.w + bb.w, 0.f);
                split2(x0, x1, hi[j * 2], lo[j * 2]);
                split2(x2, x3, hi[j * 2 + 1], lo[j * 2 + 1]);
            }
            char* ad = smem + (c & 1) * 20480 + arow * 80 + quad * 16;
            *(uint4*)ad = make_uint4(hi[0], hi[1], hi[2], hi[3]);
            *(uint4*)(ad + 10240) = make_uint4(lo[0], lo[1], lo[2], lo[3]);
        }
        asm volatile("cp.async.wait_group 1;");
        __syncthreads();
        if (c + 1 < NC) DEC_LDGA((c + 1) * 32);
        if (c + 2 < NC) DEC_LOADB((c + 2) % 3, (c + 2) * 32);
        asm volatile("cp.async.commit_group;");

        const unsigned ast = sb + (c & 1) * 20480;
        const unsigned bst = sb + 40960 + (c % 3) * 20480;
#pragma unroll
        for (int ks = 0; ks < 2; ks++) {
            const unsigned koff = ks * 32;
            unsigned ah[2][4], al[2][4];
#pragma unroll
            for (int mf = 0; mf < 2; mf++) {
                unsigned addr = ast + (wm * 32 + mf * 16 + (lane & 15)) * 80 +
                                ((lane >> 4) * 16) + koff;
                ldm4(ah[mf], addr);
                ldm4(al[mf], addr + 10240);
            }
#pragma unroll
            for (int nb = 0; nb < NB; nb++) {
                unsigned addr = bst + (wn * 32 + nb * 16 + (lane & 15)) * 80 +
                                ((lane >> 4) * 16) + koff;
                unsigned bh[4], bl[4];
                ldm4(bh, addr);
                ldm4(bl, addr + 10240);
                unsigned b0h[2] = {bh[0], bh[2]}, b1h[2] = {bh[1], bh[3]};
                unsigned b0l[2] = {bl[0], bl[2]}, b1l[2] = {bl[1], bl[3]};
                float* a0 = acc[0][nb * 2];
                float* a1 = acc[1][nb * 2];
                float* c0 = acc[0][nb * 2 + 1];
                float* c1 = acc[1][nb * 2 + 1];
                MMA_GROUP(a0, a1, c0, c1, ah, al, b0h, b1h, b0l, b1l)
            }
        }
    }
#undef DEC_LOADB
#undef DEC_LDGA

#pragma unroll
    for (int mf = 0; mf < 2; mf++) {
        const int r0 = bm + wm * 32 + mf * 16 + (lane >> 2);
#pragma unroll
        for (int nf = 0; nf < 2 * NB; nf++) {
            const int col = wn * 32 + nf * 8 + (lane & 3) * 2;
#pragma unroll
            for (int hh = 0; hh < 2; hh++) {
                const int row = r0 + hh * 8;
                if (row >= M) continue;
                float2 s = make_float2(acc[mf][nf][hh * 2] + bias2[col],
                                       acc[mf][nf][hh * 2 + 1] + bias2[col + 1]);
                *(float2*)(Cf + (size_t)row * OUTD + col) = s;
            }
        }
    }
}

// ---------------- CSR build ----------------
__global__ void k_zerodeg(int Nn) {
    int i = blockIdx.x * blockDim.x + threadIdx.x;
    if (i < Nn) g_deg[i] = 0;
}
__global__ void k_deg(const int* __restrict__ u, const int* __restrict__ v, int E) {
    int e = blockIdx.x * blockDim.x + threadIdx.x;
    if (e >= E) return;
    atomicAdd(&g_deg[u[e]], 1);
    atomicAdd(&g_deg[v[e]], 1);
}
__global__ void k_scan(int Nn) {
    __shared__ int warpsum[32];
    __shared__ int s_carry;
    const int tid = threadIdx.x, lane = tid & 31, w = tid >> 5;
    if (tid == 0) s_carry = 0;
    __syncthreads();
    for (int base = 0; base < Nn; base += 1024) {
        int i = base + tid;
        int v = (i < Nn) ? g_deg[i] : 0;
        int x = v;
#pragma unroll
        for (int o = 1; o < 32; o <<= 1) {
            int t = __shfl_up_sync(0xffffffffu, x, o);
            if (lane >= o) x += t;
        }
        if (lane == 31) warpsum[w] = x;
        __syncthreads();
        if (w == 0) {
            int s = warpsum[lane];
#pragma unroll
            for (int o = 1; o < 32; o <<= 1) {
                int t = __shfl_up_sync(0xffffffffu, s, o);
                if (lane >= o) s += t;
            }
            warpsum[lane] = s;
        }
        __syncthreads();
        int incl = x + (w > 0 ? warpsum[w - 1] : 0) + s_carry;
        if (i < Nn) {
            int excl = incl - v;
            g_off[i] = excl;
            g_cur[i] = excl;
        }
        __syncthreads();
        if (tid == 1023) s_carry = incl;
        __syncthreads();
    }
    if (tid == 0) g_off[Nn] = s_carry;
}
__global__ void k_fill(const int* __restrict__ u, const int* __restrict__ v, int E) {
    int e = blockIdx.x * blockDim.x + threadIdx.x;
    if (e >= E) return;
    int a = u[e], b = v[e];
    int p = atomicAdd(&g_cur[b], 1);
    g_adj[p] = a;
    int q = atomicAdd(&g_cur[a], 1);
    g_adj[q] = b;
}

// ---------------- aggregation: z = 2h + sum_{nb} h[nb]  -> bf16 pairs ----------------
__global__ void k_agg(int Nn) {
    int node = blockIdx.x * 8 + (threadIdx.x >> 5);
    if (node >= Nn) return;
    const int lane = threadIdx.x & 31;
    float4 acc[4];
    const float4* hp = (const float4*)(g_h + (size_t)node * D);
#pragma unroll
    for (int j = 0; j < 4; j++) {
        float4 t = hp[j * 32 + lane];
        acc[j] = make_float4(2.f * t.x, 2.f * t.y, 2.f * t.z, 2.f * t.w);
    }
    const int e1 = g_off[node + 1];
    for (int e = g_off[node]; e < e1; e++) {
        const float4* np = (const float4*)(g_h + (size_t)g_adj[e] * D);
#pragma unroll
        for (int j = 0; j < 4; j++) {
            float4 t = np[j * 32 + lane];
            acc[j].x += t.x; acc[j].y += t.y; acc[j].z += t.z; acc[j].w += t.w;
        }
    }
#pragma unroll
    for (int j = 0; j < 4; j++) {
        unsigned h0, l0, h1, l1;
        split2(acc[j].x, acc[j].y, h0, l0);
        split2(acc[j].z, acc[j].w, h1, l1);
        size_t o = (size_t)node * D + (j * 32 + lane) * 4;
        ((unsigned*)(g_zh + o))[0] = h0;
        ((unsigned*)(g_zh + o))[1] = h1;
        ((unsigned*)(g_zl + o))[0] = l0;
        ((unsigned*)(g_zl + o))[1] = l1;
    }
}

// ---------------- elementwise kernels ----------------
__global__ void k_gather(const int* __restrict__ ids, const float* __restrict__ emb, int Nn) {
    int idx = blockIdx.x * blockDim.x + threadIdx.x;
    int row = idx >> 7;
    if (row >= Nn) return;
    int c = (idx & 127) << 2;
    float4 val = *(const float4*)(emb + (size_t)ids[row] * D + c);
    *(float4*)(g_h + (size_t)row * D + c) = val;
    *(float4*)(g_hsum + (size_t)row * D + c) = val;
}

// weight transpose+convert: src [K,Nn] row-major -> dst [Nn,K] pairs
__global__ void k_tcvt(const float* __restrict__ B, __nv_bfloat16* __restrict__ H,
                       __nv_bfloat16* __restrict__ Lo, int K, int Nn) {
    int idx = blockIdx.x * blockDim.x + threadIdx.x;
    if (idx >= K * Nn) return;
    int n = idx / K, k = idx - n * K;
    float x = B[(size_t)k * Nn + n];
    __nv_bfloat16 h, l;
    f2pair(x, h, l);
    H[idx] = h; Lo[idx] = l;
}

__global__ void k_bnzero() {
    int t = threadIdx.x;
    if (t < 2 * D) g_stats[t] = 0.f;
}

__global__ void k_bnfin(const float* __restrict__ gamma, const float* __restrict__ beta, int M) {
    int j = threadIdx.x;
    if (j >= D) return;
    float inv = 1.f / (float)M;
    float m = g_stats[j] * inv;
    float var = g_stats[D + j] * inv - m * m;
    float sc = gamma[j] * rsqrtf(var + BN_EPS);
    g_aff[j] = sc;
    g_aff[D + j] = beta[j] - m * sc;
}

// relu(affine(Y)) -> bf16 pairs
__global__ void k_bnrelu_cvt(const float* __restrict__ Y, __nv_bfloat16* __restrict__ H,
                             __nv_bfloat16* __restrict__ Lo, int Nn) {
    int idx = blockIdx.x * blockDim.x + threadIdx.x;
    if (idx >= Nn * 128) return;
    int c = (idx & 127) << 2;
    float4 v = *(const float4*)(Y + (size_t)idx * 4);
    v.x = fmaxf(v.x * g_aff[c + 0] + g_aff[D + c + 0], 0.f);
    v.y = fmaxf(v.y * g_aff[c + 1] + g_aff[D + c + 1], 0.f);
    v.z = fmaxf(v.z * g_aff[c + 2] + g_aff[D + c + 2], 0.f);
    v.w = fmaxf(v.w * g_aff[c + 3] + g_aff[D + c + 3], 0.f);
    unsigned h0, l0, h1, l1;
    split2(v.x, v.y, h0, l0);
    split2(v.z, v.w, h1, l1);
    ((unsigned*)(H + (size_t)idx * 4))[0] = h0;
    ((unsigned*)(H + (size_t)idx * 4))[1] = h1;
    ((unsigned*)(Lo + (size_t)idx * 4))[0] = l0;
    ((unsigned*)(Lo + (size_t)idx * 4))[1] = l1;
}

// h = relu(affine(Y2)); hsum += h
// LAST=0: write h fp32 + hsum fp32.  LAST=1: write (hsum+h) as bf16 pairs only.
template <int LAST>
__global__ void k_bnrelu_acc(const float* __restrict__ Y2, int Nn) {
    int idx = blockIdx.x * blockDim.x + threadIdx.x;
    if (idx >= Nn * 128) return;
    int c = (idx & 127) << 2;
    float4 v = *(const float4*)(Y2 + (size_t)idx * 4);
    v.x = fmaxf(v.x * g_aff[c + 0] + g_aff[D + c + 0], 0.f);
    v.y = fmaxf(v.y * g_aff[c + 1] + g_aff[D + c + 1], 0.f);
    v.z = fmaxf(v.z * g_aff[c + 2] + g_aff[D + c + 2], 0.f);
    v.w = fmaxf(v.w * g_aff[c + 3] + g_aff[D + c + 3], 0.f);
    float4 hs = *(const float4*)(g_hsum + (size_t)idx * 4);
    hs.x += v.x; hs.y += v.y; hs.z += v.z; hs.w += v.w;
    if (!LAST) {
        *(float4*)(g_h + (size_t)idx * 4) = v;
        *(float4*)(g_hsum + (size_t)idx * 4) = hs;
    } else {
        unsigned h0, l0, h1, l1;
        split2(hs.x, hs.y, h0, l0);
        split2(hs.z, hs.w, h1, l1);
        ((unsigned*)(g_hsh + (size_t)idx * 4))[0] = h0;
        ((unsigned*)(g_hsh + (size_t)idx * 4))[1] = h1;
        ((unsigned*)(g_hsl + (size_t)idx * 4))[0] = l0;
        ((unsigned*)(g_hsl + (size_t)idx * 4))[1] = l1;
    }
}

// ---------------- launch ----------------
extern "C" void kernel_launch(void* const* d_in, const int* in_sizes, int n_in,
                              void* d_out, int out_size) {
    const int* h_ids = (const int*)d_in[0];
    const int* u     = (const int*)d_in[1];
    const int* v     = (const int*)d_in[2];
    const float* emb   = (const float*)d_in[3];
    const float* lin1  = (const float*)d_in[4];
    const float* lin2  = (const float*)d_in[5];
    const float* bn1_g = (const float*)d_in[6];
    const float* bn1_b = (const float*)d_in[7];
    const float* bn2_g = (const float*)d_in[8];
    const float* bn2_b = (const float*)d_in[9];
    const float* W1_w  = (const float*)d_in[10];
    const float* W1_b  = (const float*)d_in[11];
    const float* W2_w  = (const float*)d_in[12];
    const float* W2_b  = (const float*)d_in[13];
    float* out = (float*)d_out;

    const int N = in_sizes[0];
    const int E = in_sizes[1];
    const int L = in_sizes[4] / (D * D);

    const int SMEM_256 = (20480 + 256 * 160) * NSTAGE;  // 184320

    static int s_attr = 0;
    if (!s_attr) {
        cudaFuncSetAttribute(k_mma<512, 256, 0, 1>, cudaFuncAttributeMaxDynamicSharedMemorySize, SMEM_256);
        cudaFuncSetAttribute(k_mma<512, 256, 0, 0>, cudaFuncAttributeMaxDynamicSharedMemorySize, SMEM_256);
        cudaFuncSetAttribute(k_dec, cudaFuncAttributeMaxDynamicSharedMemorySize, DEC_SMEM);
        s_attr = 1;
    }

    float *dg_z, *dg_y, *dg_pq;
    cudaGetSymbolAddress((void**)&dg_z, g_z);
    cudaGetSymbolAddress((void**)&dg_y, g_y);
    cudaGetSymbolAddress((void**)&dg_pq, g_pq);
    __nv_bfloat16 *zh, *zl, *yh, *yl, *hsh, *hsl;
    __nv_bfloat16 *l1th, *l1tl, *l2th, *l2tl, *w1th, *w1tl, *w2th, *w2tl;
    cudaGetSymbolAddress((void**)&zh, g_zh);  cudaGetSymbolAddress((void**)&zl, g_zl);
    cudaGetSymbolAddress((void**)&yh, g_yh);  cudaGetSymbolAddress((void**)&yl, g_yl);
    cudaGetSymbolAddress((void**)&hsh, g_hsh); cudaGetSymbolAddress((void**)&hsl, g_hsl);
    cudaGetSymbolAddress((void**)&l1th, g_l1th); cudaGetSymbolAddress((void**)&l1tl, g_l1tl);
    cudaGetSymbolAddress((void**)&l2th, g_l2th); cudaGetSymbolAddress((void**)&l2tl, g_l2tl);
    cudaGetSymbolAddress((void**)&w1th, g_w1th); cudaGetSymbolAddress((void**)&w1tl, g_w1tl);
    cudaGetSymbolAddress((void**)&w2th, g_w2th); cudaGetSymbolAddress((void**)&w2tl, g_w2tl);

    const int ew = N * 128, ewB = (ew + 255) / 256;
    const int mtiles = (N + 127) / 128;
    const int etiles = (E + 127) / 128;
    const int edB = (E + 255) / 256;
    const int ndB = (N + 255) / 256;
    const int aggB = (N + 7) / 8;

    // weight conversion (transpose + split)
    const int wB = (D * D + 255) / 256;
    for (int i = 0; i < L; i++) {
        k_tcvt<<<wB, 256>>>(lin1 + (size_t)i * D * D, l1th + (size_t)i * D * D, l1tl + (size_t)i * D * D, D, D);
        k_tcvt<<<wB, 256>>>(lin2 + (size_t)i * D * D, l2th + (size_t)i * D * D, l2tl + (size_t)i * D * D, D, D);
    }
    k_tcvt<<<wB, 256>>>(W1_w, w1th, w1tl, D, D);
    k_tcvt<<<wB, 256>>>(W1_w + (size_t)D * D, w1th + (size_t)D * D, w1tl + (size_t)D * D, D, D);
    k_tcvt<<<(D * OUTD + 255) / 256, 256>>>(W2_w, w2th, w2tl, D, OUTD);

    // h = emb[h_ids]; hidden_sum = h
    k_gather<<<ewB, 256>>>(h_ids, emb, N);

    // CSR build (once)
    k_zerodeg<<<ndB, 256>>>(N);
    k_deg<<<edB, 256>>>(u, v, E);
    k_scan<<<1, 1024>>>(N);
    k_fill<<<edB, 256>>>(u, v, E);

    for (int i = 0; i < L; i++) {
        // z = 2h + neighbor sums -> bf16 pairs
        k_agg<<<aggB, 256>>>(N);
        // y = z @ lin1[i]  (+ fused BN stats)
        k_bnzero<<<1, 1024>>>();
        k_mma<512, 256, 0, 1><<<dim3(mtiles, 2), 512, SMEM_256>>>(
            zh, zl, l1th + (size_t)i * D * D, l1tl + (size_t)i * D * D,
            dg_y, N, D, nullptr);
        k_bnfin<<<1, D>>>(bn1_g + (size_t)i * D, bn1_b + (size_t)i * D, N);
        k_bnrelu_cvt<<<ewB, 256>>>(dg_y, yh, yl, N);
        // z(out) = y @ lin2[i]  (+ fused BN stats)
        k_bnzero<<<1, 1024>>>();
        k_mma<512, 256, 0, 1><<<dim3(mtiles, 2), 512, SMEM_256>>>(
            yh, yl, l2th + (size_t)i * D * D, l2tl + (size_t)i * D * D,
            dg_z, N, D, nullptr);
        k_bnfin<<<1, D>>>(bn2_g + (size_t)i * D, bn2_b + (size_t)i * D, N);
        if (i == L - 1)
            k_bnrelu_acc<1><<<ewB, 256>>>(dg_z, N);
        else
            k_bnrelu_acc<0><<<ewB, 256>>>(dg_z, N);
    }

    // decoder: [P|Q] = hsum_pairs @ [W1a;W1b]^T  (one GEMM, Nout=1024)
    k_mma<512, 256, 0, 0><<<dim3(mtiles, 4), 512, SMEM_256>>>(
        hsh, hsl, w1th, w1tl, dg_pq, N, 2 * D, nullptr);
    // out = relu(P[u]+Q[v]+b1) @ W2^T + b2  (fused edge loader)
    k_dec<<<etiles, 512, DEC_SMEM>>>(dg_pq, w2th, w2tl, out, E, u, v, W1_b, W2_b);
}

// round 10
// speedup vs baseline: 3.1274x; 1.0484x over previous
#include <cuda_runtime.h>
#include <cuda_bf16.h>

#define D 512
#define OUTD 128
#define MAXN 50000
#define MAXE 150000
#define BN_EPS 1e-5f

// ---------------- scratch (static device globals; no allocation) ----------------
__device__ float g_h[(size_t)MAXN * D];     // current node features
__device__ float g_hsum[(size_t)MAXN * D];  // hidden_sum accumulator
__device__ float g_y[(size_t)MAXN * D];     // gemm1 output
__device__ float g_z[(size_t)MAXN * D];     // gemm2 output
__device__ float g_pq[(size_t)MAXN * 2 * D];// decoder P|Q concat
__device__ float g_stats[2 * 1024];         // slot0: GEMM1 (sum,sumsq), slot1: GEMM2

// CSR graph
__device__ int g_deg[MAXN];
__device__ int g_off[MAXN + 1];
__device__ int g_cur[MAXN];
__device__ int g_adj[2 * MAXE];

// bf16 split pairs
__device__ __nv_bfloat16 g_zh[(size_t)MAXN * D], g_zl[(size_t)MAXN * D];
__device__ __nv_bfloat16 g_hsh[(size_t)MAXN * D], g_hsl[(size_t)MAXN * D];
// transposed + split weights: Bt[n][k]
__device__ __nv_bfloat16 g_l1th[(size_t)4 * D * D], g_l1tl[(size_t)4 * D * D];
__device__ __nv_bfloat16 g_l2th[(size_t)4 * D * D], g_l2tl[(size_t)4 * D * D];
__device__ __nv_bfloat16 g_w1th[(size_t)D * 2 * D], g_w1tl[(size_t)D * 2 * D];
__device__ __nv_bfloat16 g_w2th[(size_t)OUTD * D], g_w2tl[(size_t)OUTD * D];

// ---------------- PTX helpers (plain compute_100-legal) ----------------
__device__ __forceinline__ unsigned smem_u32(const void* p) {
    unsigned a;
    asm("{ .reg .u64 t; cvta.to.shared.u64 t, %1; cvt.u32.u64 %0, t; }" : "=r"(a) : "l"(p));
    return a;
}
__device__ __forceinline__ void cpasync16(unsigned dst, const void* src) {
    asm volatile("cp.async.cg.shared.global [%0], [%1], 16;" ::"r"(dst), "l"(src));
}
__device__ __forceinline__ void ldm4(unsigned* r, unsigned addr) {
    asm volatile("ldmatrix.sync.aligned.m8n8.x4.shared.b16 {%0,%1,%2,%3}, [%4];"
                 : "=r"(r[0]), "=r"(r[1]), "=r"(r[2]), "=r"(r[3]) : "r"(addr));
}
__device__ __forceinline__ void mma16816(float* c, const unsigned* a, const unsigned* b) {
    asm volatile(
        "mma.sync.aligned.m16n8k16.row.col.f32.bf16.bf16.f32 "
        "{%0,%1,%2,%3}, {%4,%5,%6,%7}, {%8,%9}, {%0,%1,%2,%3};"
        : "+f"(c[0]), "+f"(c[1]), "+f"(c[2]), "+f"(c[3])
        : "r"(a[0]), "r"(a[1]), "r"(a[2]), "r"(a[3]), "r"(b[0]), "r"(b[1]));
}
__device__ __forceinline__ void f2pair(float v, __nv_bfloat16& h, __nv_bfloat16& l) {
    h = __float2bfloat16(v);
    l = __float2bfloat16(v - __bfloat162float(h));
}
__device__ __forceinline__ void split2(float a, float b, unsigned& hi, unsigned& lo) {
    __nv_bfloat16 h0, l0, h1, l1;
    f2pair(a, h0, l0);
    f2pair(b, h1, l1);
    __nv_bfloat162 hp; hp.x = h0; hp.y = h1;
    __nv_bfloat162 lp; lp.x = l0; lp.y = l1;
    hi = *(unsigned*)&hp;
    lo = *(unsigned*)&lp;
}

// 12 mma for one nb-block, accumulator reuse distance >= 3
#define MMA_GROUP(A0, A1, C0, C1, AH, AL, B0H, B1H, B0L, B1L)                  \
    mma16816(A0, AH[0], B0H); mma16816(A1, AH[1], B0H);                        \
    mma16816(C0, AH[0], B1H); mma16816(C1, AH[1], B1H);                        \
    mma16816(A0, AH[0], B0L); mma16816(A1, AH[1], B0L);                        \
    mma16816(C0, AH[0], B1L); mma16816(C1, AH[1], B1L);                        \
    mma16816(A0, AL[0], B0H); mma16816(A1, AL[1], B0H);                        \
    mma16816(C0, AL[0], B1H); mma16816(C1, AL[1], B1H);

// shared epilogue: store fp32 + optional column stats into stats_out
#define EPILOGUE_STORE(BN_, NOUT_, BIAS_EXPR)                                  \
    _Pragma("unroll") for (int mf = 0; mf < 2; mf++) {                         \
        const int r0 = bm + wm * 32 + mf * 16 + (lane >> 2);                   \
        _Pragma("unroll") for (int nf = 0; nf < 2 * ((BN_) / 64); nf++) {      \
            const int col = bn + wn * ((BN_) / 4) + nf * 8 + (lane & 3) * 2;   \
            const float* a = acc[mf][nf];                                      \
            _Pragma("unroll") for (int hh = 0; hh < 2; hh++) {                 \
                const int row = r0 + hh * 8;                                   \
                if (row >= M) continue;                                        \
                float2 s = make_float2(a[hh * 2] BIAS_EXPR(col),               \
                                       a[hh * 2 + 1] BIAS_EXPR(col + 1));      \
                *(float2*)(Cf + (size_t)row * (NOUT_) + col) = s;              \
            }                                                                  \
        }                                                                      \
    }

#define EPILOGUE_STATS(BN_)                                                    \
    _Pragma("unroll") for (int nf = 0; nf < 2 * ((BN_) / 64); nf++) {          \
        float s0 = 0.f, s1 = 0.f, q0 = 0.f, q1 = 0.f;                          \
        _Pragma("unroll") for (int mf = 0; mf < 2; mf++) {                     \
            const int rb = bm + wm * 32 + mf * 16 + (lane >> 2);               \
            _Pragma("unroll") for (int hh = 0; hh < 2; hh++) {                 \
                if (rb + hh * 8 < M) {                                         \
                    float v0 = acc[mf][nf][hh * 2], v1 = acc[mf][nf][hh * 2 + 1];\
                    s0 += v0; q0 += v0 * v0;                                   \
                    s1 += v1; q1 += v1 * v1;                                   \
                }                                                              \
            }                                                                  \
        }                                                                      \
        _Pragma("unroll") for (int o = 4; o < 32; o <<= 1) {                   \
            s0 += __shfl_xor_sync(0xffffffffu, s0, o);                         \
            s1 += __shfl_xor_sync(0xffffffffu, s1, o);                         \
            q0 += __shfl_xor_sync(0xffffffffu, q0, o);                         \
            q1 += __shfl_xor_sync(0xffffffffu, q1, o);                         \
        }                                                                      \
        if ((lane >> 2) == 0) {                                                \
            int col = bn + wn * ((BN_) / 4) + nf * 8 + (lane & 3) * 2;         \
            atomicAdd(&stats_out[col], s0);                                    \
            atomicAdd(&stats_out[col + 1], s1);                                \
            atomicAdd(&stats_out[512 + col], q0);                              \
            atomicAdd(&stats_out[512 + col + 1], q1);                          \
        }                                                                      \
    }

#define NO_BIAS(c)
#define ACC_INIT(NB_)                                                          \
    float acc[2][2 * (NB_)][4];                                                \
    _Pragma("unroll") for (int i = 0; i < 2; i++)                              \
        _Pragma("unroll") for (int j = 0; j < 2 * (NB_); j++)                  \
            _Pragma("unroll") for (int q = 0; q < 4; q++) acc[i][j][q] = 0.f;

// ---------------- mma.sync split-bf16 GEMM (pair inputs) ----------------
// 512 threads, 128 x BN CTA tile, 16 warps 4x4, 3-stage cp.async, BK=32.
#define NSTAGE 3

template <int KTOT, int BN, int STATS>
__global__ __launch_bounds__(512)
void k_mma(const __nv_bfloat16* __restrict__ Ah, const __nv_bfloat16* __restrict__ Al,
           const __nv_bfloat16* __restrict__ Bh, const __nv_bfloat16* __restrict__ Bl,
           float* __restrict__ Cf, int M, int Nout, float* __restrict__ stats_out) {
    constexpr int NB = BN / 64;
    constexpr int O_AL = 10240;
    constexpr int O_BH = 20480;
    constexpr int O_BL = 20480 + BN * 80;
    constexpr int STAGE_BYTES = 20480 + BN * 160;

    extern __shared__ __align__(16) char smem[];
    const int tid = threadIdx.x;
    const int wid = tid >> 5, lane = tid & 31;
    const int wm = wid & 3, wn = wid >> 2;
    const int bm = blockIdx.x * 128, bn = blockIdx.y * BN;
    const unsigned sb = smem_u32(smem);

    const int arow = tid >> 2, quad = tid & 3;
    const int grA = min(bm + arow, M - 1);

    ACC_INIT(NB)

#define LOAD_CHUNK(STG, K0)                                                    \
    {                                                                          \
        unsigned st = sb + (STG) * STAGE_BYTES;                                \
        unsigned dsto = arow * 80 + quad * 16;                                 \
        size_t o = (size_t)grA * KTOT + (K0) + quad * 8;                       \
        cpasync16(st + dsto, Ah + o);                                          \
        cpasync16(st + O_AL + dsto, Al + o);                                   \
        _Pragma("unroll") for (int i = 0; i < BN / 128; i++) {                 \
            int brow = arow + i * 128;                                         \
            unsigned bd = brow * 80 + quad * 16;                               \
            size_t ob = (size_t)(bn + brow) * KTOT + (K0) + quad * 8;          \
            cpasync16(st + O_BH + bd, Bh + ob);                                \
            cpasync16(st + O_BL + bd, Bl + ob);                                \
        }                                                                      \
    }

    const int NC = KTOT / 32;
#pragma unroll
    for (int p = 0; p < NSTAGE - 1; p++) {
        if (p < NC) LOAD_CHUNK(p, p * 32);
        asm volatile("cp.async.commit_group;");
    }

    int cstg = 0, lstg = NSTAGE - 1;
    for (int c = 0; c < NC; c++) {
        asm volatile("cp.async.wait_group %0;" ::"n"(NSTAGE - 2));
        __syncthreads();
        if (c + NSTAGE - 1 < NC) LOAD_CHUNK(lstg, (c + NSTAGE - 1) * 32);
        asm volatile("cp.async.commit_group;");
        lstg = (lstg + 1 == NSTAGE) ? 0 : lstg + 1;

        const unsigned st = sb + cstg * STAGE_BYTES;
        cstg = (cstg + 1 == NSTAGE) ? 0 : cstg + 1;
#pragma unroll
        for (int ks = 0; ks < 2; ks++) {
            const unsigned koff = ks * 32;
            unsigned ah[2][4], al[2][4];
#pragma unroll
            for (int mf = 0; mf < 2; mf++) {
                unsigned addr = st + (wm * 32 + mf * 16 + (lane & 15)) * 80 +
                                ((lane >> 4) * 16) + koff;
                ldm4(ah[mf], addr);
                ldm4(al[mf], addr + O_AL);
            }
#pragma unroll
            for (int nb = 0; nb < NB; nb++) {
                unsigned addr = st + O_BH +
                                (wn * (BN / 4) + nb * 16 + (lane & 15)) * 80 +
                                ((lane >> 4) * 16) + koff;
                unsigned bh[4], bl[4];
                ldm4(bh, addr);
                ldm4(bl, addr + BN * 80);
                unsigned b0h[2] = {bh[0], bh[2]}, b1h[2] = {bh[1], bh[3]};
                unsigned b0l[2] = {bl[0], bl[2]}, b1l[2] = {bl[1], bl[3]};
                float* a0 = acc[0][nb * 2];
                float* a1 = acc[1][nb * 2];
                float* c0 = acc[0][nb * 2 + 1];
                float* c1 = acc[1][nb * 2 + 1];
                MMA_GROUP(a0, a1, c0, c1, ah, al, b0h, b1h, b0l, b1l)
            }
        }
    }
#undef LOAD_CHUNK

    EPILOGUE_STORE(BN, Nout, NO_BIAS)
    if (STATS) { EPILOGUE_STATS(BN) }
}

// ---------------- GEMM2: fused BN-apply loader ----------------
// C = relu(affine(Y)) @ Bt^T ; affine computed in-kernel from stats_in+gamma+beta.
// A: fp32 LDG -> regs (1 chunk ahead) -> affine/relu/split -> STS, 2 stages.
// B: 3-stage cp.async. BN=256.
#define BNG_SMEM (2 * 20480 + 3 * 40960 + 4096)  // 167936

__global__ __launch_bounds__(512)
void k_mma_bn(const float* __restrict__ Y,
              const __nv_bfloat16* __restrict__ Bh, const __nv_bfloat16* __restrict__ Bl,
              float* __restrict__ Cf, int M,
              const float* __restrict__ stats_in, const float* __restrict__ gamma,
              const float* __restrict__ beta, float* __restrict__ stats_out) {
    constexpr int KTOT = 512, BN = 256, NB = 4, NC = 16;
    constexpr int O_B = 40960;        // B stages base
    constexpr int O_AFF = 163840;     // aff: scale[512] then shift[512]
    extern __shared__ __align__(16) char smem[];
    float* s_aff = (float*)(smem + O_AFF);
    const int tid = threadIdx.x;
    const int wid = tid >> 5, lane = tid & 31;
    const int wm = wid & 3, wn = wid >> 2;
    const int bm = blockIdx.x * 128, bn = blockIdx.y * BN;
    const unsigned sb = smem_u32(smem);

    // in-kernel BN-affine from stats (GEMM1 finished before this kernel launches)
    if (tid < 512) {
        float inv = 1.f / (float)M;
        float m = stats_in[tid] * inv;
        float var = stats_in[512 + tid] * inv - m * m;
        float sc = gamma[tid] * rsqrtf(var + BN_EPS);
        s_aff[tid] = sc;
        s_aff[512 + tid] = beta[tid] - m * sc;
    }

    const int arow = tid >> 2, quad = tid & 3;
    const int grA = min(bm + arow, M - 1);

    ACC_INIT(NB)

#define BNG_LOADB(STG, K0)                                                     \
    {                                                                          \
        unsigned st = sb + O_B + (STG) * 40960;                                \
        _Pragma("unroll") for (int i = 0; i < 2; i++) {                        \
            int brow = arow + i * 128;                                         \
            unsigned bd = brow * 80 + quad * 16;                               \
            size_t ob = (size_t)(bn + brow) * KTOT + (K0) + quad * 8;          \
            cpasync16(st + bd, Bh + ob);                                       \
            cpasync16(st + 20480 + bd, Bl + ob);                               \
        }                                                                      \
    }
#define BNG_LDGA(K0)                                                           \
    {                                                                          \
        const float4* yp = (const float4*)(Y + (size_t)grA * KTOT + (K0) + quad * 8);\
        ya[0] = __ldg(yp); ya[1] = __ldg(yp + 1);                              \
    }

    float4 ya[2];
    BNG_LDGA(0);
    BNG_LOADB(0, 0);
    asm volatile("cp.async.commit_group;");
    BNG_LOADB(1, 32);
    asm volatile("cp.async.commit_group;");
    __syncthreads();  // s_aff visible

    for (int c = 0; c < NC; c++) {
        // STS A(c): affine + relu + split (stage c&1; compute(c-2) done before sync(c-1))
        {
            unsigned hi[4], lo[4];
            const int kb = c * 32 + quad * 8;
#pragma unroll
            for (int j = 0; j < 2; j++) {
                float4 y = ya[j];
                const int k = kb + j * 4;
                float x0 = fmaxf(y.x * s_aff[k + 0] + s_aff[512 + k + 0], 0.f);
                float x1 = fmaxf(y.y * s_aff[k + 1] + s_aff[512 + k + 1], 0.f);
                float x2 = fmaxf(y.z * s_aff[k + 2] + s_aff[512 + k + 2], 0.f);
                float x3 = fmaxf(y.w * s_aff[k + 3] + s_aff[512 + k + 3], 0.f);
                split2(x0, x1, hi[j * 2], lo[j * 2]);
                split2(x2, x3, hi[j * 2 + 1], lo[j * 2 + 1]);
            }
            char* ad = smem + (c & 1) * 20480 + arow * 80 + quad * 16;
            *(uint4*)ad = make_uint4(hi[0], hi[1], hi[2], hi[3]);
            *(uint4*)(ad + 10240) = make_uint4(lo[0], lo[1], lo[2], lo[3]);
        }
        asm volatile("cp.async.wait_group 1;");
        __syncthreads();
        if (c + 1 < NC) BNG_LDGA((c + 1) * 32);
        if (c + 2 < NC) BNG_LOADB((c + 2) % 3, (c + 2) * 32);
        asm volatile("cp.async.commit_group;");

        const unsigned ast = sb + (c & 1) * 20480;
        const unsigned bst = sb + O_B + (c % 3) * 40960;
#pragma unroll
        for (int ks = 0; ks < 2; ks++) {
            const unsigned koff = ks * 32;
            unsigned ah[2][4], al[2][4];
#pragma unroll
            for (int mf = 0; mf < 2; mf++) {
                unsigned addr = ast + (wm * 32 + mf * 16 + (lane & 15)) * 80 +
                                ((lane >> 4) * 16) + koff;
                ldm4(ah[mf], addr);
                ldm4(al[mf], addr + 10240);
            }
#pragma unroll
            for (int nb = 0; nb < NB; nb++) {
                unsigned addr = bst + (wn * 64 + nb * 16 + (lane & 15)) * 80 +
                                ((lane >> 4) * 16) + koff;
                unsigned bh[4], bl[4];
                ldm4(bh, addr);
                ldm4(bl, addr + 20480);
                unsigned b0h[2] = {bh[0], bh[2]}, b1h[2] = {bh[1], bh[3]};
                unsigned b0l[2] = {bl[0], bl[2]}, b1l[2] = {bl[1], bl[3]};
                float* a0 = acc[0][nb * 2];
                float* a1 = acc[1][nb * 2];
                float* c0 = acc[0][nb * 2 + 1];
                float* c1 = acc[1][nb * 2 + 1];
                MMA_GROUP(a0, a1, c0, c1, ah, al, b0h, b1h, b0l, b1l)
            }
        }
    }
#undef BNG_LOADB
#undef BNG_LDGA

    const int M_ = M, Nout = 512;
    (void)M_;
    EPILOGUE_STORE(256, Nout, NO_BIAS)
    EPILOGUE_STATS(256)
}

// ---------------- decoder final GEMM with fused edge-combine loader ----------------
#define DEC_SMEM (2 * 20480 + 3 * 20480)

__global__ __launch_bounds__(512)
void k_dec(const float* __restrict__ PQ,
           const __nv_bfloat16* __restrict__ Bh, const __nv_bfloat16* __restrict__ Bl,
           float* __restrict__ Cf, int M,
           const int* __restrict__ gu, const int* __restrict__ gv,
           const float* __restrict__ bias1, const float* __restrict__ bias2) {
    constexpr int KTOT = 512, NB = 2, NC = 16;
    extern __shared__ __align__(16) char smem[];
    __shared__ int s_u[128], s_v[128];
    const int tid = threadIdx.x;
    const int wid = tid >> 5, lane = tid & 31;
    const int wm = wid & 3, wn = wid >> 2;
    const int bm = blockIdx.x * 128;
    const unsigned sb = smem_u32(smem);

    if (tid < 128) {
        int e = min(bm + tid, M - 1);
        s_u[tid] = gu[e];
        s_v[tid] = gv[e];
    }
    __syncthreads();

    const int arow = tid >> 2, quad = tid & 3;
    const size_t prow = (size_t)s_u[arow] * 1024;
    const size_t qrow = (size_t)s_v[arow] * 1024 + 512;

    ACC_INIT(NB)

#define DEC_LOADB(STG, K0)                                                     \
    {                                                                          \
        unsigned st = sb + 40960 + (STG) * 20480;                              \
        unsigned bd = arow * 80 + quad * 16;                                   \
        size_t ob = (size_t)arow * KTOT + (K0) + quad * 8;                     \
        cpasync16(st + bd, Bh + ob);                                           \
        cpasync16(st + 10240 + bd, Bl + ob);                                   \
    }
#define DEC_LDGA(K0)                                                           \
    {                                                                          \
        const float4* pp = (const float4*)(PQ + prow + (K0) + quad * 8);       \
        const float4* qq = (const float4*)(PQ + qrow + (K0) + quad * 8);       \
        pa[0] = __ldg(pp); pa[1] = __ldg(pp + 1);                              \
        qa[0] = __ldg(qq); qa[1] = __ldg(qq + 1);                              \
    }

    float4 pa[2], qa[2];
    DEC_LDGA(0);
    DEC_LOADB(0, 0);
    asm volatile("cp.async.commit_group;");
    DEC_LOADB(1, 32);
    asm volatile("cp.async.commit_group;");

    for (int c = 0; c < NC; c++) {
        {
            unsigned hi[4], lo[4];
            const float* b1 = bias1 + c * 32 + quad * 8;
#pragma unroll
            for (int j = 0; j < 2; j++) {
                float4 p = pa[j], q = qa[j];
                float4 bb = *(const float4*)(b1 + j * 4);
                float x0 = fmaxf(p.x + q.x + bb.x, 0.f);
                float x1 = fmaxf(p.y + q.y + bb.y, 0.f);
                float x2 = fmaxf(p.z + q.z + bb.z, 0.f);
                float x3 = fmaxf(p.w + q.w + bb.w, 0.f);
                split2(x0, x1, hi[j * 2], lo[j * 2]);
                split2(x2, x3, hi[j * 2 + 1], lo[j * 2 + 1]);
            }
            char* ad = smem + (c & 1) * 20480 + arow * 80 + quad * 16;
            *(uint4*)ad = make_uint4(hi[0], hi[1], hi[2], hi[3]);
            *(uint4*)(ad + 10240) = make_uint4(lo[0], lo[1], lo[2], lo[3]);
        }
        asm volatile("cp.async.wait_group 1;");
        __syncthreads();
        if (c + 1 < NC) DEC_LDGA((c + 1) * 32);
        if (c + 2 < NC) DEC_LOADB((c + 2) % 3, (c + 2) * 32);
        asm volatile("cp.async.commit_group;");

        const unsigned ast = sb + (c & 1) * 20480;
        const unsigned bst = sb + 40960 + (c % 3) * 20480;
#pragma unroll
        for (int ks = 0; ks < 2; ks++) {
            const unsigned koff = ks * 32;
            unsigned ah[2][4], al[2][4];
#pragma unroll
            for (int mf = 0; mf < 2; mf++) {
                unsigned addr = ast + (wm * 32 + mf * 16 + (lane & 15)) * 80 +
                                ((lane >> 4) * 16) + koff;
                ldm4(ah[mf], addr);
                ldm4(al[mf], addr + 10240);
            }
#pragma unroll
            for (int nb = 0; nb < NB; nb++) {
                unsigned addr = bst + (wn * 32 + nb * 16 + (lane & 15)) * 80 +
                                ((lane >> 4) * 16) + koff;
                unsigned bh[4], bl[4];
                ldm4(bh, addr);
                ldm4(bl, addr + 10240);
                unsigned b0h[2] = {bh[0], bh[2]}, b1h[2] = {bh[1], bh[3]};
                unsigned b0l[2] = {bl[0], bl[2]}, b1l[2] = {bl[1], bl[3]};
                float* a0 = acc[0][nb * 2];
                float* a1 = acc[1][nb * 2];
                float* c0 = acc[0][nb * 2 + 1];
                float* c1 = acc[1][nb * 2 + 1];
                MMA_GROUP(a0, a1, c0, c1, ah, al, b0h, b1h, b0l, b1l)
            }
        }
    }
#undef DEC_LOADB
#undef DEC_LDGA

#pragma unroll
    for (int mf = 0; mf < 2; mf++) {
        const int r0 = bm + wm * 32 + mf * 16 + (lane >> 2);
#pragma unroll
        for (int nf = 0; nf < 2 * NB; nf++) {
            const int col = wn * 32 + nf * 8 + (lane & 3) * 2;
#pragma unroll
            for (int hh = 0; hh < 2; hh++) {
                const int row = r0 + hh * 8;
                if (row >= M) continue;
                float2 s = make_float2(acc[mf][nf][hh * 2] + bias2[col],
                                       acc[mf][nf][hh * 2 + 1] + bias2[col + 1]);
                *(float2*)(Cf + (size_t)row * OUTD + col) = s;
            }
        }
    }
}

// ---------------- CSR build ----------------
__global__ void k_zerodeg(int Nn) {
    int i = blockIdx.x * blockDim.x + threadIdx.x;
    if (i < Nn) g_deg[i] = 0;
}
__global__ void k_deg(const int* __restrict__ u, const int* __restrict__ v, int E) {
    int e = blockIdx.x * blockDim.x + threadIdx.x;
    if (e >= E) return;
    atomicAdd(&g_deg[u[e]], 1);
    atomicAdd(&g_deg[v[e]], 1);
}
__global__ void k_scan(int Nn) {
    __shared__ int warpsum[32];
    __shared__ int s_carry;
    const int tid = threadIdx.x, lane = tid & 31, w = tid >> 5;
    if (tid == 0) s_carry = 0;
    __syncthreads();
    for (int base = 0; base < Nn; base += 1024) {
        int i = base + tid;
        int v = (i < Nn) ? g_deg[i] : 0;
        int x = v;
#pragma unroll
        for (int o = 1; o < 32; o <<= 1) {
            int t = __shfl_up_sync(0xffffffffu, x, o);
            if (lane >= o) x += t;
        }
        if (lane == 31) warpsum[w] = x;
        __syncthreads();
        if (w == 0) {
            int s = warpsum[lane];
#pragma unroll
            for (int o = 1; o < 32; o <<= 1) {
                int t = __shfl_up_sync(0xffffffffu, s, o);
                if (lane >= o) s += t;
            }
            warpsum[lane] = s;
        }
        __syncthreads();
        int incl = x + (w > 0 ? warpsum[w - 1] : 0) + s_carry;
        if (i < Nn) {
            int excl = incl - v;
            g_off[i] = excl;
            g_cur[i] = excl;
        }
        __syncthreads();
        if (tid == 1023) s_carry = incl;
        __syncthreads();
    }
    if (tid == 0) g_off[Nn] = s_carry;
}
__global__ void k_fill(const int* __restrict__ u, const int* __restrict__ v, int E) {
    int e = blockIdx.x * blockDim.x + threadIdx.x;
    if (e >= E) return;
    int a = u[e], b = v[e];
    int p = atomicAdd(&g_cur[b], 1);
    g_adj[p] = a;
    int q = atomicAdd(&g_cur[a], 1);
    g_adj[q] = b;
}

// ---------------- aggregation: z = 2h + sum_{nb} h[nb]  -> bf16 pairs ----------------
__global__ void k_agg(int Nn) {
    int node = blockIdx.x * 8 + (threadIdx.x >> 5);
    if (node >= Nn) return;
    const int lane = threadIdx.x & 31;
    float4 acc[4];
    const float4* hp = (const float4*)(g_h + (size_t)node * D);
#pragma unroll
    for (int j = 0; j < 4; j++) {
        float4 t = hp[j * 32 + lane];
        acc[j] = make_float4(2.f * t.x, 2.f * t.y, 2.f * t.z, 2.f * t.w);
    }
    const int e1 = g_off[node + 1];
    for (int e = g_off[node]; e < e1; e++) {
        const float4* np = (const float4*)(g_h + (size_t)g_adj[e] * D);
#pragma unroll
        for (int j = 0; j < 4; j++) {
            float4 t = np[j * 32 + lane];
            acc[j].x += t.x; acc[j].y += t.y; acc[j].z += t.z; acc[j].w += t.w;
        }
    }
#pragma unroll
    for (int j = 0; j < 4; j++) {
        unsigned h0, l0, h1, l1;
        split2(acc[j].x, acc[j].y, h0, l0);
        split2(acc[j].z, acc[j].w, h1, l1);
        size_t o = (size_t)node * D + (j * 32 + lane) * 4;
        ((unsigned*)(g_zh + o))[0] = h0;
        ((unsigned*)(g_zh + o))[1] = h1;
        ((unsigned*)(g_zl + o))[0] = l0;
        ((unsigned*)(g_zl + o))[1] = l1;
    }
}

// ---------------- elementwise kernels ----------------
__global__ void k_gather(const int* __restrict__ ids, const float* __restrict__ emb, int Nn) {
    int idx = blockIdx.x * blockDim.x + threadIdx.x;
    int row = idx >> 7;
    if (row >= Nn) return;
    int c = (idx & 127) << 2;
    float4 val = *(const float4*)(emb + (size_t)ids[row] * D + c);
    *(float4*)(g_h + (size_t)row * D + c) = val;
    *(float4*)(g_hsum + (size_t)row * D + c) = val;
}

__global__ void k_tcvt(const float* __restrict__ B, __nv_bfloat16* __restrict__ H,
                       __nv_bfloat16* __restrict__ Lo, int K, int Nn) {
    int idx = blockIdx.x * blockDim.x + threadIdx.x;
    if (idx >= K * Nn) return;
    int n = idx / K, k = idx - n * K;
    float x = B[(size_t)k * Nn + n];
    __nv_bfloat16 h, l;
    f2pair(x, h, l);
    H[idx] = h; Lo[idx] = l;
}

__global__ void k_bnzero2() {
    int t = blockIdx.x * blockDim.x + threadIdx.x;
    if (t < 2048) g_stats[t] = 0.f;
}

// h = relu(affine(Y2)); hsum += h ; aff computed in-block from stats slot
// LAST=0: write h fp32 + hsum fp32.  LAST=1: write (hsum+h) as bf16 pairs only.
template <int LAST>
__global__ void k_bnrelu_acc(const float* __restrict__ Y2,
                             const float* __restrict__ stats,
                             const float* __restrict__ gamma,
                             const float* __restrict__ beta, int Nn) {
    __shared__ float s_aff[1024];
    int tid = threadIdx.x;
    {
        float inv = 1.f / (float)Nn;
#pragma unroll
        for (int j = tid; j < 512; j += 256) {
            float m = stats[j] * inv;
            float var = stats[512 + j] * inv - m * m;
            float sc = gamma[j] * rsqrtf(var + BN_EPS);
            s_aff[j] = sc;
            s_aff[512 + j] = beta[j] - m * sc;
        }
    }
    __syncthreads();
    int idx = blockIdx.x * blockDim.x + tid;
    if (idx >= Nn * 128) return;
    int c = (idx & 127) << 2;
    float4 v = *(const float4*)(Y2 + (size_t)idx * 4);
    v.x = fmaxf(v.x * s_aff[c + 0] + s_aff[512 + c + 0], 0.f);
    v.y = fmaxf(v.y * s_aff[c + 1] + s_aff[512 + c + 1], 0.f);
    v.z = fmaxf(v.z * s_aff[c + 2] + s_aff[512 + c + 2], 0.f);
    v.w = fmaxf(v.w * s_aff[c + 3] + s_aff[512 + c + 3], 0.f);
    float4 hs = *(const float4*)(g_hsum + (size_t)idx * 4);
    hs.x += v.x; hs.y += v.y; hs.z += v.z; hs.w += v.w;
    if (!LAST) {
        *(float4*)(g_h + (size_t)idx * 4) = v;
        *(float4*)(g_hsum + (size_t)idx * 4) = hs;
    } else {
        unsigned h0, l0, h1, l1;
        split2(hs.x, hs.y, h0, l0);
        split2(hs.z, hs.w, h1, l1);
        ((unsigned*)(g_hsh + (size_t)idx * 4))[0] = h0;
        ((unsigned*)(g_hsh + (size_t)idx * 4))[1] = h1;
        ((unsigned*)(g_hsl + (size_t)idx * 4))[0] = l0;
        ((unsigned*)(g_hsl + (size_t)idx * 4))[1] = l1;
    }
}

// ---------------- launch ----------------
extern "C" void kernel_launch(void* const* d_in, const int* in_sizes, int n_in,
                              void* d_out, int out_size) {
    const int* h_ids = (const int*)d_in[0];
    const int* u     = (const int*)d_in[1];
    const int* v     = (const int*)d_in[2];
    const float* emb   = (const float*)d_in[3];
    const float* lin1  = (const float*)d_in[4];
    const float* lin2  = (const float*)d_in[5];
    const float* bn1_g = (const float*)d_in[6];
    const float* bn1_b = (const float*)d_in[7];
    const float* bn2_g = (const float*)d_in[8];
    const float* bn2_b = (const float*)d_in[9];
    const float* W1_w  = (const float*)d_in[10];
    const float* W1_b  = (const float*)d_in[11];
    const float* W2_w  = (const float*)d_in[12];
    const float* W2_b  = (const float*)d_in[13];
    float* out = (float*)d_out;

    const int N = in_sizes[0];
    const int E = in_sizes[1];
    const int L = in_sizes[4] / (D * D);

    const int SMEM_256 = (20480 + 256 * 160) * NSTAGE;  // 184320

    static int s_attr = 0;
    if (!s_attr) {
        cudaFuncSetAttribute(k_mma<512, 256, 1>, cudaFuncAttributeMaxDynamicSharedMemorySize, SMEM_256);
        cudaFuncSetAttribute(k_mma<512, 256, 0>, cudaFuncAttributeMaxDynamicSharedMemorySize, SMEM_256);
        cudaFuncSetAttribute(k_mma_bn, cudaFuncAttributeMaxDynamicSharedMemorySize, BNG_SMEM);
        cudaFuncSetAttribute(k_dec, cudaFuncAttributeMaxDynamicSharedMemorySize, DEC_SMEM);
        s_attr = 1;
    }

    float *dg_z, *dg_y, *dg_pq, *dg_stats;
    cudaGetSymbolAddress((void**)&dg_z, g_z);
    cudaGetSymbolAddress((void**)&dg_y, g_y);
    cudaGetSymbolAddress((void**)&dg_pq, g_pq);
    cudaGetSymbolAddress((void**)&dg_stats, g_stats);
    __nv_bfloat16 *zh, *zl, *hsh, *hsl;
    __nv_bfloat16 *l1th, *l1tl, *l2th, *l2tl, *w1th, *w1tl, *w2th, *w2tl;
    cudaGetSymbolAddress((void**)&zh, g_zh);  cudaGetSymbolAddress((void**)&zl, g_zl);
    cudaGetSymbolAddress((void**)&hsh, g_hsh); cudaGetSymbolAddress((void**)&hsl, g_hsl);
    cudaGetSymbolAddress((void**)&l1th, g_l1th); cudaGetSymbolAddress((void**)&l1tl, g_l1tl);
    cudaGetSymbolAddress((void**)&l2th, g_l2th); cudaGetSymbolAddress((void**)&l2tl, g_l2tl);
    cudaGetSymbolAddress((void**)&w1th, g_w1th); cudaGetSymbolAddress((void**)&w1tl, g_w1tl);
    cudaGetSymbolAddress((void**)&w2th, g_w2th); cudaGetSymbolAddress((void**)&w2tl, g_w2tl);

    const int ew = N * 128, ewB = (ew + 255) / 256;
    const int mtiles = (N + 127) / 128;
    const int etiles = (E + 127) / 128;
    const int edB = (E + 255) / 256;
    const int ndB = (N + 255) / 256;
    const int aggB = (N + 7) / 8;

    // weight conversion (transpose + split)
    const int wB = (D * D + 255) / 256;
    for (int i = 0; i < L; i++) {
        k_tcvt<<<wB, 256>>>(lin1 + (size_t)i * D * D, l1th + (size_t)i * D * D, l1tl + (size_t)i * D * D, D, D);
        k_tcvt<<<wB, 256>>>(lin2 + (size_t)i * D * D, l2th + (size_t)i * D * D, l2tl + (size_t)i * D * D, D, D);
    }
    k_tcvt<<<wB, 256>>>(W1_w, w1th, w1tl, D, D);
    k_tcvt<<<wB, 256>>>(W1_w + (size_t)D * D, w1th + (size_t)D * D, w1tl + (size_t)D * D, D, D);
    k_tcvt<<<(D * OUTD + 255) / 256, 256>>>(W2_w, w2th, w2tl, D, OUTD);

    // h = emb[h_ids]; hidden_sum = h
    k_gather<<<ewB, 256>>>(h_ids, emb, N);

    // CSR build (once)
    k_zerodeg<<<ndB, 256>>>(N);
    k_deg<<<edB, 256>>>(u, v, E);
    k_scan<<<1, 1024>>>(N);
    k_fill<<<edB, 256>>>(u, v, E);

    for (int i = 0; i < L; i++) {
        // z = 2h + neighbor sums -> bf16 pairs ; zero both stats slots
        k_agg<<<aggB, 256>>>(N);
        k_bnzero2<<<2, 1024>>>();
        // y = z @ lin1[i]  (stats -> slot0)
        k_mma<512, 256, 1><<<dim3(mtiles, 2), 512, SMEM_256>>>(
            zh, zl, l1th + (size_t)i * D * D, l1tl + (size_t)i * D * D,
            dg_y, N, D, dg_stats);
        // z(out) = relu(bn1(y)) @ lin2[i]  (fused BN loader; stats -> slot1)
        k_mma_bn<<<dim3(mtiles, 2), 512, BNG_SMEM>>>(
            dg_y, l2th + (size_t)i * D * D, l2tl + (size_t)i * D * D,
            dg_z, N,
            dg_stats, bn1_g + (size_t)i * D, bn1_b + (size_t)i * D,
            dg_stats + 1024);
        // h = relu(bn2(z)); hsum += h  (aff computed in-block from slot1)
        if (i == L - 1)
            k_bnrelu_acc<1><<<ewB, 256>>>(dg_z, dg_stats + 1024,
                bn2_g + (size_t)i * D, bn2_b + (size_t)i * D, N);
        else
            k_bnrelu_acc<0><<<ewB, 256>>>(dg_z, dg_stats + 1024,
                bn2_g + (size_t)i * D, bn2_b + (size_t)i * D, N);
    }

    // decoder: [P|Q] = hsum_pairs @ [W1a;W1b]^T  (one GEMM, Nout=1024)
    k_mma<512, 256, 0><<<dim3(mtiles, 4), 512, SMEM_256>>>(
        hsh, hsl, w1th, w1tl, dg_pq, N, 2 * D, nullptr);
    // out = relu(P[u]+Q[v]+b1) @ W2^T + b2  (fused edge loader)
    k_dec<<<etiles, 512, DEC_SMEM>>>(dg_pq, w2th, w2tl, out, E, u, v, W1_b, W2_b);
}

// round 11
// speedup vs baseline: 3.2165x; 1.0285x over previous
#include <cuda_runtime.h>
#include <cuda_bf16.h>
#include <cuda_fp16.h>

#define D 512
#define OUTD 128
#define MAXN 50000
#define MAXE 150000
#define BN_EPS 1e-5f

// ---------------- scratch (static device globals; no allocation) ----------------
__device__ float g_h[(size_t)MAXN * D];     // current node features
__device__ float g_hsum[(size_t)MAXN * D];  // hidden_sum accumulator
__device__ float g_y[(size_t)MAXN * D];     // gemm1 output
__device__ float g_z[(size_t)MAXN * D];     // gemm2 output
__device__ float g_pq[(size_t)MAXN * 2 * D];// decoder P|Q concat
__device__ float g_stats[2 * 1024];         // slot0: GEMM1 (sum,sumsq), slot1: GEMM2

// CSR graph
__device__ int g_deg[MAXN];
__device__ int g_off[MAXN + 1];
__device__ int g_cur[MAXN];
__device__ int g_adj[2 * MAXE];

// bf16 split pairs (layer path)
__device__ __nv_bfloat16 g_zh[(size_t)MAXN * D], g_zl[(size_t)MAXN * D];
// fp16 split pairs (decoder PQ path)
__device__ __half g_hsfh[(size_t)MAXN * D], g_hsfl[(size_t)MAXN * D];
// transposed + split weights: Bt[n][k]
__device__ __nv_bfloat16 g_l1th[(size_t)4 * D * D], g_l1tl[(size_t)4 * D * D];
__device__ __nv_bfloat16 g_l2th[(size_t)4 * D * D], g_l2tl[(size_t)4 * D * D];
__device__ __half g_w1f[(size_t)D * 2 * D];                 // fp16 single, [a|b] rows
__device__ __nv_bfloat16 g_w2th[(size_t)OUTD * D], g_w2tl[(size_t)OUTD * D];

// ---------------- PTX helpers (plain compute_100-legal) ----------------
__device__ __forceinline__ unsigned smem_u32(const void* p) {
    unsigned a;
    asm("{ .reg .u64 t; cvta.to.shared.u64 t, %1; cvt.u32.u64 %0, t; }" : "=r"(a) : "l"(p));
    return a;
}
__device__ __forceinline__ void cpasync16(unsigned dst, const void* src) {
    asm volatile("cp.async.cg.shared.global [%0], [%1], 16;" ::"r"(dst), "l"(src));
}
__device__ __forceinline__ void ldm4(unsigned* r, unsigned addr) {
    asm volatile("ldmatrix.sync.aligned.m8n8.x4.shared.b16 {%0,%1,%2,%3}, [%4];"
                 : "=r"(r[0]), "=r"(r[1]), "=r"(r[2]), "=r"(r[3]) : "r"(addr));
}
__device__ __forceinline__ void mma16816(float* c, const unsigned* a, const unsigned* b) {
    asm volatile(
        "mma.sync.aligned.m16n8k16.row.col.f32.bf16.bf16.f32 "
        "{%0,%1,%2,%3}, {%4,%5,%6,%7}, {%8,%9}, {%0,%1,%2,%3};"
        : "+f"(c[0]), "+f"(c[1]), "+f"(c[2]), "+f"(c[3])
        : "r"(a[0]), "r"(a[1]), "r"(a[2]), "r"(a[3]), "r"(b[0]), "r"(b[1]));
}
__device__ __forceinline__ void mma16816h(float* c, const unsigned* a, const unsigned* b) {
    asm volatile(
        "mma.sync.aligned.m16n8k16.row.col.f32.f16.f16.f32 "
        "{%0,%1,%2,%3}, {%4,%5,%6,%7}, {%8,%9}, {%0,%1,%2,%3};"
        : "+f"(c[0]), "+f"(c[1]), "+f"(c[2]), "+f"(c[3])
        : "r"(a[0]), "r"(a[1]), "r"(a[2]), "r"(a[3]), "r"(b[0]), "r"(b[1]));
}
__device__ __forceinline__ void f2pair(float v, __nv_bfloat16& h, __nv_bfloat16& l) {
    h = __float2bfloat16(v);
    l = __float2bfloat16(v - __bfloat162float(h));
}
__device__ __forceinline__ void split2(float a, float b, unsigned& hi, unsigned& lo) {
    __nv_bfloat16 h0, l0, h1, l1;
    f2pair(a, h0, l0);
    f2pair(b, h1, l1);
    __nv_bfloat162 hp; hp.x = h0; hp.y = h1;
    __nv_bfloat162 lp; lp.x = l0; lp.y = l1;
    hi = *(unsigned*)&hp;
    lo = *(unsigned*)&lp;
}
__device__ __forceinline__ void split2h(float a, float b, unsigned& hi, unsigned& lo) {
    __half h0 = __float2half(a);
    __half l0 = __float2half(a - __half2float(h0));
    __half h1 = __float2half(b);
    __half l1 = __float2half(b - __half2float(h1));
    __half2 hp; hp.x = h0; hp.y = h1;
    __half2 lp; lp.x = l0; lp.y = l1;
    hi = *(unsigned*)&hp;
    lo = *(unsigned*)&lp;
}

// 12 mma for one nb-block, accumulator reuse distance >= 3
#define MMA_GROUP(A0, A1, C0, C1, AH, AL, B0H, B1H, B0L, B1L)                  \
    mma16816(A0, AH[0], B0H); mma16816(A1, AH[1], B0H);                        \
    mma16816(C0, AH[0], B1H); mma16816(C1, AH[1], B1H);                        \
    mma16816(A0, AH[0], B0L); mma16816(A1, AH[1], B0L);                        \
    mma16816(C0, AH[0], B1L); mma16816(C1, AH[1], B1L);                        \
    mma16816(A0, AL[0], B0H); mma16816(A1, AL[1], B0H);                        \
    mma16816(C0, AL[0], B1H); mma16816(C1, AL[1], B1H);

#define EPILOGUE_STORE(BN_, NOUT_)                                             \
    _Pragma("unroll") for (int mf = 0; mf < 2; mf++) {                         \
        const int r0 = bm + wm * 32 + mf * 16 + (lane >> 2);                   \
        _Pragma("unroll") for (int nf = 0; nf < 2 * ((BN_) / 64); nf++) {      \
            const int col = bn + wn * ((BN_) / 4) + nf * 8 + (lane & 3) * 2;   \
            const float* a = acc[mf][nf];                                      \
            _Pragma("unroll") for (int hh = 0; hh < 2; hh++) {                 \
                const int row = r0 + hh * 8;                                   \
                if (row >= M) continue;                                        \
                float2 s = make_float2(a[hh * 2], a[hh * 2 + 1]);              \
                *(float2*)(Cf + (size_t)row * (NOUT_) + col) = s;              \
            }                                                                  \
        }                                                                      \
    }

#define EPILOGUE_STATS(BN_)                                                    \
    _Pragma("unroll") for (int nf = 0; nf < 2 * ((BN_) / 64); nf++) {          \
        float s0 = 0.f, s1 = 0.f, q0 = 0.f, q1 = 0.f;                          \
        _Pragma("unroll") for (int mf = 0; mf < 2; mf++) {                     \
            const int rb = bm + wm * 32 + mf * 16 + (lane >> 2);               \
            _Pragma("unroll") for (int hh = 0; hh < 2; hh++) {                 \
                if (rb + hh * 8 < M) {                                         \
                    float v0 = acc[mf][nf][hh * 2], v1 = acc[mf][nf][hh * 2 + 1];\
                    s0 += v0; q0 += v0 * v0;                                   \
                    s1 += v1; q1 += v1 * v1;                                   \
                }                                                              \
            }                                                                  \
        }                                                                      \
        _Pragma("unroll") for (int o = 4; o < 32; o <<= 1) {                   \
            s0 += __shfl_xor_sync(0xffffffffu, s0, o);                         \
            s1 += __shfl_xor_sync(0xffffffffu, s1, o);                         \
            q0 += __shfl_xor_sync(0xffffffffu, q0, o);                         \
            q1 += __shfl_xor_sync(0xffffffffu, q1, o);                         \
        }                                                                      \
        if ((lane >> 2) == 0) {                                                \
            int col = bn + wn * ((BN_) / 4) + nf * 8 + (lane & 3) * 2;         \
            atomicAdd(&stats_out[col], s0);                                    \
            atomicAdd(&stats_out[col + 1], s1);                                \
            atomicAdd(&stats_out[512 + col], q0);                              \
            atomicAdd(&stats_out[512 + col + 1], q1);                          \
        }                                                                      \
    }

#define ACC_INIT(NB_)                                                          \
    float acc[2][2 * (NB_)][4];                                                \
    _Pragma("unroll") for (int i = 0; i < 2; i++)                              \
        _Pragma("unroll") for (int j = 0; j < 2 * (NB_); j++)                  \
            _Pragma("unroll") for (int q = 0; q < 4; q++) acc[i][j][q] = 0.f;

// ---------------- mma.sync split-bf16 GEMM (pair inputs) ----------------
#define NSTAGE 3

template <int KTOT, int BN, int STATS>
__global__ __launch_bounds__(512)
void k_mma(const __nv_bfloat16* __restrict__ Ah, const __nv_bfloat16* __restrict__ Al,
           const __nv_bfloat16* __restrict__ Bh, const __nv_bfloat16* __restrict__ Bl,
           float* __restrict__ Cf, int M, int Nout, float* __restrict__ stats_out) {
    constexpr int NB = BN / 64;
    constexpr int O_AL = 10240;
    constexpr int O_BH = 20480;
    constexpr int O_BL = 20480 + BN * 80;
    constexpr int STAGE_BYTES = 20480 + BN * 160;

    extern __shared__ __align__(16) char smem[];
    const int tid = threadIdx.x;
    const int wid = tid >> 5, lane = tid & 31;
    const int wm = wid & 3, wn = wid >> 2;
    const int bm = blockIdx.x * 128, bn = blockIdx.y * BN;
    const unsigned sb = smem_u32(smem);

    const int arow = tid >> 2, quad = tid & 3;
    const int grA = min(bm + arow, M - 1);

    ACC_INIT(NB)

#define LOAD_CHUNK(STG, K0)                                                    \
    {                                                                          \
        unsigned st = sb + (STG) * STAGE_BYTES;                                \
        unsigned dsto = arow * 80 + quad * 16;                                 \
        size_t o = (size_t)grA * KTOT + (K0) + quad * 8;                       \
        cpasync16(st + dsto, Ah + o);                                          \
        cpasync16(st + O_AL + dsto, Al + o);                                   \
        _Pragma("unroll") for (int i = 0; i < BN / 128; i++) {                 \
            int brow = arow + i * 128;                                         \
            unsigned bd = brow * 80 + quad * 16;                               \
            size_t ob = (size_t)(bn + brow) * KTOT + (K0) + quad * 8;          \
            cpasync16(st + O_BH + bd, Bh + ob);                                \
            cpasync16(st + O_BL + bd, Bl + ob);                                \
        }                                                                      \
    }

    const int NC = KTOT / 32;
#pragma unroll
    for (int p = 0; p < NSTAGE - 1; p++) {
        if (p < NC) LOAD_CHUNK(p, p * 32);
        asm volatile("cp.async.commit_group;");
    }

    int cstg = 0, lstg = NSTAGE - 1;
    for (int c = 0; c < NC; c++) {
        asm volatile("cp.async.wait_group %0;" ::"n"(NSTAGE - 2));
        __syncthreads();
        if (c + NSTAGE - 1 < NC) LOAD_CHUNK(lstg, (c + NSTAGE - 1) * 32);
        asm volatile("cp.async.commit_group;");
        lstg = (lstg + 1 == NSTAGE) ? 0 : lstg + 1;

        const unsigned st = sb + cstg * STAGE_BYTES;
        cstg = (cstg + 1 == NSTAGE) ? 0 : cstg + 1;
#pragma unroll
        for (int ks = 0; ks < 2; ks++) {
            const unsigned koff = ks * 32;
            unsigned ah[2][4], al[2][4];
#pragma unroll
            for (int mf = 0; mf < 2; mf++) {
                unsigned addr = st + (wm * 32 + mf * 16 + (lane & 15)) * 80 +
                                ((lane >> 4) * 16) + koff;
                ldm4(ah[mf], addr);
                ldm4(al[mf], addr + O_AL);
            }
#pragma unroll
            for (int nb = 0; nb < NB; nb++) {
                unsigned addr = st + O_BH +
                                (wn * (BN / 4) + nb * 16 + (lane & 15)) * 80 +
                                ((lane >> 4) * 16) + koff;
                unsigned bh[4], bl[4];
                ldm4(bh, addr);
                ldm4(bl, addr + BN * 80);
                unsigned b0h[2] = {bh[0], bh[2]}, b1h[2] = {bh[1], bh[3]};
                unsigned b0l[2] = {bl[0], bl[2]}, b1l[2] = {bl[1], bl[3]};
                float* a0 = acc[0][nb * 2];
                float* a1 = acc[1][nb * 2];
                float* c0 = acc[0][nb * 2 + 1];
                float* c1 = acc[1][nb * 2 + 1];
                MMA_GROUP(a0, a1, c0, c1, ah, al, b0h, b1h, b0l, b1l)
            }
        }
    }
#undef LOAD_CHUNK

    EPILOGUE_STORE(BN, Nout)
    if (STATS) { EPILOGUE_STATS(BN) }
}

// ---------------- PQ GEMM: 2-pass fp16 (A hi+lo fp16, B single fp16) ----------------
// C = A @ Bf^T ; A = g_hsfh + g_hsfl (exact to 2^-22), Bf = fp16(W1t).
#define PQ_SMEM (3 * 40960)  // 122880

__global__ __launch_bounds__(512)
void k_mma_pq(const __half* __restrict__ Ah, const __half* __restrict__ Al,
              const __half* __restrict__ Bf,
              float* __restrict__ Cf, int M, int Nout) {
    constexpr int KTOT = 512, BN = 256, NB = 4, NC = 16;
    constexpr int O_AL = 10240, O_B = 20480, STAGE_BYTES = 40960;

    extern __shared__ __align__(16) char smem[];
    const int tid = threadIdx.x;
    const int wid = tid >> 5, lane = tid & 31;
    const int wm = wid & 3, wn = wid >> 2;
    const int bm = blockIdx.x * 128, bn = blockIdx.y * BN;
    const unsigned sb = smem_u32(smem);

    const int arow = tid >> 2, quad = tid & 3;
    const int grA = min(bm + arow, M - 1);

    ACC_INIT(NB)

#define PQ_LOAD(STG, K0)                                                       \
    {                                                                          \
        unsigned st = sb + (STG) * STAGE_BYTES;                                \
        unsigned dsto = arow * 80 + quad * 16;                                 \
        size_t o = (size_t)grA * KTOT + (K0) + quad * 8;                       \
        cpasync16(st + dsto, Ah + o);                                          \
        cpasync16(st + O_AL + dsto, Al + o);                                   \
        _Pragma("unroll") for (int i = 0; i < 2; i++) {                        \
            int brow = arow + i * 128;                                         \
            unsigned bd = brow * 80 + quad * 16;                               \
            size_t ob = (size_t)(bn + brow) * KTOT + (K0) + quad * 8;          \
            cpasync16(st + O_B + bd, Bf + ob);                                 \
        }                                                                      \
    }

#pragma unroll
    for (int p = 0; p < NSTAGE - 1; p++) {
        if (p < NC) PQ_LOAD(p, p * 32);
        asm volatile("cp.async.commit_group;");
    }

    int cstg = 0, lstg = NSTAGE - 1;
    for (int c = 0; c < NC; c++) {
        asm volatile("cp.async.wait_group %0;" ::"n"(NSTAGE - 2));
        __syncthreads();
        if (c + NSTAGE - 1 < NC) PQ_LOAD(lstg, (c + NSTAGE - 1) * 32);
        asm volatile("cp.async.commit_group;");
        lstg = (lstg + 1 == NSTAGE) ? 0 : lstg + 1;

        const unsigned st = sb + cstg * STAGE_BYTES;
        cstg = (cstg + 1 == NSTAGE) ? 0 : cstg + 1;
#pragma unroll
        for (int ks = 0; ks < 2; ks++) {
            const unsigned koff = ks * 32;
            unsigned ah[2][4], al[2][4];
#pragma unroll
            for (int mf = 0; mf < 2; mf++) {
                unsigned addr = st + (wm * 32 + mf * 16 + (lane & 15)) * 80 +
                                ((lane >> 4) * 16) + koff;
                ldm4(ah[mf], addr);
                ldm4(al[mf], addr + O_AL);
            }
#pragma unroll
            for (int nb = 0; nb < NB; nb++) {
                unsigned addr = st + O_B +
                                (wn * 64 + nb * 16 + (lane & 15)) * 80 +
                                ((lane >> 4) * 16) + koff;
                unsigned bb[4];
                ldm4(bb, addr);
                unsigned b0[2] = {bb[0], bb[2]}, b1[2] = {bb[1], bb[3]};
                float* a0 = acc[0][nb * 2];
                float* a1 = acc[1][nb * 2];
                float* c0 = acc[0][nb * 2 + 1];
                float* c1 = acc[1][nb * 2 + 1];
                mma16816h(a0, ah[0], b0); mma16816h(a1, ah[1], b0);
                mma16816h(c0, ah[0], b1); mma16816h(c1, ah[1], b1);
                mma16816h(a0, al[0], b0); mma16816h(a1, al[1], b0);
                mma16816h(c0, al[0], b1); mma16816h(c1, al[1], b1);
            }
        }
    }
#undef PQ_LOAD

    EPILOGUE_STORE(256, Nout)
}

// ---------------- GEMM2: fused BN-apply loader ----------------
#define BNG_SMEM (2 * 20480 + 3 * 40960 + 4096)  // 167936

__global__ __launch_bounds__(512)
void k_mma_bn(const float* __restrict__ Y,
              const __nv_bfloat16* __restrict__ Bh, const __nv_bfloat16* __restrict__ Bl,
              float* __restrict__ Cf, int M,
              const float* __restrict__ stats_in, const float* __restrict__ gamma,
              const float* __restrict__ beta, float* __restrict__ stats_out) {
    constexpr int KTOT = 512, BN = 256, NB = 4, NC = 16;
    constexpr int O_B = 40960;
    constexpr int O_AFF = 163840;
    extern __shared__ __align__(16) char smem[];
    float* s_aff = (float*)(smem + O_AFF);
    const int tid = threadIdx.x;
    const int wid = tid >> 5, lane = tid & 31;
    const int wm = wid & 3, wn = wid >> 2;
    const int bm = blockIdx.x * 128, bn = blockIdx.y * BN;
    const unsigned sb = smem_u32(smem);

    if (tid < 512) {
        float inv = 1.f / (float)M;
        float m = stats_in[tid] * inv;
        float var = stats_in[512 + tid] * inv - m * m;
        float sc = gamma[tid] * rsqrtf(var + BN_EPS);
        s_aff[tid] = sc;
        s_aff[512 + tid] = beta[tid] - m * sc;
    }

    const int arow = tid >> 2, quad = tid & 3;
    const int grA = min(bm + arow, M - 1);

    ACC_INIT(NB)

#define BNG_LOADB(STG, K0)                                                     \
    {                                                                          \
        unsigned st = sb + O_B + (STG) * 40960;                                \
        _Pragma("unroll") for (int i = 0; i < 2; i++) {                        \
            int brow = arow + i * 128;                                         \
            unsigned bd = brow * 80 + quad * 16;                               \
            size_t ob = (size_t)(bn + brow) * KTOT + (K0) + quad * 8;          \
            cpasync16(st + bd, Bh + ob);                                       \
            cpasync16(st + 20480 + bd, Bl + ob);                               \
        }                                                                      \
    }
#define BNG_LDGA(K0)                                                           \
    {                                                                          \
        const float4* yp = (const float4*)(Y + (size_t)grA * KTOT + (K0) + quad * 8);\
        ya[0] = __ldg(yp); ya[1] = __ldg(yp + 1);                              \
    }

    float4 ya[2];
    BNG_LDGA(0);
    BNG_LOADB(0, 0);
    asm volatile("cp.async.commit_group;");
    BNG_LOADB(1, 32);
    asm volatile("cp.async.commit_group;");
    __syncthreads();  // s_aff visible

    for (int c = 0; c < NC; c++) {
        {
            unsigned hi[4], lo[4];
            const int kb = c * 32 + quad * 8;
#pragma unroll
            for (int j = 0; j < 2; j++) {
                float4 y = ya[j];
                const int k = kb + j * 4;
                float x0 = fmaxf(y.x * s_aff[k + 0] + s_aff[512 + k + 0], 0.f);
                float x1 = fmaxf(y.y * s_aff[k + 1] + s_aff[512 + k + 1], 0.f);
                float x2 = fmaxf(y.z * s_aff[k + 2] + s_aff[512 + k + 2], 0.f);
                float x3 = fmaxf(y.w * s_aff[k + 3] + s_aff[512 + k + 3], 0.f);
                split2(x0, x1, hi[j * 2], lo[j * 2]);
                split2(x2, x3, hi[j * 2 + 1], lo[j * 2 + 1]);
            }
            char* ad = smem + (c & 1) * 20480 + arow * 80 + quad * 16;
            *(uint4*)ad = make_uint4(hi[0], hi[1], hi[2], hi[3]);
            *(uint4*)(ad + 10240) = make_uint4(lo[0], lo[1], lo[2], lo[3]);
        }
        asm volatile("cp.async.wait_group 1;");
        __syncthreads();
        if (c + 1 < NC) BNG_LDGA((c + 1) * 32);
        if (c + 2 < NC) BNG_LOADB((c + 2) % 3, (c + 2) * 32);
        asm volatile("cp.async.commit_group;");

        const unsigned ast = sb + (c & 1) * 20480;
        const unsigned bst = sb + O_B + (c % 3) * 40960;
#pragma unroll
        for (int ks = 0; ks < 2; ks++) {
            const unsigned koff = ks * 32;
            unsigned ah[2][4], al[2][4];
#pragma unroll
            for (int mf = 0; mf < 2; mf++) {
                unsigned addr = ast + (wm * 32 + mf * 16 + (lane & 15)) * 80 +
                                ((lane >> 4) * 16) + koff;
                ldm4(ah[mf], addr);
                ldm4(al[mf], addr + 10240);
            }
#pragma unroll
            for (int nb = 0; nb < NB; nb++) {
                unsigned addr = bst + (wn * 64 + nb * 16 + (lane & 15)) * 80 +
                                ((lane >> 4) * 16) + koff;
                unsigned bh[4], bl[4];
                ldm4(bh, addr);
                ldm4(bl, addr + 20480);
                unsigned b0h[2] = {bh[0], bh[2]}, b1h[2] = {bh[1], bh[3]};
                unsigned b0l[2] = {bl[0], bl[2]}, b1l[2] = {bl[1], bl[3]};
                float* a0 = acc[0][nb * 2];
                float* a1 = acc[1][nb * 2];
                float* c0 = acc[0][nb * 2 + 1];
                float* c1 = acc[1][nb * 2 + 1];
                MMA_GROUP(a0, a1, c0, c1, ah, al, b0h, b1h, b0l, b1l)
            }
        }
    }
#undef BNG_LOADB
#undef BNG_LDGA

    const int Nout = 512;
    EPILOGUE_STORE(256, Nout)
    EPILOGUE_STATS(256)
}

// ---------------- decoder final GEMM with fused edge-combine loader ----------------
#define DEC_SMEM (2 * 20480 + 3 * 20480)

__global__ __launch_bounds__(512)
void k_dec(const float* __restrict__ PQ,
           const __nv_bfloat16* __restrict__ Bh, const __nv_bfloat16* __restrict__ Bl,
           float* __restrict__ Cf, int M,
           const int* __restrict__ gu, const int* __restrict__ gv,
           const float* __restrict__ bias1, const float* __restrict__ bias2) {
    constexpr int KTOT = 512, NB = 2, NC = 16;
    extern __shared__ __align__(16) char smem[];
    __shared__ int s_u[128], s_v[128];
    const int tid = threadIdx.x;
    const int wid = tid >> 5, lane = tid & 31;
    const int wm = wid & 3, wn = wid >> 2;
    const int bm = blockIdx.x * 128;
    const unsigned sb = smem_u32(smem);

    if (tid < 128) {
        int e = min(bm + tid, M - 1);
        s_u[tid] = gu[e];
        s_v[tid] = gv[e];
    }
    __syncthreads();

    const int arow = tid >> 2, quad = tid & 3;
    const size_t prow = (size_t)s_u[arow] * 1024;
    const size_t qrow = (size_t)s_v[arow] * 1024 + 512;

    ACC_INIT(NB)

#define DEC_LOADB(STG, K0)                                                     \
    {                                                                          \
        unsigned st = sb + 40960 + (STG) * 20480;                              \
        unsigned bd = arow * 80 + quad * 16;                                   \
        size_t ob = (size_t)arow * KTOT + (K0) + quad * 8;                     \
        cpasync16(st + bd, Bh + ob);                                           \
        cpasync16(st + 10240 + bd, Bl + ob);                                   \
    }
#define DEC_LDGA(K0)                                                           \
    {                                                                          \
        const float4* pp = (const float4*)(PQ + prow + (K0) + quad * 8);       \
        const float4* qq = (const float4*)(PQ + qrow + (K0) + quad * 8);       \
        pa[0] = __ldg(pp); pa[1] = __ldg(pp + 1);                              \
        qa[0] = __ldg(qq); qa[1] = __ldg(qq + 1);                              \
    }

    float4 pa[2], qa[2];
    DEC_LDGA(0);
    DEC_LOADB(0, 0);
    asm volatile("cp.async.commit_group;");
    DEC_LOADB(1, 32);
    asm volatile("cp.async.commit_group;");

    for (int c = 0; c < NC; c++) {
        {
            unsigned hi[4], lo[4];
            const float* b1 = bias1 + c * 32 + quad * 8;
#pragma unroll
            for (int j = 0; j < 2; j++) {
                float4 p = pa[j], q = qa[j];
                float4 bb = *(const float4*)(b1 + j * 4);
                float x0 = fmaxf(p.x + q.x + bb.x, 0.f);
                float x1 = fmaxf(p.y + q.y + bb.y, 0.f);
                float x2 = fmaxf(p.z + q.z + bb.z, 0.f);
                float x3 = fmaxf(p.w + q.w + bb.w, 0.f);
                split2(x0, x1, hi[j * 2], lo[j * 2]);
                split2(x2, x3, hi[j * 2 + 1], lo[j * 2 + 1]);
            }
            char* ad = smem + (c & 1) * 20480 + arow * 80 + quad * 16;
            *(uint4*)ad = make_uint4(hi[0], hi[1], hi[2], hi[3]);
            *(uint4*)(ad + 10240) = make_uint4(lo[0], lo[1], lo[2], lo[3]);
        }
        asm volatile("cp.async.wait_group 1;");
        __syncthreads();
        if (c + 1 < NC) DEC_LDGA((c + 1) * 32);
        if (c + 2 < NC) DEC_LOADB((c + 2) % 3, (c + 2) * 32);
        asm volatile("cp.async.commit_group;");

        const unsigned ast = sb + (c & 1) * 20480;
        const unsigned bst = sb + 40960 + (c % 3) * 20480;
#pragma unroll
        for (int ks = 0; ks < 2; ks++) {
            const unsigned koff = ks * 32;
            unsigned ah[2][4], al[2][4];
#pragma unroll
            for (int mf = 0; mf < 2; mf++) {
                unsigned addr = ast + (wm * 32 + mf * 16 + (lane & 15)) * 80 +
                                ((lane >> 4) * 16) + koff;
                ldm4(ah[mf], addr);
                ldm4(al[mf], addr + 10240);
            }
#pragma unroll
            for (int nb = 0; nb < NB; nb++) {
                unsigned addr = bst + (wn * 32 + nb * 16 + (lane & 15)) * 80 +
                                ((lane >> 4) * 16) + koff;
                unsigned bh[4], bl[4];
                ldm4(bh, addr);
                ldm4(bl, addr + 10240);
                unsigned b0h[2] = {bh[0], bh[2]}, b1h[2] = {bh[1], bh[3]};
                unsigned b0l[2] = {bl[0], bl[2]}, b1l[2] = {bl[1], bl[3]};
                float* a0 = acc[0][nb * 2];
                float* a1 = acc[1][nb * 2];
                float* c0 = acc[0][nb * 2 + 1];
                float* c1 = acc[1][nb * 2 + 1];
                MMA_GROUP(a0, a1, c0, c1, ah, al, b0h, b1h, b0l, b1l)
            }
        }
    }
#undef DEC_LOADB
#undef DEC_LDGA

#pragma unroll
    for (int mf = 0; mf < 2; mf++) {
        const int r0 = bm + wm * 32 + mf * 16 + (lane >> 2);
#pragma unroll
        for (int nf = 0; nf < 2 * NB; nf++) {
            const int col = wn * 32 + nf * 8 + (lane & 3) * 2;
#pragma unroll
            for (int hh = 0; hh < 2; hh++) {
                const int row = r0 + hh * 8;
                if (row >= M) continue;
                float2 s = make_float2(acc[mf][nf][hh * 2] + bias2[col],
                                       acc[mf][nf][hh * 2 + 1] + bias2[col + 1]);
                *(float2*)(Cf + (size_t)row * OUTD + col) = s;
            }
        }
    }
}

// ---------------- CSR build ----------------
__global__ void k_zerodeg(int Nn) {
    int i = blockIdx.x * blockDim.x + threadIdx.x;
    if (i < Nn) g_deg[i] = 0;
}
__global__ void k_deg(const int* __restrict__ u, const int* __restrict__ v, int E) {
    int e = blockIdx.x * blockDim.x + threadIdx.x;
    if (e >= E) return;
    atomicAdd(&g_deg[u[e]], 1);
    atomicAdd(&g_deg[v[e]], 1);
}
__global__ void k_scan(int Nn) {
    __shared__ int warpsum[32];
    __shared__ int s_carry;
    const int tid = threadIdx.x, lane = tid & 31, w = tid >> 5;
    if (tid == 0) s_carry = 0;
    __syncthreads();
    for (int base = 0; base < Nn; base += 1024) {
        int i = base + tid;
        int v = (i < Nn) ? g_deg[i] : 0;
        int x = v;
#pragma unroll
        for (int o = 1; o < 32; o <<= 1) {
            int t = __shfl_up_sync(0xffffffffu, x, o);
            if (lane >= o) x += t;
        }
        if (lane == 31) warpsum[w] = x;
        __syncthreads();
        if (w == 0) {
            int s = warpsum[lane];
#pragma unroll
            for (int o = 1; o < 32; o <<= 1) {
                int t = __shfl_up_sync(0xffffffffu, s, o);
                if (lane >= o) s += t;
            }
            warpsum[lane] = s;
        }
        __syncthreads();
        int incl = x + (w > 0 ? warpsum[w - 1] : 0) + s_carry;
        if (i < Nn) {
            int excl = incl - v;
            g_off[i] = excl;
            g_cur[i] = excl;
        }
        __syncthreads();
        if (tid == 1023) s_carry = incl;
        __syncthreads();
    }
    if (tid == 0) g_off[Nn] = s_carry;
}
__global__ void k_fill(const int* __restrict__ u, const int* __restrict__ v, int E) {
    int e = blockIdx.x * blockDim.x + threadIdx.x;
    if (e >= E) return;
    int a = u[e], b = v[e];
    int p = atomicAdd(&g_cur[b], 1);
    g_adj[p] = a;
    int q = atomicAdd(&g_cur[a], 1);
    g_adj[q] = b;
}

// ---------------- aggregation: z = 2h + sum_{nb} h[nb]  -> bf16 pairs ----------------
// One warp per half-row (2 warps/node): 2x warps for latency hiding.
// Software-pipelined neighbor loop: next adjacency index + row prefetched
// while the current row is summed.
__global__ void k_agg(int Nn) {
    const int w = threadIdx.x >> 5;               // 0..7
    const int node = blockIdx.x * 4 + (w >> 1);
    if (node >= Nn) return;
    const int lane = threadIdx.x & 31;
    const int cbase = (w & 1) * 64 + lane;        // float4 index in [0,128)

    float4 acc0, acc1;
    {
        const float4* hp = (const float4*)(g_h + (size_t)node * D);
        float4 t0 = hp[cbase], t1 = hp[cbase + 32];
        acc0 = make_float4(2.f * t0.x, 2.f * t0.y, 2.f * t0.z, 2.f * t0.w);
        acc1 = make_float4(2.f * t1.x, 2.f * t1.y, 2.f * t1.z, 2.f * t1.w);
    }
    const int e1 = g_off[node + 1];
    int e = g_off[node];
    if (e < e1) {
        const float4* np = (const float4*)(g_h + (size_t)__ldg(&g_adj[e]) * D);
        float4 c0 = np[cbase], c1 = np[cbase + 32];
        for (++e; e < e1; ++e) {
            const float4* np2 = (const float4*)(g_h + (size_t)__ldg(&g_adj[e]) * D);
            float4 n0 = np2[cbase], n1 = np2[cbase + 32];
            acc0.x += c0.x; acc0.y += c0.y; acc0.z += c0.z; acc0.w += c0.w;
            acc1.x += c1.x; acc1.y += c1.y; acc1.z += c1.z; acc1.w += c1.w;
            c0 = n0; c1 = n1;
        }
        acc0.x += c0.x; acc0.y += c0.y; acc0.z += c0.z; acc0.w += c0.w;
        acc1.x += c1.x; acc1.y += c1.y; acc1.z += c1.z; acc1.w += c1.w;
    }
    {
        unsigned h0, l0, h1, l1;
        split2(acc0.x, acc0.y, h0, l0);
        split2(acc0.z, acc0.w, h1, l1);
        size_t o = (size_t)node * D + (size_t)cbase * 4;
        ((unsigned*)(g_zh + o))[0] = h0;
        ((unsigned*)(g_zh + o))[1] = h1;
        ((unsigned*)(g_zl + o))[0] = l0;
        ((unsigned*)(g_zl + o))[1] = l1;
        split2(acc1.x, acc1.y, h0, l0);
        split2(acc1.z, acc1.w, h1, l1);
        o = (size_t)node * D + (size_t)(cbase + 32) * 4;
        ((unsigned*)(g_zh + o))[0] = h0;
        ((unsigned*)(g_zh + o))[1] = h1;
        ((unsigned*)(g_zl + o))[0] = l0;
        ((unsigned*)(g_zl + o))[1] = l1;
    }
}

// ---------------- elementwise kernels ----------------
__global__ void k_gather(const int* __restrict__ ids, const float* __restrict__ emb, int Nn) {
    int idx = blockIdx.x * blockDim.x + threadIdx.x;
    int row = idx >> 7;
    if (row >= Nn) return;
    int c = (idx & 127) << 2;
    float4 val = *(const float4*)(emb + (size_t)ids[row] * D + c);
    *(float4*)(g_h + (size_t)row * D + c) = val;
    *(float4*)(g_hsum + (size_t)row * D + c) = val;
}

// weight transpose+convert: src [K,Nn] -> dst [Nn,K] bf16 pairs
__global__ void k_tcvt(const float* __restrict__ B, __nv_bfloat16* __restrict__ H,
                       __nv_bfloat16* __restrict__ Lo, int K, int Nn) {
    int idx = blockIdx.x * blockDim.x + threadIdx.x;
    if (idx >= K * Nn) return;
    int n = idx / K, k = idx - n * K;
    float x = B[(size_t)k * Nn + n];
    __nv_bfloat16 h, l;
    f2pair(x, h, l);
    H[idx] = h; Lo[idx] = l;
}

// weight transpose+convert to single fp16: src [K,Nn] -> dst [Nn,K]
__global__ void k_tcvt16(const float* __restrict__ B, __half* __restrict__ H, int K, int Nn) {
    int idx = blockIdx.x * blockDim.x + threadIdx.x;
    if (idx >= K * Nn) return;
    int n = idx / K, k = idx - n * K;
    H[idx] = __float2half(B[(size_t)k * Nn + n]);
}

__global__ void k_bnzero2() {
    int t = blockIdx.x * blockDim.x + threadIdx.x;
    if (t < 2048) g_stats[t] = 0.f;
}

// h = relu(affine(Y2)); hsum += h ; aff computed in-block from stats slot
// LAST=0: write h fp32 + hsum fp32.  LAST=1: write (hsum+h) as fp16 pairs only.
template <int LAST>
__global__ void k_bnrelu_acc(const float* __restrict__ Y2,
                             const float* __restrict__ stats,
                             const float* __restrict__ gamma,
                             const float* __restrict__ beta, int Nn) {
    __shared__ float s_aff[1024];
    int tid = threadIdx.x;
    {
        float inv = 1.f / (float)Nn;
#pragma unroll
        for (int j = tid; j < 512; j += 256) {
            float m = stats[j] * inv;
            float var = stats[512 + j] * inv - m * m;
            float sc = gamma[j] * rsqrtf(var + BN_EPS);
            s_aff[j] = sc;
            s_aff[512 + j] = beta[j] - m * sc;
        }
    }
    __syncthreads();
    int idx = blockIdx.x * blockDim.x + tid;
    if (idx >= Nn * 128) return;
    int c = (idx & 127) << 2;
    float4 v = *(const float4*)(Y2 + (size_t)idx * 4);
    v.x = fmaxf(v.x * s_aff[c + 0] + s_aff[512 + c + 0], 0.f);
    v.y = fmaxf(v.y * s_aff[c + 1] + s_aff[512 + c + 1], 0.f);
    v.z = fmaxf(v.z * s_aff[c + 2] + s_aff[512 + c + 2], 0.f);
    v.w = fmaxf(v.w * s_aff[c + 3] + s_aff[512 + c + 3], 0.f);
    float4 hs = *(const float4*)(g_hsum + (size_t)idx * 4);
    hs.x += v.x; hs.y += v.y; hs.z += v.z; hs.w += v.w;
    if (!LAST) {
        *(float4*)(g_h + (size_t)idx * 4) = v;
        *(float4*)(g_hsum + (size_t)idx * 4) = hs;
    } else {
        unsigned h0, l0, h1, l1;
        split2h(hs.x, hs.y, h0, l0);
        split2h(hs.z, hs.w, h1, l1);
        ((unsigned*)(g_hsfh + (size_t)idx * 4))[0] = h0;
        ((unsigned*)(g_hsfh + (size_t)idx * 4))[1] = h1;
        ((unsigned*)(g_hsfl + (size_t)idx * 4))[0] = l0;
        ((unsigned*)(g_hsfl + (size_t)idx * 4))[1] = l1;
    }
}

// ---------------- launch ----------------
extern "C" void kernel_launch(void* const* d_in, const int* in_sizes, int n_in,
                              void* d_out, int out_size) {
    const int* h_ids = (const int*)d_in[0];
    const int* u     = (const int*)d_in[1];
    const int* v     = (const int*)d_in[2];
    const float* emb   = (const float*)d_in[3];
    const float* lin1  = (const float*)d_in[4];
    const float* lin2  = (const float*)d_in[5];
    const float* bn1_g = (const float*)d_in[6];
    const float* bn1_b = (const float*)d_in[7];
    const float* bn2_g = (const float*)d_in[8];
    const float* bn2_b = (const float*)d_in[9];
    const float* W1_w  = (const float*)d_in[10];
    const float* W1_b  = (const float*)d_in[11];
    const float* W2_w  = (const float*)d_in[12];
    const float* W2_b  = (const float*)d_in[13];
    float* out = (float*)d_out;

    const int N = in_sizes[0];
    const int E = in_sizes[1];
    const int L = in_sizes[4] / (D * D);

    const int SMEM_256 = (20480 + 256 * 160) * NSTAGE;  // 184320

    static int s_attr = 0;
    if (!s_attr) {
        cudaFuncSetAttribute(k_mma<512, 256, 1>, cudaFuncAttributeMaxDynamicSharedMemorySize, SMEM_256);
        cudaFuncSetAttribute(k_mma_pq, cudaFuncAttributeMaxDynamicSharedMemorySize, PQ_SMEM);
        cudaFuncSetAttribute(k_mma_bn, cudaFuncAttributeMaxDynamicSharedMemorySize, BNG_SMEM);
        cudaFuncSetAttribute(k_dec, cudaFuncAttributeMaxDynamicSharedMemorySize, DEC_SMEM);
        s_attr = 1;
    }

    float *dg_z, *dg_y, *dg_pq, *dg_stats;
    cudaGetSymbolAddress((void**)&dg_z, g_z);
    cudaGetSymbolAddress((void**)&dg_y, g_y);
    cudaGetSymbolAddress((void**)&dg_pq, g_pq);
    cudaGetSymbolAddress((void**)&dg_stats, g_stats);
    __nv_bfloat16 *zh, *zl;
    __nv_bfloat16 *l1th, *l1tl, *l2th, *l2tl, *w2th, *w2tl;
    __half *hsfh, *hsfl, *w1f;
    cudaGetSymbolAddress((void**)&zh, g_zh);  cudaGetSymbolAddress((void**)&zl, g_zl);
    cudaGetSymbolAddress((void**)&hsfh, g_hsfh); cudaGetSymbolAddress((void**)&hsfl, g_hsfl);
    cudaGetSymbolAddress((void**)&l1th, g_l1th); cudaGetSymbolAddress((void**)&l1tl, g_l1tl);
    cudaGetSymbolAddress((void**)&l2th, g_l2th); cudaGetSymbolAddress((void**)&l2tl, g_l2tl);
    cudaGetSymbolAddress((void**)&w1f, g_w1f);
    cudaGetSymbolAddress((void**)&w2th, g_w2th); cudaGetSymbolAddress((void**)&w2tl, g_w2tl);

    const int ew = N * 128, ewB = (ew + 255) / 256;
    const int mtiles = (N + 127) / 128;
    const int etiles = (E + 127) / 128;
    const int edB = (E + 255) / 256;
    const int ndB = (N + 255) / 256;
    const int aggB = (N + 3) / 4;

    // weight conversion (transpose + split)
    const int wB = (D * D + 255) / 256;
    for (int i = 0; i < L; i++) {
        k_tcvt<<<wB, 256>>>(lin1 + (size_t)i * D * D, l1th + (size_t)i * D * D, l1tl + (size_t)i * D * D, D, D);
        k_tcvt<<<wB, 256>>>(lin2 + (size_t)i * D * D, l2th + (size_t)i * D * D, l2tl + (size_t)i * D * D, D, D);
    }
    // W1 halves -> transposed single fp16: rows 0..511 = W1a^T, rows 512..1023 = W1b^T
    k_tcvt16<<<wB, 256>>>(W1_w, w1f, D, D);
    k_tcvt16<<<wB, 256>>>(W1_w + (size_t)D * D, w1f + (size_t)D * D, D, D);
    k_tcvt<<<(D * OUTD + 255) / 256, 256>>>(W2_w, w2th, w2tl, D, OUTD);

    // h = emb[h_ids]; hidden_sum = h
    k_gather<<<ewB, 256>>>(h_ids, emb, N);

    // CSR build (once)
    k_zerodeg<<<ndB, 256>>>(N);
    k_deg<<<edB, 256>>>(u, v, E);
    k_scan<<<1, 1024>>>(N);
    k_fill<<<edB, 256>>>(u, v, E);

    for (int i = 0; i < L; i++) {
        // z = 2h + neighbor sums -> bf16 pairs ; zero both stats slots
        k_agg<<<aggB, 256>>>(N);
        k_bnzero2<<<2, 1024>>>();
        // y = z @ lin1[i]  (stats -> slot0)
        k_mma<512, 256, 1><<<dim3(mtiles, 2), 512, SMEM_256>>>(
            zh, zl, l1th + (size_t)i * D * D, l1tl + (size_t)i * D * D,
            dg_y, N, D, dg_stats);
        // z(out) = relu(bn1(y)) @ lin2[i]  (fused BN loader; stats -> slot1)
        k_mma_bn<<<dim3(mtiles, 2), 512, BNG_SMEM>>>(
            dg_y, l2th + (size_t)i * D * D, l2tl + (size_t)i * D * D,
            dg_z, N,
            dg_stats, bn1_g + (size_t)i * D, bn1_b + (size_t)i * D,
            dg_stats + 1024);
        // h = relu(bn2(z)); hsum += h  (aff computed in-block from slot1)
        if (i == L - 1)
            k_bnrelu_acc<1><<<ewB, 256>>>(dg_z, dg_stats + 1024,
                bn2_g + (size_t)i * D, bn2_b + (size_t)i * D, N);
        else
            k_bnrelu_acc<0><<<ewB, 256>>>(dg_z, dg_stats + 1024,
                bn2_g + (size_t)i * D, bn2_b + (size_t)i * D, N);
    }

    // decoder: [P|Q] = hsum_fp16pairs @ fp16(W1t)^T  (2-pass fp16, Nout=1024)
    k_mma_pq<<<dim3(mtiles, 4), 512, PQ_SMEM>>>(
        hsfh, hsfl, w1f, dg_pq, N, 2 * D);
    // out = relu(P[u]+Q[v]+b1) @ W2^T + b2  (fused edge loader, 3-term bf16)
    k_dec<<<etiles, 512, DEC_SMEM>>>(dg_pq, w2th, w2tl, out, E, u, v, W1_b, W2_b);
}

// round 13
// speedup vs baseline: 3.4247x; 1.0648x over previous
#include <cuda_runtime.h>
#include <cuda_bf16.h>
#include <cuda_fp16.h>

#define D 512
#define OUTD 128
#define MAXN 50000
#define MAXE 150000
#define BN_EPS 1e-5f

// ---------------- scratch (static device globals; no allocation) ----------------
__device__ __half g_h[(size_t)MAXN * D];    // current node features (fp16)
__device__ float g_hsum[(size_t)MAXN * D];  // hidden_sum accumulator (fp32)
__device__ float g_y[(size_t)MAXN * D];     // gemm1 output
__device__ float g_z[(size_t)MAXN * D];     // gemm2 output
__device__ float g_pq[(size_t)MAXN * 2 * D];// decoder P|Q concat
__device__ float g_stats[2 * 1024];         // slot0: GEMM1 (sum,sumsq), slot1: GEMM2

// CSR graph
__device__ int g_deg[MAXN];
__device__ int g_off[MAXN + 1];
__device__ int g_cur[MAXN];
__device__ int g_adj[2 * MAXE];

// bf16 split pairs (layer path)
__device__ __nv_bfloat16 g_zh[(size_t)MAXN * D], g_zl[(size_t)MAXN * D];
// fp16 split pairs (decoder PQ path)
__device__ __half g_hsfh[(size_t)MAXN * D], g_hsfl[(size_t)MAXN * D];
// transposed + split weights: Bt[n][k]
__device__ __nv_bfloat16 g_l1th[(size_t)4 * D * D], g_l1tl[(size_t)4 * D * D];
__device__ __nv_bfloat16 g_l2th[(size_t)4 * D * D], g_l2tl[(size_t)4 * D * D];
__device__ __half g_w1f[(size_t)D * 2 * D];   // fp16 single, [a|b] rows
__device__ __half g_w2f[(size_t)OUTD * D];    // fp16 single

// ---------------- PTX helpers (plain compute_100-legal) ----------------
__device__ __forceinline__ unsigned smem_u32(const void* p) {
    unsigned a;
    asm("{ .reg .u64 t; cvta.to.shared.u64 t, %1; cvt.u32.u64 %0, t; }" : "=r"(a) : "l"(p));
    return a;
}
__device__ __forceinline__ void cpasync16(unsigned dst, const void* src) {
    asm volatile("cp.async.cg.shared.global [%0], [%1], 16;" ::"r"(dst), "l"(src));
}
__device__ __forceinline__ void ldm4(unsigned* r, unsigned addr) {
    asm volatile("ldmatrix.sync.aligned.m8n8.x4.shared.b16 {%0,%1,%2,%3}, [%4];"
                 : "=r"(r[0]), "=r"(r[1]), "=r"(r[2]), "=r"(r[3]) : "r"(addr));
}
__device__ __forceinline__ void mma16816(float* c, const unsigned* a, const unsigned* b) {
    asm volatile(
        "mma.sync.aligned.m16n8k16.row.col.f32.bf16.bf16.f32 "
        "{%0,%1,%2,%3}, {%4,%5,%6,%7}, {%8,%9}, {%0,%1,%2,%3};"
        : "+f"(c[0]), "+f"(c[1]), "+f"(c[2]), "+f"(c[3])
        : "r"(a[0]), "r"(a[1]), "r"(a[2]), "r"(a[3]), "r"(b[0]), "r"(b[1]));
}
__device__ __forceinline__ void mma16816h(float* c, const unsigned* a, const unsigned* b) {
    asm volatile(
        "mma.sync.aligned.m16n8k16.row.col.f32.f16.f16.f32 "
        "{%0,%1,%2,%3}, {%4,%5,%6,%7}, {%8,%9}, {%0,%1,%2,%3};"
        : "+f"(c[0]), "+f"(c[1]), "+f"(c[2]), "+f"(c[3])
        : "r"(a[0]), "r"(a[1]), "r"(a[2]), "r"(a[3]), "r"(b[0]), "r"(b[1]));
}
__device__ __forceinline__ void f2pair(float v, __nv_bfloat16& h, __nv_bfloat16& l) {
    h = __float2bfloat16(v);
    l = __float2bfloat16(v - __bfloat162float(h));
}
__device__ __forceinline__ void split2(float a, float b, unsigned& hi, unsigned& lo) {
    __nv_bfloat16 h0, l0, h1, l1;
    f2pair(a, h0, l0);
    f2pair(b, h1, l1);
    __nv_bfloat162 hp; hp.x = h0; hp.y = h1;
    __nv_bfloat162 lp; lp.x = l0; lp.y = l1;
    hi = *(unsigned*)&hp;
    lo = *(unsigned*)&lp;
}
__device__ __forceinline__ void split2h(float a, float b, unsigned& hi, unsigned& lo) {
    __half h0 = __float2half(a);
    __half l0 = __float2half(a - __half2float(h0));
    __half h1 = __float2half(b);
    __half l1 = __float2half(b - __half2float(h1));
    __half2 hp; hp.x = h0; hp.y = h1;
    __half2 lp; lp.x = l0; lp.y = l1;
    hi = *(unsigned*)&hp;
    lo = *(unsigned*)&lp;
}
__device__ __forceinline__ unsigned pack2h(float a, float b) {
    __half2 p; p.x = __float2half(a); p.y = __float2half(b);
    return *(unsigned*)&p;
}

// 12 mma for one nb-block, accumulator reuse distance >= 3
#define MMA_GROUP(A0, A1, C0, C1, AH, AL, B0H, B1H, B0L, B1L)                  \
    mma16816(A0, AH[0], B0H); mma16816(A1, AH[1], B0H);                        \
    mma16816(C0, AH[0], B1H); mma16816(C1, AH[1], B1H);                        \
    mma16816(A0, AH[0], B0L); mma16816(A1, AH[1], B0L);                        \
    mma16816(C0, AH[0], B1L); mma16816(C1, AH[1], B1L);                        \
    mma16816(A0, AL[0], B0H); mma16816(A1, AL[1], B0H);                        \
    mma16816(C0, AL[0], B1H); mma16816(C1, AL[1], B1H);

#define EPILOGUE_STORE(BN_, NOUT_)                                             \
    _Pragma("unroll") for (int mf = 0; mf < 2; mf++) {                         \
        const int r0 = bm + wm * 32 + mf * 16 + (lane >> 2);                   \
        _Pragma("unroll") for (int nf = 0; nf < 2 * ((BN_) / 64); nf++) {      \
            const int col = bn + wn * ((BN_) / 4) + nf * 8 + (lane & 3) * 2;   \
            const float* a = acc[mf][nf];                                      \
            _Pragma("unroll") for (int hh = 0; hh < 2; hh++) {                 \
                const int row = r0 + hh * 8;                                   \
                if (row >= M) continue;                                        \
                float2 s = make_float2(a[hh * 2], a[hh * 2 + 1]);              \
                *(float2*)(Cf + (size_t)row * (NOUT_) + col) = s;              \
            }                                                                  \
        }                                                                      \
    }

#define EPILOGUE_STATS(BN_)                                                    \
    _Pragma("unroll") for (int nf = 0; nf < 2 * ((BN_) / 64); nf++) {          \
        float s0 = 0.f, s1 = 0.f, q0 = 0.f, q1 = 0.f;                          \
        _Pragma("unroll") for (int mf = 0; mf < 2; mf++) {                     \
            const int rb = bm + wm * 32 + mf * 16 + (lane >> 2);               \
            _Pragma("unroll") for (int hh = 0; hh < 2; hh++) {                 \
                if (rb + hh * 8 < M) {                                         \
                    float v0 = acc[mf][nf][hh * 2], v1 = acc[mf][nf][hh * 2 + 1];\
                    s0 += v0; q0 += v0 * v0;                                   \
                    s1 += v1; q1 += v1 * v1;                                   \
                }                                                              \
            }                                                                  \
        }                                                                      \
        _Pragma("unroll") for (int o = 4; o < 32; o <<= 1) {                   \
            s0 += __shfl_xor_sync(0xffffffffu, s0, o);                         \
            s1 += __shfl_xor_sync(0xffffffffu, s1, o);                         \
            q0 += __shfl_xor_sync(0xffffffffu, q0, o);                         \
            q1 += __shfl_xor_sync(0xffffffffu, q1, o);                         \
        }                                                                      \
        if ((lane >> 2) == 0) {                                                \
            int col = bn + wn * ((BN_) / 4) + nf * 8 + (lane & 3) * 2;         \
            atomicAdd(&stats_out[col], s0);                                    \
            atomicAdd(&stats_out[col + 1], s1);                                \
            atomicAdd(&stats_out[512 + col], q0);                              \
            atomicAdd(&stats_out[512 + col + 1], q1);                          \
        }                                                                      \
    }

#define ACC_INIT(NB_)                                                          \
    float acc[2][2 * (NB_)][4];                                                \
    _Pragma("unroll") for (int i = 0; i < 2; i++)                              \
        _Pragma("unroll") for (int j = 0; j < 2 * (NB_); j++)                  \
            _Pragma("unroll") for (int q = 0; q < 4; q++) acc[i][j][q] = 0.f;

// ---------------- mma.sync split-bf16 GEMM (pair inputs) ----------------
#define NSTAGE 3

template <int KTOT, int BN, int STATS>
__global__ __launch_bounds__(512)
void k_mma(const __nv_bfloat16* __restrict__ Ah, const __nv_bfloat16* __restrict__ Al,
           const __nv_bfloat16* __restrict__ Bh, const __nv_bfloat16* __restrict__ Bl,
           float* __restrict__ Cf, int M, int Nout, float* __restrict__ stats_out) {
    constexpr int NB = BN / 64;
    constexpr int O_AL = 10240;
    constexpr int O_BH = 20480;
    constexpr int O_BL = 20480 + BN * 80;
    constexpr int STAGE_BYTES = 20480 + BN * 160;

    extern __shared__ __align__(16) char smem[];
    const int tid = threadIdx.x;
    const int wid = tid >> 5, lane = tid & 31;
    const int wm = wid & 3, wn = wid >> 2;
    const int bm = blockIdx.x * 128, bn = blockIdx.y * BN;
    const unsigned sb = smem_u32(smem);

    const int arow = tid >> 2, quad = tid & 3;
    const int grA = min(bm + arow, M - 1);

    ACC_INIT(NB)

#define LOAD_CHUNK(STG, K0)                                                    \
    {                                                                          \
        unsigned st = sb + (STG) * STAGE_BYTES;                                \
        unsigned dsto = arow * 80 + quad * 16;                                 \
        size_t o = (size_t)grA * KTOT + (K0) + quad * 8;                       \
        cpasync16(st + dsto, Ah + o);                                          \
        cpasync16(st + O_AL + dsto, Al + o);                                   \
        _Pragma("unroll") for (int i = 0; i < BN / 128; i++) {                 \
            int brow = arow + i * 128;                                         \
            unsigned bd = brow * 80 + quad * 16;                               \
            size_t ob = (size_t)(bn + brow) * KTOT + (K0) + quad * 8;          \
            cpasync16(st + O_BH + bd, Bh + ob);                                \
            cpasync16(st + O_BL + bd, Bl + ob);                                \
        }                                                                      \
    }

    const int NC = KTOT / 32;
#pragma unroll
    for (int p = 0; p < NSTAGE - 1; p++) {
        if (p < NC) LOAD_CHUNK(p, p * 32);
        asm volatile("cp.async.commit_group;");
    }

    int cstg = 0, lstg = NSTAGE - 1;
    for (int c = 0; c < NC; c++) {
        asm volatile("cp.async.wait_group %0;" ::"n"(NSTAGE - 2));
        __syncthreads();
        if (c + NSTAGE - 1 < NC) LOAD_CHUNK(lstg, (c + NSTAGE - 1) * 32);
        asm volatile("cp.async.commit_group;");
        lstg = (lstg + 1 == NSTAGE) ? 0 : lstg + 1;

        const unsigned st = sb + cstg * STAGE_BYTES;
        cstg = (cstg + 1 == NSTAGE) ? 0 : cstg + 1;
#pragma unroll
        for (int ks = 0; ks < 2; ks++) {
            const unsigned koff = ks * 32;
            unsigned ah[2][4], al[2][4];
#pragma unroll
            for (int mf = 0; mf < 2; mf++) {
                unsigned addr = st + (wm * 32 + mf * 16 + (lane & 15)) * 80 +
                                ((lane >> 4) * 16) + koff;
                ldm4(ah[mf], addr);
                ldm4(al[mf], addr + O_AL);
            }
#pragma unroll
            for (int nb = 0; nb < NB; nb++) {
                unsigned addr = st + O_BH +
                                (wn * (BN / 4) + nb * 16 + (lane & 15)) * 80 +
                                ((lane >> 4) * 16) + koff;
                unsigned bh[4], bl[4];
                ldm4(bh, addr);
                ldm4(bl, addr + BN * 80);
                unsigned b0h[2] = {bh[0], bh[2]}, b1h[2] = {bh[1], bh[3]};
                unsigned b0l[2] = {bl[0], bl[2]}, b1l[2] = {bl[1], bl[3]};
                float* a0 = acc[0][nb * 2];
                float* a1 = acc[1][nb * 2];
                float* c0 = acc[0][nb * 2 + 1];
                float* c1 = acc[1][nb * 2 + 1];
                MMA_GROUP(a0, a1, c0, c1, ah, al, b0h, b1h, b0l, b1l)
            }
        }
    }
#undef LOAD_CHUNK

    EPILOGUE_STORE(BN, Nout)
    if (STATS) { EPILOGUE_STATS(BN) }
}

// ---------------- PQ GEMM: 2-pass fp16 (A hi+lo fp16, B single fp16) ----------------
#define PQ_SMEM (3 * 40960)  // 122880

__global__ __launch_bounds__(512)
void k_mma_pq(const __half* __restrict__ Ah, const __half* __restrict__ Al,
              const __half* __restrict__ Bf,
              float* __restrict__ Cf, int M, int Nout) {
    constexpr int KTOT = 512, BN = 256, NB = 4, NC = 16;
    constexpr int O_AL = 10240, O_B = 20480, STAGE_BYTES = 40960;

    extern __shared__ __align__(16) char smem[];
    const int tid = threadIdx.x;
    const int wid = tid >> 5, lane = tid & 31;
    const int wm = wid & 3, wn = wid >> 2;
    const int bm = blockIdx.x * 128, bn = blockIdx.y * BN;
    const unsigned sb = smem_u32(smem);

    const int arow = tid >> 2, quad = tid & 3;
    const int grA = min(bm + arow, M - 1);

    ACC_INIT(NB)

#define PQ_LOAD(STG, K0)                                                       \
    {                                                                          \
        unsigned st = sb + (STG) * STAGE_BYTES;                                \
        unsigned dsto = arow * 80 + quad * 16;                                 \
        size_t o = (size_t)grA * KTOT + (K0) + quad * 8;                       \
        cpasync16(st + dsto, Ah + o);                                          \
        cpasync16(st + O_AL + dsto, Al + o);                                   \
        _Pragma("unroll") for (int i = 0; i < 2; i++) {                        \
            int brow = arow + i * 128;                                         \
            unsigned bd = brow * 80 + quad * 16;                               \
            size_t ob = (size_t)(bn + brow) * KTOT + (K0) + quad * 8;          \
            cpasync16(st + O_B + bd, Bf + ob);                                 \
        }                                                                      \
    }

#pragma unroll
    for (int p = 0; p < NSTAGE - 1; p++) {
        if (p < NC) PQ_LOAD(p, p * 32);
        asm volatile("cp.async.commit_group;");
    }

    int cstg = 0, lstg = NSTAGE - 1;
    for (int c = 0; c < NC; c++) {
        asm volatile("cp.async.wait_group %0;" ::"n"(NSTAGE - 2));
        __syncthreads();
        if (c + NSTAGE - 1 < NC) PQ_LOAD(lstg, (c + NSTAGE - 1) * 32);
        asm volatile("cp.async.commit_group;");
        lstg = (lstg + 1 == NSTAGE) ? 0 : lstg + 1;

        const unsigned st = sb + cstg * STAGE_BYTES;
        cstg = (cstg + 1 == NSTAGE) ? 0 : cstg + 1;
#pragma unroll
        for (int ks = 0; ks < 2; ks++) {
            const unsigned koff = ks * 32;
            unsigned ah[2][4], al[2][4];
#pragma unroll
            for (int mf = 0; mf < 2; mf++) {
                unsigned addr = st + (wm * 32 + mf * 16 + (lane & 15)) * 80 +
                                ((lane >> 4) * 16) + koff;
                ldm4(ah[mf], addr);
                ldm4(al[mf], addr + O_AL);
            }
#pragma unroll
            for (int nb = 0; nb < NB; nb++) {
                unsigned addr = st + O_B +
                                (wn * 64 + nb * 16 + (lane & 15)) * 80 +
                                ((lane >> 4) * 16) + koff;
                unsigned bb[4];
                ldm4(bb, addr);
                unsigned b0[2] = {bb[0], bb[2]}, b1[2] = {bb[1], bb[3]};
                float* a0 = acc[0][nb * 2];
                float* a1 = acc[1][nb * 2];
                float* c0 = acc[0][nb * 2 + 1];
                float* c1 = acc[1][nb * 2 + 1];
                mma16816h(a0, ah[0], b0); mma16816h(a1, ah[1], b0);
                mma16816h(c0, ah[0], b1); mma16816h(c1, ah[1], b1);
                mma16816h(a0, al[0], b0); mma16816h(a1, al[1], b0);
                mma16816h(c0, al[0], b1); mma16816h(c1, al[1], b1);
            }
        }
    }
#undef PQ_LOAD

    EPILOGUE_STORE(256, Nout)
}

// ---------------- GEMM2: fused BN-apply loader ----------------
#define BNG_SMEM (2 * 20480 + 3 * 40960 + 4096)  // 167936

__global__ __launch_bounds__(512)
void k_mma_bn(const float* __restrict__ Y,
              const __nv_bfloat16* __restrict__ Bh, const __nv_bfloat16* __restrict__ Bl,
              float* __restrict__ Cf, int M,
              const float* __restrict__ stats_in, const float* __restrict__ gamma,
              const float* __restrict__ beta, float* __restrict__ stats_out) {
    constexpr int KTOT = 512, BN = 256, NB = 4, NC = 16;
    constexpr int O_B = 40960;
    constexpr int O_AFF = 163840;
    extern __shared__ __align__(16) char smem[];
    float* s_aff = (float*)(smem + O_AFF);
    const int tid = threadIdx.x;
    const int wid = tid >> 5, lane = tid & 31;
    const int wm = wid & 3, wn = wid >> 2;
    const int bm = blockIdx.x * 128, bn = blockIdx.y * BN;
    const unsigned sb = smem_u32(smem);

    if (tid < 512) {
        float inv = 1.f / (float)M;
        float m = stats_in[tid] * inv;
        float var = stats_in[512 + tid] * inv - m * m;
        float sc = gamma[tid] * rsqrtf(var + BN_EPS);
        s_aff[tid] = sc;
        s_aff[512 + tid] = beta[tid] - m * sc;
    }

    const int arow = tid >> 2, quad = tid & 3;
    const int grA = min(bm + arow, M - 1);

    ACC_INIT(NB)

#define BNG_LOADB(STG, K0)                                                     \
    {                                                                          \
        unsigned st = sb + O_B + (STG) * 40960;                                \
        _Pragma("unroll") for (int i = 0; i < 2; i++) {                        \
            int brow = arow + i * 128;                                         \
            unsigned bd = brow * 80 + quad * 16;                               \
            size_t ob = (size_t)(bn + brow) * KTOT + (K0) + quad * 8;          \
            cpasync16(st + bd, Bh + ob);                                       \
            cpasync16(st + 20480 + bd, Bl + ob);                               \
        }                                                                      \
    }
#define BNG_LDGA(K0)                                                           \
    {                                                                          \
        const float4* yp = (const float4*)(Y + (size_t)grA * KTOT + (K0) + quad * 8);\
        ya[0] = __ldg(yp); ya[1] = __ldg(yp + 1);                              \
    }

    float4 ya[2];
    BNG_LDGA(0);
    BNG_LOADB(0, 0);
    asm volatile("cp.async.commit_group;");
    BNG_LOADB(1, 32);
    asm volatile("cp.async.commit_group;");
    __syncthreads();  // s_aff visible

    for (int c = 0; c < NC; c++) {
        {
            unsigned hi[4], lo[4];
            const int kb = c * 32 + quad * 8;
#pragma unroll
            for (int j = 0; j < 2; j++) {
                float4 y = ya[j];
                const int k = kb + j * 4;
                float x0 = fmaxf(y.x * s_aff[k + 0] + s_aff[512 + k + 0], 0.f);
                float x1 = fmaxf(y.y * s_aff[k + 1] + s_aff[512 + k + 1], 0.f);
                float x2 = fmaxf(y.z * s_aff[k + 2] + s_aff[512 + k + 2], 0.f);
                float x3 = fmaxf(y.w * s_aff[k + 3] + s_aff[512 + k + 3], 0.f);
                split2(x0, x1, hi[j * 2], lo[j * 2]);
                split2(x2, x3, hi[j * 2 + 1], lo[j * 2 + 1]);
            }
            char* ad = smem + (c & 1) * 20480 + arow * 80 + quad * 16;
            *(uint4*)ad = make_uint4(hi[0], hi[1], hi[2], hi[3]);
            *(uint4*)(ad + 10240) = make_uint4(lo[0], lo[1], lo[2], lo[3]);
        }
        asm volatile("cp.async.wait_group 1;");
        __syncthreads();
        if (c + 1 < NC) BNG_LDGA((c + 1) * 32);
        if (c + 2 < NC) BNG_LOADB((c + 2) % 3, (c + 2) * 32);
        asm volatile("cp.async.commit_group;");

        const unsigned ast = sb + (c & 1) * 20480;
        const unsigned bst = sb + O_B + (c % 3) * 40960;
#pragma unroll
        for (int ks = 0; ks < 2; ks++) {
            const unsigned koff = ks * 32;
            unsigned ah[2][4], al[2][4];
#pragma unroll
            for (int mf = 0; mf < 2; mf++) {
                unsigned addr = ast + (wm * 32 + mf * 16 + (lane & 15)) * 80 +
                                ((lane >> 4) * 16) + koff;
                ldm4(ah[mf], addr);
                ldm4(al[mf], addr + 10240);
            }
#pragma unroll
            for (int nb = 0; nb < NB; nb++) {
                unsigned addr = bst + (wn * 64 + nb * 16 + (lane & 15)) * 80 +
                                ((lane >> 4) * 16) + koff;
                unsigned bh[4], bl[4];
                ldm4(bh, addr);
                ldm4(bl, addr + 20480);
                unsigned b0h[2] = {bh[0], bh[2]}, b1h[2] = {bh[1], bh[3]};
                unsigned b0l[2] = {bl[0], bl[2]}, b1l[2] = {bl[1], bl[3]};
                float* a0 = acc[0][nb * 2];
                float* a1 = acc[1][nb * 2];
                float* c0 = acc[0][nb * 2 + 1];
                float* c1 = acc[1][nb * 2 + 1];
                MMA_GROUP(a0, a1, c0, c1, ah, al, b0h, b1h, b0l, b1l)
            }
        }
    }
#undef BNG_LOADB
#undef BNG_LDGA

    const int Nout = 512;
    EPILOGUE_STORE(256, Nout)
    EPILOGUE_STATS(256)
}

// ---------------- decoder final GEMM: fused edge loader, 2-pass fp16 ----------------
// A: 2 stages x 20480 (hi at +0, lo at +10240). B: 3 stages x 10240 at +40960.
#define DEC_SMEM (2 * 20480 + 3 * 10240)  // 71680

__global__ __launch_bounds__(512)
void k_dec(const float* __restrict__ PQ,
           const __half* __restrict__ Bf,
           float* __restrict__ Cf, int M,
           const int* __restrict__ gu, const int* __restrict__ gv,
           const float* __restrict__ bias1, const float* __restrict__ bias2) {
    constexpr int KTOT = 512, NB = 2, NC = 16;
    extern __shared__ __align__(16) char smem[];
    __shared__ int s_u[128], s_v[128];
    const int tid = threadIdx.x;
    const int wid = tid >> 5, lane = tid & 31;
    const int wm = wid & 3, wn = wid >> 2;
    const int bm = blockIdx.x * 128;
    const unsigned sb = smem_u32(smem);

    if (tid < 128) {
        int e = min(bm + tid, M - 1);
        s_u[tid] = gu[e];
        s_v[tid] = gv[e];
    }
    __syncthreads();

    const int arow = tid >> 2, quad = tid & 3;
    const size_t prow = (size_t)s_u[arow] * 1024;
    const size_t qrow = (size_t)s_v[arow] * 1024 + 512;

    ACC_INIT(NB)

#define DEC_LOADB(STG, K0)                                                     \
    {                                                                          \
        unsigned st = sb + 40960 + (STG) * 10240;                              \
        unsigned bd = arow * 80 + quad * 16;                                   \
        size_t ob = (size_t)arow * KTOT + (K0) + quad * 8;                     \
        cpasync16(st + bd, Bf + ob);                                           \
    }
#define DEC_LDGA(K0)                                                           \
    {                                                                          \
        const float4* pp = (const float4*)(PQ + prow + (K0) + quad * 8);       \
        const float4* qq = (const float4*)(PQ + qrow + (K0) + quad * 8);       \
        pa[0] = __ldg(pp); pa[1] = __ldg(pp + 1);                              \
        qa[0] = __ldg(qq); qa[1] = __ldg(qq + 1);                              \
    }

    float4 pa[2], qa[2];
    DEC_LDGA(0);
    DEC_LOADB(0, 0);
    asm volatile("cp.async.commit_group;");
    DEC_LOADB(1, 32);
    asm volatile("cp.async.commit_group;");

    for (int c = 0; c < NC; c++) {
        {
            unsigned hi[4], lo[4];
            const float* b1 = bias1 + c * 32 + quad * 8;
#pragma unroll
            for (int j = 0; j < 2; j++) {
                float4 p = pa[j], q = qa[j];
                float4 bb = *(const float4*)(b1 + j * 4);
                float x0 = fmaxf(p.x + q.x + bb.x, 0.f);
                float x1 = fmaxf(p.y + q.y + bb.y, 0.f);
                float x2 = fmaxf(p.z + q.z + bb.z, 0.f);
                float x3 = fmaxf(p.w + q.w + bb.w, 0.f);
                split2h(x0, x1, hi[j * 2], lo[j * 2]);
                split2h(x2, x3, hi[j * 2 + 1], lo[j * 2 + 1]);
            }
            char* ad = smem + (c & 1) * 20480 + arow * 80 + quad * 16;
            *(uint4*)ad = make_uint4(hi[0], hi[1], hi[2], hi[3]);
            *(uint4*)(ad + 10240) = make_uint4(lo[0], lo[1], lo[2], lo[3]);
        }
        asm volatile("cp.async.wait_group 1;");
        __syncthreads();
        if (c + 1 < NC) DEC_LDGA((c + 1) * 32);
        if (c + 2 < NC) DEC_LOADB((c + 2) % 3, (c + 2) * 32);
        asm volatile("cp.async.commit_group;");

        const unsigned ast = sb + (c & 1) * 20480;
        const unsigned bst = sb + 40960 + (c % 3) * 10240;
#pragma unroll
        for (int ks = 0; ks < 2; ks++) {
            const unsigned koff = ks * 32;
            unsigned ah[2][4], al[2][4];
#pragma unroll
            for (int mf = 0; mf < 2; mf++) {
                unsigned addr = ast + (wm * 32 + mf * 16 + (lane & 15)) * 80 +
                                ((lane >> 4) * 16) + koff;
                ldm4(ah[mf], addr);
                ldm4(al[mf], addr + 10240);
            }
#pragma unroll
            for (int nb = 0; nb < NB; nb++) {
                unsigned addr = bst + (wn * 32 + nb * 16 + (lane & 15)) * 80 +
                                ((lane >> 4) * 16) + koff;
                unsigned bb[4];
                ldm4(bb, addr);
                unsigned b0[2] = {bb[0], bb[2]}, b1[2] = {bb[1], bb[3]};
                float* a0 = acc[0][nb * 2];
                float* a1 = acc[1][nb * 2];
                float* c0 = acc[0][nb * 2 + 1];
                float* c1 = acc[1][nb * 2 + 1];
                mma16816h(a0, ah[0], b0); mma16816h(a1, ah[1], b0);
                mma16816h(c0, ah[0], b1); mma16816h(c1, ah[1], b1);
                mma16816h(a0, al[0], b0); mma16816h(a1, al[1], b0);
                mma16816h(c0, al[0], b1); mma16816h(c1, al[1], b1);
            }
        }
    }
#undef DEC_LOADB
#undef DEC_LDGA

#pragma unroll
    for (int mf = 0; mf < 2; mf++) {
        const int r0 = bm + wm * 32 + mf * 16 + (lane >> 2);
#pragma unroll
        for (int nf = 0; nf < 2 * NB; nf++) {
            const int col = wn * 32 + nf * 8 + (lane & 3) * 2;
#pragma unroll
            for (int hh = 0; hh < 2; hh++) {
                const int row = r0 + hh * 8;
                if (row >= M) continue;
                float2 s = make_float2(acc[mf][nf][hh * 2] + bias2[col],
                                       acc[mf][nf][hh * 2 + 1] + bias2[col + 1]);
                *(float2*)(Cf + (size_t)row * OUTD + col) = s;
            }
        }
    }
}

// ---------------- CSR build ----------------
__global__ void k_zerodeg(int Nn) {
    int i = blockIdx.x * blockDim.x + threadIdx.x;
    if (i < Nn) g_deg[i] = 0;
}
__global__ void k_deg(const int* __restrict__ u, const int* __restrict__ v, int E) {
    int e = blockIdx.x * blockDim.x + threadIdx.x;
    if (e >= E) return;
    atomicAdd(&g_deg[u[e]], 1);
    atomicAdd(&g_deg[v[e]], 1);
}
__global__ void k_scan(int Nn) {
    __shared__ int warpsum[32];
    __shared__ int s_carry;
    const int tid = threadIdx.x, lane = tid & 31, w = tid >> 5;
    if (tid == 0) s_carry = 0;
    __syncthreads();
    for (int base = 0; base < Nn; base += 1024) {
        int i = base + tid;
        int v = (i < Nn) ? g_deg[i] : 0;
        int x = v;
#pragma unroll
        for (int o = 1; o < 32; o <<= 1) {
            int t = __shfl_up_sync(0xffffffffu, x, o);
            if (lane >= o) x += t;
        }
        if (lane == 31) warpsum[w] = x;
        __syncthreads();
        if (w == 0) {
            int s = warpsum[lane];
#pragma unroll
            for (int o = 1; o < 32; o <<= 1) {
                int t = __shfl_up_sync(0xffffffffu, s, o);
                if (lane >= o) s += t;
            }
            warpsum[lane] = s;
        }
        __syncthreads();
        int incl = x + (w > 0 ? warpsum[w - 1] : 0) + s_carry;
        if (i < Nn) {
            int excl = incl - v;
            g_off[i] = excl;
            g_cur[i] = excl;
        }
        __syncthreads();
        if (tid == 1023) s_carry = incl;
        __syncthreads();
    }
    if (tid == 0) g_off[Nn] = s_carry;
}
__global__ void k_fill(const int* __restrict__ u, const int* __restrict__ v, int E) {
    int e = blockIdx.x * blockDim.x + threadIdx.x;
    if (e >= E) return;
    int a = u[e], b = v[e];
    int p = atomicAdd(&g_cur[b], 1);
    g_adj[p] = a;
    int q = atomicAdd(&g_cur[a], 1);
    g_adj[q] = b;
}

// ---------------- aggregation: z = 2h + sum_{nb} h[nb] (h fp16) -> bf16 pairs ----------------
// 2 warps/node; each thread owns one uint4 = 8 halves of the row.
__global__ void k_agg(int Nn) {
    const int w = threadIdx.x >> 5;               // 0..7
    const int node = blockIdx.x * 4 + (w >> 1);
    if (node >= Nn) return;
    const int lane = threadIdx.x & 31;
    const int ci = (w & 1) * 32 + lane;           // uint4 index 0..63 (8 halves each)

    float acc[8];
    {
        uint4 t = ((const uint4*)(g_h + (size_t)node * D))[ci];
        const __half2* hh = (const __half2*)&t;
#pragma unroll
        for (int j = 0; j < 4; j++) {
            float2 f = __half22float2(hh[j]);
            acc[j * 2] = 2.f * f.x;
            acc[j * 2 + 1] = 2.f * f.y;
        }
    }
    const int e1 = g_off[node + 1];
    int e = g_off[node];
    if (e < e1) {
        uint4 cur = ((const uint4*)(g_h + (size_t)__ldg(&g_adj[e]) * D))[ci];
        for (++e; e < e1; ++e) {
            uint4 nxt = ((const uint4*)(g_h + (size_t)__ldg(&g_adj[e]) * D))[ci];
            const __half2* hh = (const __half2*)&cur;
#pragma unroll
            for (int j = 0; j < 4; j++) {
                float2 f = __half22float2(hh[j]);
                acc[j * 2] += f.x;
                acc[j * 2 + 1] += f.y;
            }
            cur = nxt;
        }
        const __half2* hh = (const __half2*)&cur;
#pragma unroll
        for (int j = 0; j < 4; j++) {
            float2 f = __half22float2(hh[j]);
            acc[j * 2] += f.x;
            acc[j * 2 + 1] += f.y;
        }
    }
    {
        unsigned hi[4], lo[4];
        split2(acc[0], acc[1], hi[0], lo[0]);
        split2(acc[2], acc[3], hi[1], lo[1]);
        split2(acc[4], acc[5], hi[2], lo[2]);
        split2(acc[6], acc[7], hi[3], lo[3]);
        size_t o = (size_t)node * D + (size_t)ci * 8;
        *(uint4*)(g_zh + o) = make_uint4(hi[0], hi[1], hi[2], hi[3]);
        *(uint4*)(g_zl + o) = make_uint4(lo[0], lo[1], lo[2], lo[3]);
    }
}

// ---------------- elementwise kernels ----------------
__global__ void k_gather(const int* __restrict__ ids, const float* __restrict__ emb, int Nn) {
    int idx = blockIdx.x * blockDim.x + threadIdx.x;
    int row = idx >> 7;
    if (row >= Nn) return;
    int c = (idx & 127) << 2;
    float4 val = *(const float4*)(emb + (size_t)ids[row] * D + c);
    size_t o = (size_t)row * D + c;
    ((unsigned*)(g_h + o))[0] = pack2h(val.x, val.y);
    ((unsigned*)(g_h + o))[1] = pack2h(val.z, val.w);
    *(float4*)(g_hsum + o) = val;
}

// weight transpose+convert: src [K,Nn] -> dst [Nn,K] bf16 pairs
__global__ void k_tcvt(const float* __restrict__ B, __nv_bfloat16* __restrict__ H,
                       __nv_bfloat16* __restrict__ Lo, int K, int Nn) {
    int idx = blockIdx.x * blockDim.x + threadIdx.x;
    if (idx >= K * Nn) return;
    int n = idx / K, k = idx - n * K;
    float x = B[(size_t)k * Nn + n];
    __nv_bfloat16 h, l;
    f2pair(x, h, l);
    H[idx] = h; Lo[idx] = l;
}

// weight transpose+convert to single fp16: src [K,Nn] -> dst [Nn,K]
__global__ void k_tcvt16(const float* __restrict__ B, __half* __restrict__ H, int K, int Nn) {
    int idx = blockIdx.x * blockDim.x + threadIdx.x;
    if (idx >= K * Nn) return;
    int n = idx / K, k = idx - n * K;
    H[idx] = __float2half(B[(size_t)k * Nn + n]);
}

__global__ void k_bnzero2() {
    int t = blockIdx.x * blockDim.x + threadIdx.x;
    if (t < 2048) g_stats[t] = 0.f;
}

// h = relu(affine(Y2)); hsum += h ; aff computed in-block from stats slot
// LAST=0: write h fp16 + hsum fp32.  LAST=1: write (hsum+h) as fp16 pairs only.
template <int LAST>
__global__ void k_bnrelu_acc(const float* __restrict__ Y2,
                             const float* __restrict__ stats,
                             const float* __restrict__ gamma,
                             const float* __restrict__ beta, int Nn) {
    __shared__ float s_aff[1024];
    int tid = threadIdx.x;
    {
        float inv = 1.f / (float)Nn;
#pragma unroll
        for (int j = tid; j < 512; j += 256) {
            float m = stats[j] * inv;
            float var = stats[512 + j] * inv - m * m;
            float sc = gamma[j] * rsqrtf(var + BN_EPS);
            s_aff[j] = sc;
            s_aff[512 + j] = beta[j] - m * sc;
        }
    }
    __syncthreads();
    int idx = blockIdx.x * blockDim.x + tid;
    if (idx >= Nn * 128) return;
    int c = (idx & 127) << 2;
    float4 v = *(const float4*)(Y2 + (size_t)idx * 4);
    v.x = fmaxf(v.x * s_aff[c + 0] + s_aff[512 + c + 0], 0.f);
    v.y = fmaxf(v.y * s_aff[c + 1] + s_aff[512 + c + 1], 0.f);
    v.z = fmaxf(v.z * s_aff[c + 2] + s_aff[512 + c + 2], 0.f);
    v.w = fmaxf(v.w * s_aff[c + 3] + s_aff[512 + c + 3], 0.f);
    float4 hs = *(const float4*)(g_hsum + (size_t)idx * 4);
    hs.x += v.x; hs.y += v.y; hs.z += v.z; hs.w += v.w;
    if (!LAST) {
        ((unsigned*)(g_h + (size_t)idx * 4))[0] = pack2h(v.x, v.y);
        ((unsigned*)(g_h + (size_t)idx * 4))[1] = pack2h(v.z, v.w);
        *(float4*)(g_hsum + (size_t)idx * 4) = hs;
    } else {
        unsigned h0, l0, h1, l1;
        split2h(hs.x, hs.y, h0, l0);
        split2h(hs.z, hs.w, h1, l1);
        ((unsigned*)(g_hsfh + (size_t)idx * 4))[0] = h0;
        ((unsigned*)(g_hsfh + (size_t)idx * 4))[1] = h1;
        ((unsigned*)(g_hsfl + (size_t)idx * 4))[0] = l0;
        ((unsigned*)(g_hsfl + (size_t)idx * 4))[1] = l1;
    }
}

// ---------------- launch ----------------
extern "C" void kernel_launch(void* const* d_in, const int* in_sizes, int n_in,
                              void* d_out, int out_size) {
    const int* h_ids = (const int*)d_in[0];
    const int* u     = (const int*)d_in[1];
    const int* v     = (const int*)d_in[2];
    const float* emb   = (const float*)d_in[3];
    const float* lin1  = (const float*)d_in[4];
    const float* lin2  = (const float*)d_in[5];
    const float* bn1_g = (const float*)d_in[6];
    const float* bn1_b = (const float*)d_in[7];
    const float* bn2_g = (const float*)d_in[8];
    const float* bn2_b = (const float*)d_in[9];
    const float* W1_w  = (const float*)d_in[10];
    const float* W1_b  = (const float*)d_in[11];
    const float* W2_w  = (const float*)d_in[12];
    const float* W2_b  = (const float*)d_in[13];
    float* out = (float*)d_out;

    const int N = in_sizes[0];
    const int E = in_sizes[1];
    const int L = in_sizes[4] / (D * D);

    const int SMEM_256 = (20480 + 256 * 160) * NSTAGE;  // 184320

    static int s_attr = 0;
    if (!s_attr) {
        cudaFuncSetAttribute(k_mma<512, 256, 1>, cudaFuncAttributeMaxDynamicSharedMemorySize, SMEM_256);
        cudaFuncSetAttribute(k_mma_pq, cudaFuncAttributeMaxDynamicSharedMemorySize, PQ_SMEM);
        cudaFuncSetAttribute(k_mma_bn, cudaFuncAttributeMaxDynamicSharedMemorySize, BNG_SMEM);
        cudaFuncSetAttribute(k_dec, cudaFuncAttributeMaxDynamicSharedMemorySize, DEC_SMEM);
        s_attr = 1;
    }

    float *dg_z, *dg_y, *dg_pq, *dg_stats;
    cudaGetSymbolAddress((void**)&dg_z, g_z);
    cudaGetSymbolAddress((void**)&dg_y, g_y);
    cudaGetSymbolAddress((void**)&dg_pq, g_pq);
    cudaGetSymbolAddress((void**)&dg_stats, g_stats);
    __nv_bfloat16 *zh, *zl;
    __nv_bfloat16 *l1th, *l1tl, *l2th, *l2tl;
    __half *hsfh, *hsfl, *w1f, *w2f;
    cudaGetSymbolAddress((void**)&zh, g_zh);  cudaGetSymbolAddress((void**)&zl, g_zl);
    cudaGetSymbolAddress((void**)&hsfh, g_hsfh); cudaGetSymbolAddress((void**)&hsfl, g_hsfl);
    cudaGetSymbolAddress((void**)&l1th, g_l1th); cudaGetSymbolAddress((void**)&l1tl, g_l1tl);
    cudaGetSymbolAddress((void**)&l2th, g_l2th); cudaGetSymbolAddress((void**)&l2tl, g_l2tl);
    cudaGetSymbolAddress((void**)&w1f, g_w1f);
    cudaGetSymbolAddress((void**)&w2f, g_w2f);

    const int ew = N * 128, ewB = (ew + 255) / 256;
    const int mtiles = (N + 127) / 128;
    const int etiles = (E + 127) / 128;
    const int edB = (E + 255) / 256;
    const int ndB = (N + 255) / 256;
    const int aggB = (N + 3) / 4;

    // weight conversion (transpose + split)
    const int wB = (D * D + 255) / 256;
    for (int i = 0; i < L; i++) {
        k_tcvt<<<wB, 256>>>(lin1 + (size_t)i * D * D, l1th + (size_t)i * D * D, l1tl + (size_t)i * D * D, D, D);
        k_tcvt<<<wB, 256>>>(lin2 + (size_t)i * D * D, l2th + (size_t)i * D * D, l2tl + (size_t)i * D * D, D, D);
    }
    k_tcvt16<<<wB, 256>>>(W1_w, w1f, D, D);
    k_tcvt16<<<wB, 256>>>(W1_w + (size_t)D * D, w1f + (size_t)D * D, D, D);
    k_tcvt16<<<(D * OUTD + 255) / 256, 256>>>(W2_w, w2f, D, OUTD);

    // h = emb[h_ids] (fp16); hidden_sum = h (fp32)
    k_gather<<<ewB, 256>>>(h_ids, emb, N);

    // CSR build (once)
    k_zerodeg<<<ndB, 256>>>(N);
    k_deg<<<edB, 256>>>(u, v, E);
    k_scan<<<1, 1024>>>(N);
    k_fill<<<edB, 256>>>(u, v, E);

    for (int i = 0; i < L; i++) {
        // z = 2h + neighbor sums -> bf16 pairs ; zero both stats slots
        k_agg<<<aggB, 256>>>(N);
        k_bnzero2<<<2, 1024>>>();
        // y = z @ lin1[i]  (stats -> slot0)
        k_mma<512, 256, 1><<<dim3(mtiles, 2), 512, SMEM_256>>>(
            zh, zl, l1th + (size_t)i * D * D, l1tl + (size_t)i * D * D,
            dg_y, N, D, dg_stats);
        // z(out) = relu(bn1(y)) @ lin2[i]  (fused BN loader; stats -> slot1)
        k_mma_bn<<<dim3(mtiles, 2), 512, BNG_SMEM>>>(
            dg_y, l2th + (size_t)i * D * D, l2tl + (size_t)i * D * D,
            dg_z, N,
            dg_stats, bn1_g + (size_t)i * D, bn1_b + (size_t)i * D,
            dg_stats + 1024);
        // h = relu(bn2(z)); hsum += h  (aff computed in-block from slot1)
        if (i == L - 1)
            k_bnrelu_acc<1><<<ewB, 256>>>(dg_z, dg_stats + 1024,
                bn2_g + (size_t)i * D, bn2_b + (size_t)i * D, N);
        else
            k_bnrelu_acc<0><<<ewB, 256>>>(dg_z, dg_stats + 1024,
                bn2_g + (size_t)i * D, bn2_b + (size_t)i * D, N);
    }

    // decoder: [P|Q] = hsum_fp16pairs @ fp16(W1t)^T  (2-pass fp16, Nout=1024)
    k_mma_pq<<<dim3(mtiles, 4), 512, PQ_SMEM>>>(
        hsfh, hsfl, w1f, dg_pq, N, 2 * D);
    // out = relu(P[u]+Q[v]+b1) @ fp16(W2)^T + b2  (fused edge loader, 2-pass fp16)
    k_dec<<<etiles, 512, DEC_SMEM>>>(dg_pq, w2f, out, E, u, v, W1_b, W2_b);
}

// round 14
// speedup vs baseline: 3.8092x; 1.1122x over previous
#include <cuda_runtime.h>
#include <cuda_bf16.h>
#include <cuda_fp16.h>

#define D 512
#define OUTD 128
#define MAXN 50000
#define MAXE 150000
#define BN_EPS 1e-5f

// ---------------- scratch (static device globals; no allocation) ----------------
__device__ __half g_h[(size_t)MAXN * D];    // current node features (fp16)
__device__ float g_hsum[(size_t)MAXN * D];  // hidden_sum accumulator (fp32)
__device__ float g_y[(size_t)MAXN * D];     // gemm1 output
__device__ float g_z[(size_t)MAXN * D];     // gemm2 output
__device__ float g_pq[(size_t)MAXN * 2 * D];// decoder P|Q concat
__device__ float g_stats[2 * 1024];         // slot0: GEMM1 (sum,sumsq), slot1: GEMM2

// CSR graph
__device__ int g_deg[MAXN];
__device__ int g_off[MAXN + 1];
__device__ int g_cur[MAXN];
__device__ int g_adj[2 * MAXE];

// fp16 split pairs: aggregation output z (exact to 2^-22)
__device__ __half g_zh[(size_t)MAXN * D], g_zl[(size_t)MAXN * D];
// fp16 split pairs: decoder hsum
__device__ __half g_hsfh[(size_t)MAXN * D], g_hsfl[(size_t)MAXN * D];
// weights: lin1 single fp16 [n][k]; lin2 bf16 pairs [n][k]; W1,W2 single fp16
__device__ __half g_l1f[(size_t)4 * D * D];
__device__ __nv_bfloat16 g_l2th[(size_t)4 * D * D], g_l2tl[(size_t)4 * D * D];
__device__ __half g_w1f[(size_t)D * 2 * D];
__device__ __half g_w2f[(size_t)OUTD * D];

// ---------------- PTX helpers (plain compute_100-legal) ----------------
__device__ __forceinline__ unsigned smem_u32(const void* p) {
    unsigned a;
    asm("{ .reg .u64 t; cvta.to.shared.u64 t, %1; cvt.u32.u64 %0, t; }" : "=r"(a) : "l"(p));
    return a;
}
__device__ __forceinline__ void cpasync16(unsigned dst, const void* src) {
    asm volatile("cp.async.cg.shared.global [%0], [%1], 16;" ::"r"(dst), "l"(src));
}
__device__ __forceinline__ void ldm4(unsigned* r, unsigned addr) {
    asm volatile("ldmatrix.sync.aligned.m8n8.x4.shared.b16 {%0,%1,%2,%3}, [%4];"
                 : "=r"(r[0]), "=r"(r[1]), "=r"(r[2]), "=r"(r[3]) : "r"(addr));
}
__device__ __forceinline__ void mma16816(float* c, const unsigned* a, const unsigned* b) {
    asm volatile(
        "mma.sync.aligned.m16n8k16.row.col.f32.bf16.bf16.f32 "
        "{%0,%1,%2,%3}, {%4,%5,%6,%7}, {%8,%9}, {%0,%1,%2,%3};"
        : "+f"(c[0]), "+f"(c[1]), "+f"(c[2]), "+f"(c[3])
        : "r"(a[0]), "r"(a[1]), "r"(a[2]), "r"(a[3]), "r"(b[0]), "r"(b[1]));
}
__device__ __forceinline__ void mma16816h(float* c, const unsigned* a, const unsigned* b) {
    asm volatile(
        "mma.sync.aligned.m16n8k16.row.col.f32.f16.f16.f32 "
        "{%0,%1,%2,%3}, {%4,%5,%6,%7}, {%8,%9}, {%0,%1,%2,%3};"
        : "+f"(c[0]), "+f"(c[1]), "+f"(c[2]), "+f"(c[3])
        : "r"(a[0]), "r"(a[1]), "r"(a[2]), "r"(a[3]), "r"(b[0]), "r"(b[1]));
}
__device__ __forceinline__ void f2pair(float v, __nv_bfloat16& h, __nv_bfloat16& l) {
    h = __float2bfloat16(v);
    l = __float2bfloat16(v - __bfloat162float(h));
}
__device__ __forceinline__ void split2(float a, float b, unsigned& hi, unsigned& lo) {
    __nv_bfloat16 h0, l0, h1, l1;
    f2pair(a, h0, l0);
    f2pair(b, h1, l1);
    __nv_bfloat162 hp; hp.x = h0; hp.y = h1;
    __nv_bfloat162 lp; lp.x = l0; lp.y = l1;
    hi = *(unsigned*)&hp;
    lo = *(unsigned*)&lp;
}
__device__ __forceinline__ void split2h(float a, float b, unsigned& hi, unsigned& lo) {
    __half h0 = __float2half(a);
    __half l0 = __float2half(a - __half2float(h0));
    __half h1 = __float2half(b);
    __half l1 = __float2half(b - __half2float(h1));
    __half2 hp; hp.x = h0; hp.y = h1;
    __half2 lp; lp.x = l0; lp.y = l1;
    hi = *(unsigned*)&hp;
    lo = *(unsigned*)&lp;
}
__device__ __forceinline__ unsigned pack2h(float a, float b) {
    __half2 p; p.x = __float2half(a); p.y = __float2half(b);
    return *(unsigned*)&p;
}

// 12 mma for one nb-block (3-term bf16), accumulator reuse distance >= 3
#define MMA_GROUP(A0, A1, C0, C1, AH, AL, B0H, B1H, B0L, B1L)                  \
    mma16816(A0, AH[0], B0H); mma16816(A1, AH[1], B0H);                        \
    mma16816(C0, AH[0], B1H); mma16816(C1, AH[1], B1H);                        \
    mma16816(A0, AH[0], B0L); mma16816(A1, AH[1], B0L);                        \
    mma16816(C0, AH[0], B1L); mma16816(C1, AH[1], B1L);                        \
    mma16816(A0, AL[0], B0H); mma16816(A1, AL[1], B0H);                        \
    mma16816(C0, AL[0], B1H); mma16816(C1, AL[1], B1H);

#define EPILOGUE_STORE(BN_, NOUT_)                                             \
    _Pragma("unroll") for (int mf = 0; mf < 2; mf++) {                         \
        const int r0 = bm + wm * 32 + mf * 16 + (lane >> 2);                   \
        _Pragma("unroll") for (int nf = 0; nf < 2 * ((BN_) / 64); nf++) {      \
            const int col = bn + wn * ((BN_) / 4) + nf * 8 + (lane & 3) * 2;   \
            const float* a = acc[mf][nf];                                      \
            _Pragma("unroll") for (int hh = 0; hh < 2; hh++) {                 \
                const int row = r0 + hh * 8;                                   \
                if (row >= M) continue;                                        \
                float2 s = make_float2(a[hh * 2], a[hh * 2 + 1]);              \
                *(float2*)(Cf + (size_t)row * (NOUT_) + col) = s;              \
            }                                                                  \
        }                                                                      \
    }

#define EPILOGUE_STATS(BN_)                                                    \
    _Pragma("unroll") for (int nf = 0; nf < 2 * ((BN_) / 64); nf++) {          \
        float s0 = 0.f, s1 = 0.f, q0 = 0.f, q1 = 0.f;                          \
        _Pragma("unroll") for (int mf = 0; mf < 2; mf++) {                     \
            const int rb = bm + wm * 32 + mf * 16 + (lane >> 2);               \
            _Pragma("unroll") for (int hh = 0; hh < 2; hh++) {                 \
                if (rb + hh * 8 < M) {                                         \
                    float v0 = acc[mf][nf][hh * 2], v1 = acc[mf][nf][hh * 2 + 1];\
                    s0 += v0; q0 += v0 * v0;                                   \
                    s1 += v1; q1 += v1 * v1;                                   \
                }                                                              \
            }                                                                  \
        }                                                                      \
        _Pragma("unroll") for (int o = 4; o < 32; o <<= 1) {                   \
            s0 += __shfl_xor_sync(0xffffffffu, s0, o);                         \
            s1 += __shfl_xor_sync(0xffffffffu, s1, o);                         \
            q0 += __shfl_xor_sync(0xffffffffu, q0, o);                         \
            q1 += __shfl_xor_sync(0xffffffffu, q1, o);                         \
        }                                                                      \
        if ((lane >> 2) == 0) {                                                \
            int col = bn + wn * ((BN_) / 4) + nf * 8 + (lane & 3) * 2;         \
            atomicAdd(&stats_out[col], s0);                                    \
            atomicAdd(&stats_out[col + 1], s1);                                \
            atomicAdd(&stats_out[512 + col], q0);                              \
            atomicAdd(&stats_out[512 + col + 1], q1);                          \
        }                                                                      \
    }

#define ACC_INIT(NB_)                                                          \
    float acc[2][2 * (NB_)][4];                                                \
    _Pragma("unroll") for (int i = 0; i < 2; i++)                              \
        _Pragma("unroll") for (int j = 0; j < 2 * (NB_); j++)                  \
            _Pragma("unroll") for (int q = 0; q < 4; q++) acc[i][j][q] = 0.f;

#define NSTAGE 3

// ---------------- fp16 2-pass GEMM: A = (hi,lo) fp16 pairs, B single fp16 ----------------
// Used for layer GEMM1 (STATS=1) and decoder PQ (STATS=0). BN=256.
#define PQ_SMEM (3 * 40960)  // 122880

template <int STATS>
__global__ __launch_bounds__(512)
void k_mma_f16(const __half* __restrict__ Ah, const __half* __restrict__ Al,
               const __half* __restrict__ Bf,
               float* __restrict__ Cf, int M, int Nout, float* __restrict__ stats_out) {
    constexpr int KTOT = 512, BN = 256, NB = 4, NC = 16;
    constexpr int O_AL = 10240, O_B = 20480, STAGE_BYTES = 40960;

    extern __shared__ __align__(16) char smem[];
    const int tid = threadIdx.x;
    const int wid = tid >> 5, lane = tid & 31;
    const int wm = wid & 3, wn = wid >> 2;
    const int bm = blockIdx.x * 128, bn = blockIdx.y * BN;
    const unsigned sb = smem_u32(smem);

    const int arow = tid >> 2, quad = tid & 3;
    const int grA = min(bm + arow, M - 1);

    ACC_INIT(NB)

#define F16_LOAD(STG, K0)                                                      \
    {                                                                          \
        unsigned st = sb + (STG) * STAGE_BYTES;                                \
        unsigned dsto = arow * 80 + quad * 16;                                 \
        size_t o = (size_t)grA * KTOT + (K0) + quad * 8;                       \
        cpasync16(st + dsto, Ah + o);                                          \
        cpasync16(st + O_AL + dsto, Al + o);                                   \
        _Pragma("unroll") for (int i = 0; i < 2; i++) {                        \
            int brow = arow + i * 128;                                         \
            unsigned bd = brow * 80 + quad * 16;                               \
            size_t ob = (size_t)(bn + brow) * KTOT + (K0) + quad * 8;          \
            cpasync16(st + O_B + bd, Bf + ob);                                 \
        }                                                                      \
    }

#pragma unroll
    for (int p = 0; p < NSTAGE - 1; p++) {
        if (p < NC) F16_LOAD(p, p * 32);
        asm volatile("cp.async.commit_group;");
    }

    int cstg = 0, lstg = NSTAGE - 1;
    for (int c = 0; c < NC; c++) {
        asm volatile("cp.async.wait_group %0;" ::"n"(NSTAGE - 2));
        __syncthreads();
        if (c + NSTAGE - 1 < NC) F16_LOAD(lstg, (c + NSTAGE - 1) * 32);
        asm volatile("cp.async.commit_group;");
        lstg = (lstg + 1 == NSTAGE) ? 0 : lstg + 1;

        const unsigned st = sb + cstg * STAGE_BYTES;
        cstg = (cstg + 1 == NSTAGE) ? 0 : cstg + 1;
#pragma unroll
        for (int ks = 0; ks < 2; ks++) {
            const unsigned koff = ks * 32;
            unsigned ah[2][4], al[2][4];
#pragma unroll
            for (int mf = 0; mf < 2; mf++) {
                unsigned addr = st + (wm * 32 + mf * 16 + (lane & 15)) * 80 +
                                ((lane >> 4) * 16) + koff;
                ldm4(ah[mf], addr);
                ldm4(al[mf], addr + O_AL);
            }
#pragma unroll
            for (int nb = 0; nb < NB; nb++) {
                unsigned addr = st + O_B +
                                (wn * 64 + nb * 16 + (lane & 15)) * 80 +
                                ((lane >> 4) * 16) + koff;
                unsigned bb[4];
                ldm4(bb, addr);
                unsigned b0[2] = {bb[0], bb[2]}, b1[2] = {bb[1], bb[3]};
                float* a0 = acc[0][nb * 2];
                float* a1 = acc[1][nb * 2];
                float* c0 = acc[0][nb * 2 + 1];
                float* c1 = acc[1][nb * 2 + 1];
                mma16816h(a0, ah[0], b0); mma16816h(a1, ah[1], b0);
                mma16816h(c0, ah[0], b1); mma16816h(c1, ah[1], b1);
                mma16816h(a0, al[0], b0); mma16816h(a1, al[1], b0);
                mma16816h(c0, al[0], b1); mma16816h(c1, al[1], b1);
            }
        }
    }
#undef F16_LOAD

    EPILOGUE_STORE(256, Nout)
    if (STATS) { EPILOGUE_STATS(256) }
}

// ---------------- GEMM2: fused BN-apply loader (3-term bf16) ----------------
#define BNG_SMEM (2 * 20480 + 3 * 40960 + 4096)  // 167936

__global__ __launch_bounds__(512)
void k_mma_bn(const float* __restrict__ Y,
              const __nv_bfloat16* __restrict__ Bh, const __nv_bfloat16* __restrict__ Bl,
              float* __restrict__ Cf, int M,
              const float* __restrict__ stats_in, const float* __restrict__ gamma,
              const float* __restrict__ beta, float* __restrict__ stats_out) {
    constexpr int KTOT = 512, BN = 256, NB = 4, NC = 16;
    constexpr int O_B = 40960;
    constexpr int O_AFF = 163840;
    extern __shared__ __align__(16) char smem[];
    float* s_aff = (float*)(smem + O_AFF);
    const int tid = threadIdx.x;
    const int wid = tid >> 5, lane = tid & 31;
    const int wm = wid & 3, wn = wid >> 2;
    const int bm = blockIdx.x * 128, bn = blockIdx.y * BN;
    const unsigned sb = smem_u32(smem);

    if (tid < 512) {
        float inv = 1.f / (float)M;
        float m = stats_in[tid] * inv;
        float var = stats_in[512 + tid] * inv - m * m;
        float sc = gamma[tid] * rsqrtf(var + BN_EPS);
        s_aff[tid] = sc;
        s_aff[512 + tid] = beta[tid] - m * sc;
    }

    const int arow = tid >> 2, quad = tid & 3;
    const int grA = min(bm + arow, M - 1);

    ACC_INIT(NB)

#define BNG_LOADB(STG, K0)                                                     \
    {                                                                          \
        unsigned st = sb + O_B + (STG) * 40960;                                \
        _Pragma("unroll") for (int i = 0; i < 2; i++) {                        \
            int brow = arow + i * 128;                                         \
            unsigned bd = brow * 80 + quad * 16;                               \
            size_t ob = (size_t)(bn + brow) * KTOT + (K0) + quad * 8;          \
            cpasync16(st + bd, Bh + ob);                                       \
            cpasync16(st + 20480 + bd, Bl + ob);                               \
        }                                                                      \
    }
#define BNG_LDGA(K0)                                                           \
    {                                                                          \
        const float4* yp = (const float4*)(Y + (size_t)grA * KTOT + (K0) + quad * 8);\
        ya[0] = __ldg(yp); ya[1] = __ldg(yp + 1);                              \
    }

    float4 ya[2];
    BNG_LDGA(0);
    BNG_LOADB(0, 0);
    asm volatile("cp.async.commit_group;");
    BNG_LOADB(1, 32);
    asm volatile("cp.async.commit_group;");
    __syncthreads();  // s_aff visible

    for (int c = 0; c < NC; c++) {
        {
            unsigned hi[4], lo[4];
            const int kb = c * 32 + quad * 8;
#pragma unroll
            for (int j = 0; j < 2; j++) {
                float4 y = ya[j];
                const int k = kb + j * 4;
                float x0 = fmaxf(y.x * s_aff[k + 0] + s_aff[512 + k + 0], 0.f);
                float x1 = fmaxf(y.y * s_aff[k + 1] + s_aff[512 + k + 1], 0.f);
                float x2 = fmaxf(y.z * s_aff[k + 2] + s_aff[512 + k + 2], 0.f);
                float x3 = fmaxf(y.w * s_aff[k + 3] + s_aff[512 + k + 3], 0.f);
                split2(x0, x1, hi[j * 2], lo[j * 2]);
                split2(x2, x3, hi[j * 2 + 1], lo[j * 2 + 1]);
            }
            char* ad = smem + (c & 1) * 20480 + arow * 80 + quad * 16;
            *(uint4*)ad = make_uint4(hi[0], hi[1], hi[2], hi[3]);
            *(uint4*)(ad + 10240) = make_uint4(lo[0], lo[1], lo[2], lo[3]);
        }
        asm volatile("cp.async.wait_group 1;");
        __syncthreads();
        if (c + 1 < NC) BNG_LDGA((c + 1) * 32);
        if (c + 2 < NC) BNG_LOADB((c + 2) % 3, (c + 2) * 32);
        asm volatile("cp.async.commit_group;");

        const unsigned ast = sb + (c & 1) * 20480;
        const unsigned bst = sb + O_B + (c % 3) * 40960;
#pragma unroll
        for (int ks = 0; ks < 2; ks++) {
            const unsigned koff = ks * 32;
            unsigned ah[2][4], al[2][4];
#pragma unroll
            for (int mf = 0; mf < 2; mf++) {
                unsigned addr = ast + (wm * 32 + mf * 16 + (lane & 15)) * 80 +
                                ((lane >> 4) * 16) + koff;
                ldm4(ah[mf], addr);
                ldm4(al[mf], addr + 10240);
            }
#pragma unroll
            for (int nb = 0; nb < NB; nb++) {
                unsigned addr = bst + (wn * 64 + nb * 16 + (lane & 15)) * 80 +
                                ((lane >> 4) * 16) + koff;
                unsigned bh[4], bl[4];
                ldm4(bh, addr);
                ldm4(bl, addr + 20480);
                unsigned b0h[2] = {bh[0], bh[2]}, b1h[2] = {bh[1], bh[3]};
                unsigned b0l[2] = {bl[0], bl[2]}, b1l[2] = {bl[1], bl[3]};
                float* a0 = acc[0][nb * 2];
                float* a1 = acc[1][nb * 2];
                float* c0 = acc[0][nb * 2 + 1];
                float* c1 = acc[1][nb * 2 + 1];
                MMA_GROUP(a0, a1, c0, c1, ah, al, b0h, b1h, b0l, b1l)
            }
        }
    }
#undef BNG_LOADB
#undef BNG_LDGA

    const int Nout = 512;
    EPILOGUE_STORE(256, Nout)
    EPILOGUE_STATS(256)
}

// ---------------- decoder final GEMM: fused edge loader, 2-pass fp16 ----------------
#define DEC_SMEM (2 * 20480 + 3 * 10240)  // 71680

__global__ __launch_bounds__(512)
void k_dec(const float* __restrict__ PQ,
           const __half* __restrict__ Bf,
           float* __restrict__ Cf, int M,
           const int* __restrict__ gu, const int* __restrict__ gv,
           const float* __restrict__ bias1, const float* __restrict__ bias2) {
    constexpr int KTOT = 512, NB = 2, NC = 16;
    extern __shared__ __align__(16) char smem[];
    __shared__ int s_u[128], s_v[128];
    const int tid = threadIdx.x;
    const int wid = tid >> 5, lane = tid & 31;
    const int wm = wid & 3, wn = wid >> 2;
    const int bm = blockIdx.x * 128;
    const unsigned sb = smem_u32(smem);

    if (tid < 128) {
        int e = min(bm + tid, M - 1);
        s_u[tid] = gu[e];
        s_v[tid] = gv[e];
    }
    __syncthreads();

    const int arow = tid >> 2, quad = tid & 3;
    const size_t prow = (size_t)s_u[arow] * 1024;
    const size_t qrow = (size_t)s_v[arow] * 1024 + 512;

    ACC_INIT(NB)

#define DEC_LOADB(STG, K0)                                                     \
    {                                                                          \
        unsigned st = sb + 40960 + (STG) * 10240;                              \
        unsigned bd = arow * 80 + quad * 16;                                   \
        size_t ob = (size_t)arow * KTOT + (K0) + quad * 8;                     \
        cpasync16(st + bd, Bf + ob);                                           \
    }
#define DEC_LDGA(K0)                                                           \
    {                                                                          \
        const float4* pp = (const float4*)(PQ + prow + (K0) + quad * 8);       \
        const float4* qq = (const float4*)(PQ + qrow + (K0) + quad * 8);       \
        pa[0] = __ldg(pp); pa[1] = __ldg(pp + 1);                              \
        qa[0] = __ldg(qq); qa[1] = __ldg(qq + 1);                              \
    }

    float4 pa[2], qa[2];
    DEC_LDGA(0);
    DEC_LOADB(0, 0);
    asm volatile("cp.async.commit_group;");
    DEC_LOADB(1, 32);
    asm volatile("cp.async.commit_group;");

    for (int c = 0; c < NC; c++) {
        {
            unsigned hi[4], lo[4];
            const float* b1 = bias1 + c * 32 + quad * 8;
#pragma unroll
            for (int j = 0; j < 2; j++) {
                float4 p = pa[j], q = qa[j];
                float4 bb = *(const float4*)(b1 + j * 4);
                float x0 = fmaxf(p.x + q.x + bb.x, 0.f);
                float x1 = fmaxf(p.y + q.y + bb.y, 0.f);
                float x2 = fmaxf(p.z + q.z + bb.z, 0.f);
                float x3 = fmaxf(p.w + q.w + bb.w, 0.f);
                split2h(x0, x1, hi[j * 2], lo[j * 2]);
                split2h(x2, x3, hi[j * 2 + 1], lo[j * 2 + 1]);
            }
            char* ad = smem + (c & 1) * 20480 + arow * 80 + quad * 16;
            *(uint4*)ad = make_uint4(hi[0], hi[1], hi[2], hi[3]);
            *(uint4*)(ad + 10240) = make_uint4(lo[0], lo[1], lo[2], lo[3]);
        }
        asm volatile("cp.async.wait_group 1;");
        __syncthreads();
        if (c + 1 < NC) DEC_LDGA((c + 1) * 32);
        if (c + 2 < NC) DEC_LOADB((c + 2) % 3, (c + 2) * 32);
        asm volatile("cp.async.commit_group;");

        const unsigned ast = sb + (c & 1) * 20480;
        const unsigned bst = sb + 40960 + (c % 3) * 10240;
#pragma unroll
        for (int ks = 0; ks < 2; ks++) {
            const unsigned koff = ks * 32;
            unsigned ah[2][4], al[2][4];
#pragma unroll
            for (int mf = 0; mf < 2; mf++) {
                unsigned addr = ast + (wm * 32 + mf * 16 + (lane & 15)) * 80 +
                                ((lane >> 4) * 16) + koff;
                ldm4(ah[mf], addr);
                ldm4(al[mf], addr + 10240);
            }
#pragma unroll
            for (int nb = 0; nb < NB; nb++) {
                unsigned addr = bst + (wn * 32 + nb * 16 + (lane & 15)) * 80 +
                                ((lane >> 4) * 16) + koff;
                unsigned bb[4];
                ldm4(bb, addr);
                unsigned b0[2] = {bb[0], bb[2]}, b1[2] = {bb[1], bb[3]};
                float* a0 = acc[0][nb * 2];
                float* a1 = acc[1][nb * 2];
                float* c0 = acc[0][nb * 2 + 1];
                float* c1 = acc[1][nb * 2 + 1];
                mma16816h(a0, ah[0], b0); mma16816h(a1, ah[1], b0);
                mma16816h(c0, ah[0], b1); mma16816h(c1, ah[1], b1);
                mma16816h(a0, al[0], b0); mma16816h(a1, al[1], b0);
                mma16816h(c0, al[0], b1); mma16816h(c1, al[1], b1);
            }
        }
    }
#undef DEC_LOADB
#undef DEC_LDGA

#pragma unroll
    for (int mf = 0; mf < 2; mf++) {
        const int r0 = bm + wm * 32 + mf * 16 + (lane >> 2);
#pragma unroll
        for (int nf = 0; nf < 2 * NB; nf++) {
            const int col = wn * 32 + nf * 8 + (lane & 3) * 2;
#pragma unroll
            for (int hh = 0; hh < 2; hh++) {
                const int row = r0 + hh * 8;
                if (row >= M) continue;
                float2 s = make_float2(acc[mf][nf][hh * 2] + bias2[col],
                                       acc[mf][nf][hh * 2 + 1] + bias2[col + 1]);
                *(float2*)(Cf + (size_t)row * OUTD + col) = s;
            }
        }
    }
}

// ---------------- CSR build ----------------
__global__ void k_zerodeg(int Nn) {
    int i = blockIdx.x * blockDim.x + threadIdx.x;
    if (i < Nn) g_deg[i] = 0;
}
__global__ void k_deg(const int* __restrict__ u, const int* __restrict__ v, int E) {
    int e = blockIdx.x * blockDim.x + threadIdx.x;
    if (e >= E) return;
    atomicAdd(&g_deg[u[e]], 1);
    atomicAdd(&g_deg[v[e]], 1);
}
__global__ void k_scan(int Nn) {
    __shared__ int warpsum[32];
    __shared__ int s_carry;
    const int tid = threadIdx.x, lane = tid & 31, w = tid >> 5;
    if (tid == 0) s_carry = 0;
    __syncthreads();
    for (int base = 0; base < Nn; base += 1024) {
        int i = base + tid;
        int v = (i < Nn) ? g_deg[i] : 0;
        int x = v;
#pragma unroll
        for (int o = 1; o < 32; o <<= 1) {
            int t = __shfl_up_sync(0xffffffffu, x, o);
            if (lane >= o) x += t;
        }
        if (lane == 31) warpsum[w] = x;
        __syncthreads();
        if (w == 0) {
            int s = warpsum[lane];
#pragma unroll
            for (int o = 1; o < 32; o <<= 1) {
                int t = __shfl_up_sync(0xffffffffu, s, o);
                if (lane >= o) s += t;
            }
            warpsum[lane] = s;
        }
        __syncthreads();
        int incl = x + (w > 0 ? warpsum[w - 1] : 0) + s_carry;
        if (i < Nn) {
            int excl = incl - v;
            g_off[i] = excl;
            g_cur[i] = excl;
        }
        __syncthreads();
        if (tid == 1023) s_carry = incl;
        __syncthreads();
    }
    if (tid == 0) g_off[Nn] = s_carry;
}
__global__ void k_fill(const int* __restrict__ u, const int* __restrict__ v, int E) {
    int e = blockIdx.x * blockDim.x + threadIdx.x;
    if (e >= E) return;
    int a = u[e], b = v[e];
    int p = atomicAdd(&g_cur[b], 1);
    g_adj[p] = a;
    int q = atomicAdd(&g_cur[a], 1);
    g_adj[q] = b;
}

// ---------------- aggregation: z = 2h + sum_{nb} h[nb] (h fp16) -> fp16 pairs ----------------
__global__ void k_agg(int Nn) {
    const int w = threadIdx.x >> 5;               // 0..7
    const int node = blockIdx.x * 4 + (w >> 1);
    if (node >= Nn) return;
    const int lane = threadIdx.x & 31;
    const int ci = (w & 1) * 32 + lane;           // uint4 index 0..63 (8 halves each)

    float acc[8];
    {
        uint4 t = ((const uint4*)(g_h + (size_t)node * D))[ci];
        const __half2* hh = (const __half2*)&t;
#pragma unroll
        for (int j = 0; j < 4; j++) {
            float2 f = __half22float2(hh[j]);
            acc[j * 2] = 2.f * f.x;
            acc[j * 2 + 1] = 2.f * f.y;
        }
    }
    const int e1 = g_off[node + 1];
    int e = g_off[node];
    if (e < e1) {
        uint4 cur = ((const uint4*)(g_h + (size_t)__ldg(&g_adj[e]) * D))[ci];
        for (++e; e < e1; ++e) {
            uint4 nxt = ((const uint4*)(g_h + (size_t)__ldg(&g_adj[e]) * D))[ci];
            const __half2* hh = (const __half2*)&cur;
#pragma unroll
            for (int j = 0; j < 4; j++) {
                float2 f = __half22float2(hh[j]);
                acc[j * 2] += f.x;
                acc[j * 2 + 1] += f.y;
            }
            cur = nxt;
        }
        const __half2* hh = (const __half2*)&cur;
#pragma unroll
        for (int j = 0; j < 4; j++) {
            float2 f = __half22float2(hh[j]);
            acc[j * 2] += f.x;
            acc[j * 2 + 1] += f.y;
        }
    }
    {
        unsigned hi[4], lo[4];
        split2h(acc[0], acc[1], hi[0], lo[0]);
        split2h(acc[2], acc[3], hi[1], lo[1]);
        split2h(acc[4], acc[5], hi[2], lo[2]);
        split2h(acc[6], acc[7], hi[3], lo[3]);
        size_t o = (size_t)node * D + (size_t)ci * 8;
        *(uint4*)(g_zh + o) = make_uint4(hi[0], hi[1], hi[2], hi[3]);
        *(uint4*)(g_zl + o) = make_uint4(lo[0], lo[1], lo[2], lo[3]);
    }
}

// ---------------- elementwise kernels ----------------
__global__ void k_gather(const int* __restrict__ ids, const float* __restrict__ emb, int Nn) {
    int idx = blockIdx.x * blockDim.x + threadIdx.x;
    int row = idx >> 7;
    if (row >= Nn) return;
    int c = (idx & 127) << 2;
    float4 val = *(const float4*)(emb + (size_t)ids[row] * D + c);
    size_t o = (size_t)row * D + c;
    ((unsigned*)(g_h + o))[0] = pack2h(val.x, val.y);
    ((unsigned*)(g_h + o))[1] = pack2h(val.z, val.w);
    *(float4*)(g_hsum + o) = val;
}

// weight transpose+convert: src [K,Nn] -> dst [Nn,K] bf16 pairs
__global__ void k_tcvt(const float* __restrict__ B, __nv_bfloat16* __restrict__ H,
                       __nv_bfloat16* __restrict__ Lo, int K, int Nn) {
    int idx = blockIdx.x * blockDim.x + threadIdx.x;
    if (idx >= K * Nn) return;
    int n = idx / K, k = idx - n * K;
    float x = B[(size_t)k * Nn + n];
    __nv_bfloat16 h, l;
    f2pair(x, h, l);
    H[idx] = h; Lo[idx] = l;
}

// weight transpose+convert to single fp16: src [K,Nn] -> dst [Nn,K]
__global__ void k_tcvt16(const float* __restrict__ B, __half* __restrict__ H, int K, int Nn) {
    int idx = blockIdx.x * blockDim.x + threadIdx.x;
    if (idx >= K * Nn) return;
    int n = idx / K, k = idx - n * K;
    H[idx] = __float2half(B[(size_t)k * Nn + n]);
}

__global__ void k_bnzero2() {
    int t = blockIdx.x * blockDim.x + threadIdx.x;
    if (t < 2048) g_stats[t] = 0.f;
}

// h = relu(affine(Y2)); hsum += h ; aff computed in-block from stats slot
// LAST=0: write h fp16 + hsum fp32.  LAST=1: write (hsum+h) as fp16 pairs only.
template <int LAST>
__global__ void k_bnrelu_acc(const float* __restrict__ Y2,
                             const float* __restrict__ stats,
                             const float* __restrict__ gamma,
                             const float* __restrict__ beta, int Nn) {
    __shared__ float s_aff[1024];
    int tid = threadIdx.x;
    {
        float inv = 1.f / (float)Nn;
#pragma unroll
        for (int j = tid; j < 512; j += 256) {
            float m = stats[j] * inv;
            float var = stats[512 + j] * inv - m * m;
            float sc = gamma[j] * rsqrtf(var + BN_EPS);
            s_aff[j] = sc;
            s_aff[512 + j] = beta[j] - m * sc;
        }
    }
    __syncthreads();
    int idx = blockIdx.x * blockDim.x + tid;
    if (idx >= Nn * 128) return;
    int c = (idx & 127) << 2;
    float4 v = *(const float4*)(Y2 + (size_t)idx * 4);
    v.x = fmaxf(v.x * s_aff[c + 0] + s_aff[512 + c + 0], 0.f);
    v.y = fmaxf(v.y * s_aff[c + 1] + s_aff[512 + c + 1], 0.f);
    v.z = fmaxf(v.z * s_aff[c + 2] + s_aff[512 + c + 2], 0.f);
    v.w = fmaxf(v.w * s_aff[c + 3] + s_aff[512 + c + 3], 0.f);
    float4 hs = *(const float4*)(g_hsum + (size_t)idx * 4);
    hs.x += v.x; hs.y += v.y; hs.z += v.z; hs.w += v.w;
    if (!LAST) {
        ((unsigned*)(g_h + (size_t)idx * 4))[0] = pack2h(v.x, v.y);
        ((unsigned*)(g_h + (size_t)idx * 4))[1] = pack2h(v.z, v.w);
        *(float4*)(g_hsum + (size_t)idx * 4) = hs;
    } else {
        unsigned h0, l0, h1, l1;
        split2h(hs.x, hs.y, h0, l0);
        split2h(hs.z, hs.w, h1, l1);
        ((unsigned*)(g_hsfh + (size_t)idx * 4))[0] = h0;
        ((unsigned*)(g_hsfh + (size_t)idx * 4))[1] = h1;
        ((unsigned*)(g_hsfl + (size_t)idx * 4))[0] = l0;
        ((unsigned*)(g_hsfl + (size_t)idx * 4))[1] = l1;
    }
}

// ---------------- launch ----------------
extern "C" void kernel_launch(void* const* d_in, const int* in_sizes, int n_in,
                              void* d_out, int out_size) {
    const int* h_ids = (const int*)d_in[0];
    const int* u     = (const int*)d_in[1];
    const int* v     = (const int*)d_in[2];
    const float* emb   = (const float*)d_in[3];
    const float* lin1  = (const float*)d_in[4];
    const float* lin2  = (const float*)d_in[5];
    const float* bn1_g = (const float*)d_in[6];
    const float* bn1_b = (const float*)d_in[7];
    const float* bn2_g = (const float*)d_in[8];
    const float* bn2_b = (const float*)d_in[9];
    const float* W1_w  = (const float*)d_in[10];
    const float* W1_b  = (const float*)d_in[11];
    const float* W2_w  = (const float*)d_in[12];
    const float* W2_b  = (const float*)d_in[13];
    float* out = (float*)d_out;

    const int N = in_sizes[0];
    const int E = in_sizes[1];
    const int L = in_sizes[4] / (D * D);

    static int s_attr = 0;
    if (!s_attr) {
        cudaFuncSetAttribute(k_mma_f16<0>, cudaFuncAttributeMaxDynamicSharedMemorySize, PQ_SMEM);
        cudaFuncSetAttribute(k_mma_f16<1>, cudaFuncAttributeMaxDynamicSharedMemorySize, PQ_SMEM);
        cudaFuncSetAttribute(k_mma_bn, cudaFuncAttributeMaxDynamicSharedMemorySize, BNG_SMEM);
        cudaFuncSetAttribute(k_dec, cudaFuncAttributeMaxDynamicSharedMemorySize, DEC_SMEM);
        s_attr = 1;
    }

    float *dg_z, *dg_y, *dg_pq, *dg_stats;
    cudaGetSymbolAddress((void**)&dg_z, g_z);
    cudaGetSymbolAddress((void**)&dg_y, g_y);
    cudaGetSymbolAddress((void**)&dg_pq, g_pq);
    cudaGetSymbolAddress((void**)&dg_stats, g_stats);
    __nv_bfloat16 *l2th, *l2tl;
    __half *zh, *zl, *hsfh, *hsfl, *l1f, *w1f, *w2f;
    cudaGetSymbolAddress((void**)&zh, g_zh);  cudaGetSymbolAddress((void**)&zl, g_zl);
    cudaGetSymbolAddress((void**)&hsfh, g_hsfh); cudaGetSymbolAddress((void**)&hsfl, g_hsfl);
    cudaGetSymbolAddress((void**)&l1f, g_l1f);
    cudaGetSymbolAddress((void**)&l2th, g_l2th); cudaGetSymbolAddress((void**)&l2tl, g_l2tl);
    cudaGetSymbolAddress((void**)&w1f, g_w1f);
    cudaGetSymbolAddress((void**)&w2f, g_w2f);

    const int ew = N * 128, ewB = (ew + 255) / 256;
    const int mtiles = (N + 127) / 128;
    const int etiles = (E + 127) / 128;
    const int edB = (E + 255) / 256;
    const int ndB = (N + 255) / 256;
    const int aggB = (N + 3) / 4;

    // weight conversion (transpose + split/convert)
    const int wB = (D * D + 255) / 256;
    for (int i = 0; i < L; i++) {
        k_tcvt16<<<wB, 256>>>(lin1 + (size_t)i * D * D, l1f + (size_t)i * D * D, D, D);
        k_tcvt<<<wB, 256>>>(lin2 + (size_t)i * D * D, l2th + (size_t)i * D * D, l2tl + (size_t)i * D * D, D, D);
    }
    k_tcvt16<<<wB, 256>>>(W1_w, w1f, D, D);
    k_tcvt16<<<wB, 256>>>(W1_w + (size_t)D * D, w1f + (size_t)D * D, D, D);
    k_tcvt16<<<(D * OUTD + 255) / 256, 256>>>(W2_w, w2f, D, OUTD);

    // h = emb[h_ids] (fp16); hidden_sum = h (fp32)
    k_gather<<<ewB, 256>>>(h_ids, emb, N);

    // CSR build (once)
    k_zerodeg<<<ndB, 256>>>(N);
    k_deg<<<edB, 256>>>(u, v, E);
    k_scan<<<1, 1024>>>(N);
    k_fill<<<edB, 256>>>(u, v, E);

    for (int i = 0; i < L; i++) {
        // z = 2h + neighbor sums -> fp16 pairs ; zero both stats slots
        k_agg<<<aggB, 256>>>(N);
        k_bnzero2<<<2, 1024>>>();
        // y = z @ lin1[i]  (2-pass fp16, stats -> slot0)
        k_mma_f16<1><<<dim3(mtiles, 2), 512, PQ_SMEM>>>(
            zh, zl, l1f + (size_t)i * D * D, dg_y, N, D, dg_stats);
        // z(out) = relu(bn1(y)) @ lin2[i]  (fused BN loader, 3-term bf16; stats -> slot1)
        k_mma_bn<<<dim3(mtiles, 2), 512, BNG_SMEM>>>(
            dg_y, l2th + (size_t)i * D * D, l2tl + (size_t)i * D * D,
            dg_z, N,
            dg_stats, bn1_g + (size_t)i * D, bn1_b + (size_t)i * D,
            dg_stats + 1024);
        // h = relu(bn2(z)); hsum += h  (aff computed in-block from slot1)
        if (i == L - 1)
            k_bnrelu_acc<1><<<ewB, 256>>>(dg_z, dg_stats + 1024,
                bn2_g + (size_t)i * D, bn2_b + (size_t)i * D, N);
        else
            k_bnrelu_acc<0><<<ewB, 256>>>(dg_z, dg_stats + 1024,
                bn2_g + (size_t)i * D, bn2_b + (size_t)i * D, N);
    }

    // decoder: [P|Q] = hsum_fp16pairs @ fp16(W1t)^T  (2-pass fp16, Nout=1024)
    k_mma_f16<0><<<dim3(mtiles, 4), 512, PQ_SMEM>>>(
        hsfh, hsfl, w1f, dg_pq, N, 2 * D, nullptr);
    // out = relu(P[u]+Q[v]+b1) @ fp16(W2)^T + b2  (fused edge loader, 2-pass fp16)
    k_dec<<<etiles, 512, DEC_SMEM>>>(dg_pq, w2f, out, E, u, v, W1_b, W2_b);
}

// round 15
// speedup vs baseline: 4.3026x; 1.1295x over previous
#include <cuda_runtime.h>
#include <cuda_bf16.h>
#include <cuda_fp16.h>

#define D 512
#define OUTD 128
#define MAXN 50000
#define MAXE 150000
#define BN_EPS 1e-5f

// ---------------- scratch (static device globals; no allocation) ----------------
__device__ __half g_h[(size_t)MAXN * D];    // current node features (fp16)
__device__ float g_hsum[(size_t)MAXN * D];  // hidden_sum accumulator (fp32)
__device__ float g_y[(size_t)MAXN * D];     // gemm1 output
__device__ float g_z[(size_t)MAXN * D];     // gemm2 output
__device__ float g_pq[(size_t)MAXN * 2 * D];// decoder P|Q concat
__device__ float g_stats[2 * 1024];         // slot0: GEMM1 (sum,sumsq), slot1: GEMM2

// CSR graph
__device__ int g_deg[MAXN];
__device__ int g_off[MAXN + 1];
__device__ int g_cur[MAXN];
__device__ int g_adj[2 * MAXE];

// fp16 split pairs: aggregation output z (exact to 2^-22)
__device__ __half g_zh[(size_t)MAXN * D], g_zl[(size_t)MAXN * D];
// fp16 split pairs: decoder hsum
__device__ __half g_hsfh[(size_t)MAXN * D], g_hsfl[(size_t)MAXN * D];
// weights (single fp16, transposed [n][k])
__device__ __half g_l1f[(size_t)4 * D * D];
__device__ __half g_l2f[(size_t)4 * D * D];
__device__ __half g_w1f[(size_t)D * 2 * D];
__device__ __half g_w2f[(size_t)OUTD * D];

// ---------------- PTX helpers (plain compute_100-legal) ----------------
__device__ __forceinline__ unsigned smem_u32(const void* p) {
    unsigned a;
    asm("{ .reg .u64 t; cvta.to.shared.u64 t, %1; cvt.u32.u64 %0, t; }" : "=r"(a) : "l"(p));
    return a;
}
__device__ __forceinline__ void cpasync16(unsigned dst, const void* src) {
    asm volatile("cp.async.cg.shared.global [%0], [%1], 16;" ::"r"(dst), "l"(src));
}
__device__ __forceinline__ void ldm4(unsigned* r, unsigned addr) {
    asm volatile("ldmatrix.sync.aligned.m8n8.x4.shared.b16 {%0,%1,%2,%3}, [%4];"
                 : "=r"(r[0]), "=r"(r[1]), "=r"(r[2]), "=r"(r[3]) : "r"(addr));
}
__device__ __forceinline__ void mma16816h(float* c, const unsigned* a, const unsigned* b) {
    asm volatile(
        "mma.sync.aligned.m16n8k16.row.col.f32.f16.f16.f32 "
        "{%0,%1,%2,%3}, {%4,%5,%6,%7}, {%8,%9}, {%0,%1,%2,%3};"
        : "+f"(c[0]), "+f"(c[1]), "+f"(c[2]), "+f"(c[3])
        : "r"(a[0]), "r"(a[1]), "r"(a[2]), "r"(a[3]), "r"(b[0]), "r"(b[1]));
}
__device__ __forceinline__ void split2h(float a, float b, unsigned& hi, unsigned& lo) {
    __half h0 = __float2half(a);
    __half l0 = __float2half(a - __half2float(h0));
    __half h1 = __float2half(b);
    __half l1 = __float2half(b - __half2float(h1));
    __half2 hp; hp.x = h0; hp.y = h1;
    __half2 lp; lp.x = l0; lp.y = l1;
    hi = *(unsigned*)&hp;
    lo = *(unsigned*)&lp;
}
__device__ __forceinline__ unsigned pack2h(float a, float b) {
    __half2 p; p.x = __float2half(a); p.y = __float2half(b);
    return *(unsigned*)&p;
}

#define EPILOGUE_STORE(BN_, NOUT_)                                             \
    _Pragma("unroll") for (int mf = 0; mf < 2; mf++) {                         \
        const int r0 = bm + wm * 32 + mf * 16 + (lane >> 2);                   \
        _Pragma("unroll") for (int nf = 0; nf < 2 * ((BN_) / 64); nf++) {      \
            const int col = bn + wn * ((BN_) / 4) + nf * 8 + (lane & 3) * 2;   \
            const float* a = acc[mf][nf];                                      \
            _Pragma("unroll") for (int hh = 0; hh < 2; hh++) {                 \
                const int row = r0 + hh * 8;                                   \
                if (row >= M) continue;                                        \
                float2 s = make_float2(a[hh * 2], a[hh * 2 + 1]);              \
                *(float2*)(Cf + (size_t)row * (NOUT_) + col) = s;              \
            }                                                                  \
        }                                                                      \
    }

#define EPILOGUE_STATS(BN_)                                                    \
    _Pragma("unroll") for (int nf = 0; nf < 2 * ((BN_) / 64); nf++) {          \
        float s0 = 0.f, s1 = 0.f, q0 = 0.f, q1 = 0.f;                          \
        _Pragma("unroll") for (int mf = 0; mf < 2; mf++) {                     \
            const int rb = bm + wm * 32 + mf * 16 + (lane >> 2);               \
            _Pragma("unroll") for (int hh = 0; hh < 2; hh++) {                 \
                if (rb + hh * 8 < M) {                                         \
                    float v0 = acc[mf][nf][hh * 2], v1 = acc[mf][nf][hh * 2 + 1];\
                    s0 += v0; q0 += v0 * v0;                                   \
                    s1 += v1; q1 += v1 * v1;                                   \
                }                                                              \
            }                                                                  \
        }                                                                      \
        _Pragma("unroll") for (int o = 4; o < 32; o <<= 1) {                   \
            s0 += __shfl_xor_sync(0xffffffffu, s0, o);                         \
            s1 += __shfl_xor_sync(0xffffffffu, s1, o);                         \
            q0 += __shfl_xor_sync(0xffffffffu, q0, o);                         \
            q1 += __shfl_xor_sync(0xffffffffu, q1, o);                         \
        }                                                                      \
        if ((lane >> 2) == 0) {                                                \
            int col = bn + wn * ((BN_) / 4) + nf * 8 + (lane & 3) * 2;         \
            atomicAdd(&stats_out[col], s0);                                    \
            atomicAdd(&stats_out[col + 1], s1);                                \
            atomicAdd(&stats_out[512 + col], q0);                              \
            atomicAdd(&stats_out[512 + col + 1], q1);                          \
        }                                                                      \
    }

#define ACC_INIT(NB_)                                                          \
    float acc[2][2 * (NB_)][4];                                                \
    _Pragma("unroll") for (int i = 0; i < 2; i++)                              \
        _Pragma("unroll") for (int j = 0; j < 2 * (NB_); j++)                  \
            _Pragma("unroll") for (int q = 0; q < 4; q++) acc[i][j][q] = 0.f;

// 8 mma for one nb-block: 2-pass fp16 (A hi+lo pairs, B single)
#define MMA8(NB_IDX, AH, AL, B0, B1)                                           \
    {                                                                          \
        float* a0 = acc[0][(NB_IDX) * 2];                                      \
        float* a1 = acc[1][(NB_IDX) * 2];                                      \
        float* c0 = acc[0][(NB_IDX) * 2 + 1];                                  \
        float* c1 = acc[1][(NB_IDX) * 2 + 1];                                  \
        mma16816h(a0, AH[0], B0); mma16816h(a1, AH[1], B0);                    \
        mma16816h(c0, AH[0], B1); mma16816h(c1, AH[1], B1);                    \
        mma16816h(a0, AL[0], B0); mma16816h(a1, AL[1], B0);                    \
        mma16816h(c0, AL[0], B1); mma16816h(c1, AL[1], B1);                    \
    }

#define NSTAGE 3

// ---------------- fp16 2-pass GEMM: A = (hi,lo) fp16 pairs in gmem, B single fp16 ----------------
// Used for layer GEMM1 (STATS=1) and decoder PQ (STATS=0). BN=256.
#define PQ_SMEM (3 * 40960)  // 122880

template <int STATS>
__global__ __launch_bounds__(512)
void k_mma_f16(const __half* __restrict__ Ah, const __half* __restrict__ Al,
               const __half* __restrict__ Bf,
               float* __restrict__ Cf, int M, int Nout, float* __restrict__ stats_out) {
    constexpr int KTOT = 512, BN = 256, NB = 4, NC = 16;
    constexpr int O_AL = 10240, O_B = 20480, STAGE_BYTES = 40960;

    extern __shared__ __align__(16) char smem[];
    const int tid = threadIdx.x;
    const int wid = tid >> 5, lane = tid & 31;
    const int wm = wid & 3, wn = wid >> 2;
    const int bm = blockIdx.x * 128, bn = blockIdx.y * BN;
    const unsigned sb = smem_u32(smem);

    const int arow = tid >> 2, quad = tid & 3;
    const int grA = min(bm + arow, M - 1);

    ACC_INIT(NB)

#define F16_LOAD(STG, K0)                                                      \
    {                                                                          \
        unsigned st = sb + (STG) * STAGE_BYTES;                                \
        unsigned dsto = arow * 80 + quad * 16;                                 \
        size_t o = (size_t)grA * KTOT + (K0) + quad * 8;                       \
        cpasync16(st + dsto, Ah + o);                                          \
        cpasync16(st + O_AL + dsto, Al + o);                                   \
        _Pragma("unroll") for (int i = 0; i < 2; i++) {                        \
            int brow = arow + i * 128;                                         \
            unsigned bd = brow * 80 + quad * 16;                               \
            size_t ob = (size_t)(bn + brow) * KTOT + (K0) + quad * 8;          \
            cpasync16(st + O_B + bd, Bf + ob);                                 \
        }                                                                      \
    }

#pragma unroll
    for (int p = 0; p < NSTAGE - 1; p++) {
        if (p < NC) F16_LOAD(p, p * 32);
        asm volatile("cp.async.commit_group;");
    }

    int cstg = 0, lstg = NSTAGE - 1;
    for (int c = 0; c < NC; c++) {
        asm volatile("cp.async.wait_group %0;" ::"n"(NSTAGE - 2));
        __syncthreads();
        if (c + NSTAGE - 1 < NC) F16_LOAD(lstg, (c + NSTAGE - 1) * 32);
        asm volatile("cp.async.commit_group;");
        lstg = (lstg + 1 == NSTAGE) ? 0 : lstg + 1;

        const unsigned st = sb + cstg * STAGE_BYTES;
        cstg = (cstg + 1 == NSTAGE) ? 0 : cstg + 1;
#pragma unroll
        for (int ks = 0; ks < 2; ks++) {
            const unsigned koff = ks * 32;
            unsigned ah[2][4], al[2][4];
#pragma unroll
            for (int mf = 0; mf < 2; mf++) {
                unsigned addr = st + (wm * 32 + mf * 16 + (lane & 15)) * 80 +
                                ((lane >> 4) * 16) + koff;
                ldm4(ah[mf], addr);
                ldm4(al[mf], addr + O_AL);
            }
#pragma unroll
            for (int nb = 0; nb < NB; nb++) {
                unsigned addr = st + O_B +
                                (wn * 64 + nb * 16 + (lane & 15)) * 80 +
                                ((lane >> 4) * 16) + koff;
                unsigned bb[4];
                ldm4(bb, addr);
                unsigned b0[2] = {bb[0], bb[2]}, b1[2] = {bb[1], bb[3]};
                MMA8(nb, ah, al, b0, b1)
            }
        }
    }
#undef F16_LOAD

    EPILOGUE_STORE(256, Nout)
    if (STATS) { EPILOGUE_STATS(256) }
}

// ---------------- GEMM2: fused BN-apply loader, 2-pass fp16 ----------------
// A: 2 stages x 20480 (hi +0, lo +10240). B: 3 stages x 20480 at +40960. aff at +102400.
#define BNG_SMEM (2 * 20480 + 3 * 20480 + 4096)  // 106496

__global__ __launch_bounds__(512)
void k_mma_bn(const float* __restrict__ Y,
              const __half* __restrict__ Bf,
              float* __restrict__ Cf, int M,
              const float* __restrict__ stats_in, const float* __restrict__ gamma,
              const float* __restrict__ beta, float* __restrict__ stats_out) {
    constexpr int KTOT = 512, BN = 256, NB = 4, NC = 16;
    constexpr int O_B = 40960;
    constexpr int O_AFF = 102400;
    extern __shared__ __align__(16) char smem[];
    float* s_aff = (float*)(smem + O_AFF);
    const int tid = threadIdx.x;
    const int wid = tid >> 5, lane = tid & 31;
    const int wm = wid & 3, wn = wid >> 2;
    const int bm = blockIdx.x * 128, bn = blockIdx.y * BN;
    const unsigned sb = smem_u32(smem);

    if (tid < 512) {
        float inv = 1.f / (float)M;
        float m = stats_in[tid] * inv;
        float var = stats_in[512 + tid] * inv - m * m;
        float sc = gamma[tid] * rsqrtf(var + BN_EPS);
        s_aff[tid] = sc;
        s_aff[512 + tid] = beta[tid] - m * sc;
    }

    const int arow = tid >> 2, quad = tid & 3;
    const int grA = min(bm + arow, M - 1);

    ACC_INIT(NB)

#define BNG_LOADB(STG, K0)                                                     \
    {                                                                          \
        unsigned st = sb + O_B + (STG) * 20480;                                \
        _Pragma("unroll") for (int i = 0; i < 2; i++) {                        \
            int brow = arow + i * 128;                                         \
            unsigned bd = brow * 80 + quad * 16;                               \
            size_t ob = (size_t)(bn + brow) * KTOT + (K0) + quad * 8;          \
            cpasync16(st + bd, Bf + ob);                                       \
        }                                                                      \
    }
#define BNG_LDGA(K0)                                                           \
    {                                                                          \
        const float4* yp = (const float4*)(Y + (size_t)grA * KTOT + (K0) + quad * 8);\
        ya[0] = __ldg(yp); ya[1] = __ldg(yp + 1);                              \
    }

    float4 ya[2];
    BNG_LDGA(0);
    BNG_LOADB(0, 0);
    asm volatile("cp.async.commit_group;");
    BNG_LOADB(1, 32);
    asm volatile("cp.async.commit_group;");
    __syncthreads();  // s_aff visible

    for (int c = 0; c < NC; c++) {
        // STS A(c): affine + relu + exact fp16 split (stage c&1)
        {
            unsigned hi[4], lo[4];
            const int kb = c * 32 + quad * 8;
#pragma unroll
            for (int j = 0; j < 2; j++) {
                float4 y = ya[j];
                const int k = kb + j * 4;
                float x0 = fmaxf(y.x * s_aff[k + 0] + s_aff[512 + k + 0], 0.f);
                float x1 = fmaxf(y.y * s_aff[k + 1] + s_aff[512 + k + 1], 0.f);
                float x2 = fmaxf(y.z * s_aff[k + 2] + s_aff[512 + k + 2], 0.f);
                float x3 = fmaxf(y.w * s_aff[k + 3] + s_aff[512 + k + 3], 0.f);
                split2h(x0, x1, hi[j * 2], lo[j * 2]);
                split2h(x2, x3, hi[j * 2 + 1], lo[j * 2 + 1]);
            }
            char* ad = smem + (c & 1) * 20480 + arow * 80 + quad * 16;
            *(uint4*)ad = make_uint4(hi[0], hi[1], hi[2], hi[3]);
            *(uint4*)(ad + 10240) = make_uint4(lo[0], lo[1], lo[2], lo[3]);
        }
        asm volatile("cp.async.wait_group 1;");
        __syncthreads();
        if (c + 1 < NC) BNG_LDGA((c + 1) * 32);
        if (c + 2 < NC) BNG_LOADB((c + 2) % 3, (c + 2) * 32);
        asm volatile("cp.async.commit_group;");

        const unsigned ast = sb + (c & 1) * 20480;
        const unsigned bst = sb + O_B + (c % 3) * 20480;
#pragma unroll
        for (int ks = 0; ks < 2; ks++) {
            const unsigned koff = ks * 32;
            unsigned ah[2][4], al[2][4];
#pragma unroll
            for (int mf = 0; mf < 2; mf++) {
                unsigned addr = ast + (wm * 32 + mf * 16 + (lane & 15)) * 80 +
                                ((lane >> 4) * 16) + koff;
                ldm4(ah[mf], addr);
                ldm4(al[mf], addr + 10240);
            }
#pragma unroll
            for (int nb = 0; nb < NB; nb++) {
                unsigned addr = bst + (wn * 64 + nb * 16 + (lane & 15)) * 80 +
                                ((lane >> 4) * 16) + koff;
                unsigned bb[4];
                ldm4(bb, addr);
                unsigned b0[2] = {bb[0], bb[2]}, b1[2] = {bb[1], bb[3]};
                MMA8(nb, ah, al, b0, b1)
            }
        }
    }
#undef BNG_LOADB
#undef BNG_LDGA

    const int Nout = 512;
    EPILOGUE_STORE(256, Nout)
    EPILOGUE_STATS(256)
}

// ---------------- decoder final GEMM: fused edge loader, 2-pass fp16 ----------------
#define DEC_SMEM (2 * 20480 + 3 * 10240)  // 71680

__global__ __launch_bounds__(512)
void k_dec(const float* __restrict__ PQ,
           const __half* __restrict__ Bf,
           float* __restrict__ Cf, int M,
           const int* __restrict__ gu, const int* __restrict__ gv,
           const float* __restrict__ bias1, const float* __restrict__ bias2) {
    constexpr int KTOT = 512, NB = 2, NC = 16;
    extern __shared__ __align__(16) char smem[];
    __shared__ int s_u[128], s_v[128];
    const int tid = threadIdx.x;
    const int wid = tid >> 5, lane = tid & 31;
    const int wm = wid & 3, wn = wid >> 2;
    const int bm = blockIdx.x * 128;
    const int bn = 0;
    const unsigned sb = smem_u32(smem);

    if (tid < 128) {
        int e = min(bm + tid, M - 1);
        s_u[tid] = gu[e];
        s_v[tid] = gv[e];
    }
    __syncthreads();

    const int arow = tid >> 2, quad = tid & 3;
    const size_t prow = (size_t)s_u[arow] * 1024;
    const size_t qrow = (size_t)s_v[arow] * 1024 + 512;

    ACC_INIT(NB)

#define DEC_LOADB(STG, K0)                                                     \
    {                                                                          \
        unsigned st = sb + 40960 + (STG) * 10240;                              \
        unsigned bd = arow * 80 + quad * 16;                                   \
        size_t ob = (size_t)arow * KTOT + (K0) + quad * 8;                     \
        cpasync16(st + bd, Bf + ob);                                           \
    }
#define DEC_LDGA(K0)                                                           \
    {                                                                          \
        const float4* pp = (const float4*)(PQ + prow + (K0) + quad * 8);       \
        const float4* qq = (const float4*)(PQ + qrow + (K0) + quad * 8);       \
        pa[0] = __ldg(pp); pa[1] = __ldg(pp + 1);                              \
        qa[0] = __ldg(qq); qa[1] = __ldg(qq + 1);                              \
    }

    float4 pa[2], qa[2];
    DEC_LDGA(0);
    DEC_LOADB(0, 0);
    asm volatile("cp.async.commit_group;");
    DEC_LOADB(1, 32);
    asm volatile("cp.async.commit_group;");

    for (int c = 0; c < NC; c++) {
        {
            unsigned hi[4], lo[4];
            const float* b1 = bias1 + c * 32 + quad * 8;
#pragma unroll
            for (int j = 0; j < 2; j++) {
                float4 p = pa[j], q = qa[j];
                float4 bb = *(const float4*)(b1 + j * 4);
                float x0 = fmaxf(p.x + q.x + bb.x, 0.f);
                float x1 = fmaxf(p.y + q.y + bb.y, 0.f);
                float x2 = fmaxf(p.z + q.z + bb.z, 0.f);
                float x3 = fmaxf(p.w + q.w + bb.w, 0.f);
                split2h(x0, x1, hi[j * 2], lo[j * 2]);
                split2h(x2, x3, hi[j * 2 + 1], lo[j * 2 + 1]);
            }
            char* ad = smem + (c & 1) * 20480 + arow * 80 + quad * 16;
            *(uint4*)ad = make_uint4(hi[0], hi[1], hi[2], hi[3]);
            *(uint4*)(ad + 10240) = make_uint4(lo[0], lo[1], lo[2], lo[3]);
        }
        asm volatile("cp.async.wait_group 1;");
        __syncthreads();
        if (c + 1 < NC) DEC_LDGA((c + 1) * 32);
        if (c + 2 < NC) DEC_LOADB((c + 2) % 3, (c + 2) * 32);
        asm volatile("cp.async.commit_group;");

        const unsigned ast = sb + (c & 1) * 20480;
        const unsigned bst = sb + 40960 + (c % 3) * 10240;
#pragma unroll
        for (int ks = 0; ks < 2; ks++) {
            const unsigned koff = ks * 32;
            unsigned ah[2][4], al[2][4];
#pragma unroll
            for (int mf = 0; mf < 2; mf++) {
                unsigned addr = ast + (wm * 32 + mf * 16 + (lane & 15)) * 80 +
                                ((lane >> 4) * 16) + koff;
                ldm4(ah[mf], addr);
                ldm4(al[mf], addr + 10240);
            }
#pragma unroll
            for (int nb = 0; nb < NB; nb++) {
                unsigned addr = bst + (wn * 32 + nb * 16 + (lane & 15)) * 80 +
                                ((lane >> 4) * 16) + koff;
                unsigned bb[4];
                ldm4(bb, addr);
                unsigned b0[2] = {bb[0], bb[2]}, b1[2] = {bb[1], bb[3]};
                MMA8(nb, ah, al, b0, b1)
            }
        }
    }
#undef DEC_LOADB
#undef DEC_LDGA
    (void)bn;

#pragma unroll
    for (int mf = 0; mf < 2; mf++) {
        const int r0 = bm + wm * 32 + mf * 16 + (lane >> 2);
#pragma unroll
        for (int nf = 0; nf < 2 * NB; nf++) {
            const int col = wn * 32 + nf * 8 + (lane & 3) * 2;
#pragma unroll
            for (int hh = 0; hh < 2; hh++) {
                const int row = r0 + hh * 8;
                if (row >= M) continue;
                float2 s = make_float2(acc[mf][nf][hh * 2] + bias2[col],
                                       acc[mf][nf][hh * 2 + 1] + bias2[col + 1]);
                *(float2*)(Cf + (size_t)row * OUTD + col) = s;
            }
        }
    }
}

// ---------------- CSR build ----------------
__global__ void k_zerodeg(int Nn) {
    int i = blockIdx.x * blockDim.x + threadIdx.x;
    if (i < Nn) g_deg[i] = 0;
}
__global__ void k_deg(const int* __restrict__ u, const int* __restrict__ v, int E) {
    int e = blockIdx.x * blockDim.x + threadIdx.x;
    if (e >= E) return;
    atomicAdd(&g_deg[u[e]], 1);
    atomicAdd(&g_deg[v[e]], 1);
}
__global__ void k_scan(int Nn) {
    __shared__ int warpsum[32];
    __shared__ int s_carry;
    const int tid = threadIdx.x, lane = tid & 31, w = tid >> 5;
    if (tid == 0) s_carry = 0;
    __syncthreads();
    for (int base = 0; base < Nn; base += 1024) {
        int i = base + tid;
        int v = (i < Nn) ? g_deg[i] : 0;
        int x = v;
#pragma unroll
        for (int o = 1; o < 32; o <<= 1) {
            int t = __shfl_up_sync(0xffffffffu, x, o);
            if (lane >= o) x += t;
        }
        if (lane == 31) warpsum[w] = x;
        __syncthreads();
        if (w == 0) {
            int s = warpsum[lane];
#pragma unroll
            for (int o = 1; o < 32; o <<= 1) {
                int t = __shfl_up_sync(0xffffffffu, s, o);
                if (lane >= o) s += t;
            }
            warpsum[lane] = s;
        }
        __syncthreads();
        int incl = x + (w > 0 ? warpsum[w - 1] : 0) + s_carry;
        if (i < Nn) {
            int excl = incl - v;
            g_off[i] = excl;
            g_cur[i] = excl;
        }
        __syncthreads();
        if (tid == 1023) s_carry = incl;
        __syncthreads();
    }
    if (tid == 0) g_off[Nn] = s_carry;
}
__global__ void k_fill(const int* __restrict__ u, const int* __restrict__ v, int E) {
    int e = blockIdx.x * blockDim.x + threadIdx.x;
    if (e >= E) return;
    int a = u[e], b = v[e];
    int p = atomicAdd(&g_cur[b], 1);
    g_adj[p] = a;
    int q = atomicAdd(&g_cur[a], 1);
    g_adj[q] = b;
}

// ---------------- aggregation: z = 2h + sum_{nb} h[nb] (h fp16) -> fp16 pairs ----------------
__global__ void k_agg(int Nn) {
    const int w = threadIdx.x >> 5;               // 0..7
    const int node = blockIdx.x * 4 + (w >> 1);
    if (node >= Nn) return;
    const int lane = threadIdx.x & 31;
    const int ci = (w & 1) * 32 + lane;           // uint4 index 0..63 (8 halves each)

    float acc[8];
    {
        uint4 t = ((const uint4*)(g_h + (size_t)node * D))[ci];
        const __half2* hh = (const __half2*)&t;
#pragma unroll
        for (int j = 0; j < 4; j++) {
            float2 f = __half22float2(hh[j]);
            acc[j * 2] = 2.f * f.x;
            acc[j * 2 + 1] = 2.f * f.y;
        }
    }
    const int e1 = g_off[node + 1];
    int e = g_off[node];
    if (e < e1) {
        uint4 cur = ((const uint4*)(g_h + (size_t)__ldg(&g_adj[e]) * D))[ci];
        for (++e; e < e1; ++e) {
            uint4 nxt = ((const uint4*)(g_h + (size_t)__ldg(&g_adj[e]) * D))[ci];
            const __half2* hh = (const __half2*)&cur;
#pragma unroll
            for (int j = 0; j < 4; j++) {
                float2 f = __half22float2(hh[j]);
                acc[j * 2] += f.x;
                acc[j * 2 + 1] += f.y;
            }
            cur = nxt;
        }
        const __half2* hh = (const __half2*)&cur;
#pragma unroll
        for (int j = 0; j < 4; j++) {
            float2 f = __half22float2(hh[j]);
            acc[j * 2] += f.x;
            acc[j * 2 + 1] += f.y;
        }
    }
    {
        unsigned hi[4], lo[4];
        split2h(acc[0], acc[1], hi[0], lo[0]);
        split2h(acc[2], acc[3], hi[1], lo[1]);
        split2h(acc[4], acc[5], hi[2], lo[2]);
        split2h(acc[6], acc[7], hi[3], lo[3]);
        size_t o = (size_t)node * D + (size_t)ci * 8;
        *(uint4*)(g_zh + o) = make_uint4(hi[0], hi[1], hi[2], hi[3]);
        *(uint4*)(g_zl + o) = make_uint4(lo[0], lo[1], lo[2], lo[3]);
    }
}

// ---------------- elementwise kernels ----------------
__global__ void k_gather(const int* __restrict__ ids, const float* __restrict__ emb, int Nn) {
    int idx = blockIdx.x * blockDim.x + threadIdx.x;
    int row = idx >> 7;
    if (row >= Nn) return;
    int c = (idx & 127) << 2;
    float4 val = *(const float4*)(emb + (size_t)ids[row] * D + c);
    size_t o = (size_t)row * D + c;
    ((unsigned*)(g_h + o))[0] = pack2h(val.x, val.y);
    ((unsigned*)(g_h + o))[1] = pack2h(val.z, val.w);
    *(float4*)(g_hsum + o) = val;
}

// weight transpose+convert to single fp16: src [K,Nn] -> dst [Nn,K]
__global__ void k_tcvt16(const float* __restrict__ B, __half* __restrict__ H, int K, int Nn) {
    int idx = blockIdx.x * blockDim.x + threadIdx.x;
    if (idx >= K * Nn) return;
    int n = idx / K, k = idx - n * K;
    H[idx] = __float2half(B[(size_t)k * Nn + n]);
}

__global__ void k_bnzero2() {
    int t = blockIdx.x * blockDim.x + threadIdx.x;
    if (t < 2048) g_stats[t] = 0.f;
}

// h = relu(affine(Y2)); hsum += h ; aff computed in-block from stats slot
// LAST=0: write h fp16 + hsum fp32.  LAST=1: write (hsum+h) as fp16 pairs only.
template <int LAST>
__global__ void k_bnrelu_acc(const float* __restrict__ Y2,
                             const float* __restrict__ stats,
                             const float* __restrict__ gamma,
                             const float* __restrict__ beta, int Nn) {
    __shared__ float s_aff[1024];
    int tid = threadIdx.x;
    {
        float inv = 1.f / (float)Nn;
#pragma unroll
        for (int j = tid; j < 512; j += 256) {
            float m = stats[j] * inv;
            float var = stats[512 + j] * inv - m * m;
            float sc = gamma[j] * rsqrtf(var + BN_EPS);
            s_aff[j] = sc;
            s_aff[512 + j] = beta[j] - m * sc;
        }
    }
    __syncthreads();
    int idx = blockIdx.x * blockDim.x + tid;
    if (idx >= Nn * 128) return;
    int c = (idx & 127) << 2;
    float4 v = *(const float4*)(Y2 + (size_t)idx * 4);
    v.x = fmaxf(v.x * s_aff[c + 0] + s_aff[512 + c + 0], 0.f);
    v.y = fmaxf(v.y * s_aff[c + 1] + s_aff[512 + c + 1], 0.f);
    v.z = fmaxf(v.z * s_aff[c + 2] + s_aff[512 + c + 2], 0.f);
    v.w = fmaxf(v.w * s_aff[c + 3] + s_aff[512 + c + 3], 0.f);
    float4 hs = *(const float4*)(g_hsum + (size_t)idx * 4);
    hs.x += v.x; hs.y += v.y; hs.z += v.z; hs.w += v.w;
    if (!LAST) {
        ((unsigned*)(g_h + (size_t)idx * 4))[0] = pack2h(v.x, v.y);
        ((unsigned*)(g_h + (size_t)idx * 4))[1] = pack2h(v.z, v.w);
        *(float4*)(g_hsum + (size_t)idx * 4) = hs;
    } else {
        unsigned h0, l0, h1, l1;
        split2h(hs.x, hs.y, h0, l0);
        split2h(hs.z, hs.w, h1, l1);
        ((unsigned*)(g_hsfh + (size_t)idx * 4))[0] = h0;
        ((unsigned*)(g_hsfh + (size_t)idx * 4))[1] = h1;
        ((unsigned*)(g_hsfl + (size_t)idx * 4))[0] = l0;
        ((unsigned*)(g_hsfl + (size_t)idx * 4))[1] = l1;
    }
}

// ---------------- launch ----------------
extern "C" void kernel_launch(void* const* d_in, const int* in_sizes, int n_in,
                              void* d_out, int out_size) {
    const int* h_ids = (const int*)d_in[0];
    const int* u     = (const int*)d_in[1];
    const int* v     = (const int*)d_in[2];
    const float* emb   = (const float*)d_in[3];
    const float* lin1  = (const float*)d_in[4];
    const float* lin2  = (const float*)d_in[5];
    const float* bn1_g = (const float*)d_in[6];
    const float* bn1_b = (const float*)d_in[7];
    const float* bn2_g = (const float*)d_in[8];
    const float* bn2_b = (const float*)d_in[9];
    const float* W1_w  = (const float*)d_in[10];
    const float* W1_b  = (const float*)d_in[11];
    const float* W2_w  = (const float*)d_in[12];
    const float* W2_b  = (const float*)d_in[13];
    float* out = (float*)d_out;

    const int N = in_sizes[0];
    const int E = in_sizes[1];
    const int L = in_sizes[4] / (D * D);

    static int s_attr = 0;
    if (!s_attr) {
        cudaFuncSetAttribute(k_mma_f16<0>, cudaFuncAttributeMaxDynamicSharedMemorySize, PQ_SMEM);
        cudaFuncSetAttribute(k_mma_f16<1>, cudaFuncAttributeMaxDynamicSharedMemorySize, PQ_SMEM);
        cudaFuncSetAttribute(k_mma_bn, cudaFuncAttributeMaxDynamicSharedMemorySize, BNG_SMEM);
        cudaFuncSetAttribute(k_dec, cudaFuncAttributeMaxDynamicSharedMemorySize, DEC_SMEM);
        s_attr = 1;
    }

    float *dg_z, *dg_y, *dg_pq, *dg_stats;
    cudaGetSymbolAddress((void**)&dg_z, g_z);
    cudaGetSymbolAddress((void**)&dg_y, g_y);
    cudaGetSymbolAddress((void**)&dg_pq, g_pq);
    cudaGetSymbolAddress((void**)&dg_stats, g_stats);
    __half *zh, *zl, *hsfh, *hsfl, *l1f, *l2f, *w1f, *w2f;
    cudaGetSymbolAddress((void**)&zh, g_zh);  cudaGetSymbolAddress((void**)&zl, g_zl);
    cudaGetSymbolAddress((void**)&hsfh, g_hsfh); cudaGetSymbolAddress((void**)&hsfl, g_hsfl);
    cudaGetSymbolAddress((void**)&l1f, g_l1f);
    cudaGetSymbolAddress((void**)&l2f, g_l2f);
    cudaGetSymbolAddress((void**)&w1f, g_w1f);
    cudaGetSymbolAddress((void**)&w2f, g_w2f);

    const int ew = N * 128, ewB = (ew + 255) / 256;
    const int mtiles = (N + 127) / 128;
    const int etiles = (E + 127) / 128;
    const int edB = (E + 255) / 256;
    const int ndB = (N + 255) / 256;
    const int aggB = (N + 3) / 4;

    // weight conversion (transpose + fp16)
    const int wB = (D * D + 255) / 256;
    for (int i = 0; i < L; i++) {
        k_tcvt16<<<wB, 256>>>(lin1 + (size_t)i * D * D, l1f + (size_t)i * D * D, D, D);
        k_tcvt16<<<wB, 256>>>(lin2 + (size_t)i * D * D, l2f + (size_t)i * D * D, D, D);
    }
    k_tcvt16<<<wB, 256>>>(W1_w, w1f, D, D);
    k_tcvt16<<<wB, 256>>>(W1_w + (size_t)D * D, w1f + (size_t)D * D, D, D);
    k_tcvt16<<<(D * OUTD + 255) / 256, 256>>>(W2_w, w2f, D, OUTD);

    // h = emb[h_ids] (fp16); hidden_sum = h (fp32)
    k_gather<<<ewB, 256>>>(h_ids, emb, N);

    // CSR build (once)
    k_zerodeg<<<ndB, 256>>>(N);
    k_deg<<<edB, 256>>>(u, v, E);
    k_scan<<<1, 1024>>>(N);
    k_fill<<<edB, 256>>>(u, v, E);

    for (int i = 0; i < L; i++) {
        // z = 2h + neighbor sums -> fp16 pairs ; zero both stats slots
        k_agg<<<aggB, 256>>>(N);
        k_bnzero2<<<2, 1024>>>();
        // y = z @ lin1[i]  (2-pass fp16, stats -> slot0)
        k_mma_f16<1><<<dim3(mtiles, 2), 512, PQ_SMEM>>>(
            zh, zl, l1f + (size_t)i * D * D, dg_y, N, D, dg_stats);
        // z(out) = relu(bn1(y)) @ lin2[i]  (fused BN loader, 2-pass fp16; stats -> slot1)
        k_mma_bn<<<dim3(mtiles, 2), 512, BNG_SMEM>>>(
            dg_y, l2f + (size_t)i * D * D, dg_z, N,
            dg_stats, bn1_g + (size_t)i * D, bn1_b + (size_t)i * D,
            dg_stats + 1024);
        // h = relu(bn2(z)); hsum += h  (aff computed in-block from slot1)
        if (i == L - 1)
            k_bnrelu_acc<1><<<ewB, 256>>>(dg_z, dg_stats + 1024,
                bn2_g + (size_t)i * D, bn2_b + (size_t)i * D, N);
        else
            k_bnrelu_acc<0><<<ewB, 256>>>(dg_z, dg_stats + 1024,
                bn2_g + (size_t)i * D, bn2_b + (size_t)i * D, N);
    }

    // decoder: [P|Q] = hsum_fp16pairs @ fp16(W1t)^T  (2-pass fp16, Nout=1024)
    k_mma_f16<0><<<dim3(mtiles, 4), 512, PQ_SMEM>>>(
        hsfh, hsfl, w1f, dg_pq, N, 2 * D, nullptr);
    // out = relu(P[u]+Q[v]+b1) @ fp16(W2)^T + b2  (fused edge loader, 2-pass fp16)
    k_dec<<<etiles, 512, DEC_SMEM>>>(dg_pq, w2f, out, E, u, v, W1_b, W2_b);
}